// round 8
// baseline (speedup 1.0000x reference)
#include <cuda_runtime.h>
#include <cuda_bf16.h>
#include <cstdint>

#define B_  2
#define N_  2048
#define D_  1024
#define H_  16
#define HD_ 64
#define S_  2048
#define BH_ (B_*H_)

// ---------------- scratch ----------------------------------------------------
static __device__ float g_rowsum[(size_t)BH_*N_];

static __device__ __nv_bfloat16 g_xh[(size_t)4096*1024];
static __device__ __nv_bfloat16 g_xl[(size_t)4096*1024];
static __device__ __nv_bfloat16 g_wih[(size_t)3072*1024];
static __device__ __nv_bfloat16 g_wil[(size_t)3072*1024];
static __device__ __nv_bfloat16 g_aoh[(size_t)4096*1024];
static __device__ __nv_bfloat16 g_aol[(size_t)4096*1024];
static __device__ __nv_bfloat16 g_woh[(size_t)1024*1024];
static __device__ __nv_bfloat16 g_wol[(size_t)1024*1024];

static __device__ __nv_bfloat16 g_Qh[(size_t)BH_*N_*HD_];   // [bh,n,hd]
static __device__ __nv_bfloat16 g_Ql[(size_t)BH_*N_*HD_];
static __device__ __nv_bfloat16 g_Kh[(size_t)BH_*N_*HD_];
static __device__ __nv_bfloat16 g_Kl[(size_t)BH_*N_*HD_];
static __device__ __nv_bfloat16 g_Vth[(size_t)BH_*HD_*N_];  // [bh,hd,n]
static __device__ __nv_bfloat16 g_Vtl[(size_t)BH_*HD_*N_];

// ---------------- helpers ----------------------------------------------------
__device__ __forceinline__ uint32_t smem_u32(const void* p) {
    uint32_t a;
    asm("{ .reg .u64 t; cvta.to.shared.u64 t, %1; cvt.u32.u64 %0, t; }"
        : "=r"(a) : "l"(p));
    return a;
}
__device__ __forceinline__ void cp16(uint32_t dst, const void* src) {
    asm volatile("cp.async.cg.shared.global [%0], [%1], 16;" :: "r"(dst), "l"(src));
}
#define CP_COMMIT asm volatile("cp.async.commit_group;" ::: "memory")
#define CP_WAIT0  asm volatile("cp.async.wait_group 0;" ::: "memory")
#define CP_WAIT1  asm volatile("cp.async.wait_group 1;" ::: "memory")

__device__ __forceinline__ void ldsm4(uint32_t& r0, uint32_t& r1, uint32_t& r2,
                                      uint32_t& r3, uint32_t addr) {
    asm volatile("ldmatrix.sync.aligned.m8n8.x4.shared.b16 {%0,%1,%2,%3}, [%4];"
                 : "=r"(r0), "=r"(r1), "=r"(r2), "=r"(r3) : "r"(addr));
}
__device__ __forceinline__ void mma16816(float* c, const uint32_t* a,
                                         const uint32_t* b) {
    asm volatile(
        "mma.sync.aligned.m16n8k16.row.col.f32.bf16.bf16.f32 "
        "{%0,%1,%2,%3}, {%4,%5,%6,%7}, {%8,%9}, {%0,%1,%2,%3};"
        : "+f"(c[0]), "+f"(c[1]), "+f"(c[2]), "+f"(c[3])
        : "r"(a[0]), "r"(a[1]), "r"(a[2]), "r"(a[3]), "r"(b[0]), "r"(b[1]));
}
__device__ __forceinline__ uint32_t pkbf(float lo, float hi) {
    uint32_t d;
    asm("cvt.rn.bf16x2.f32 %0, %1, %2;" : "=r"(d) : "f"(hi), "f"(lo));
    return d;
}

// =============================================================================
// fp32 -> bf16 hi/lo split, 3 tensors in one launch
// =============================================================================
__global__ void __launch_bounds__(256) cvt3_kernel(
        const float* __restrict__ x0, __nv_bfloat16* __restrict__ h0p,
        __nv_bfloat16* __restrict__ l0p,
        const float* __restrict__ x1, __nv_bfloat16* __restrict__ h1p,
        __nv_bfloat16* __restrict__ l1p,
        const float* __restrict__ x2, __nv_bfloat16* __restrict__ h2p,
        __nv_bfloat16* __restrict__ l2p) {
    int blk = blockIdx.x;
    const float* x; __nv_bfloat16 *hi, *lo; int i;
    if (blk < 4096)      { x = x0; hi = h0p; lo = l0p; i = blk * 256 + threadIdx.x; }
    else if (blk < 7168) { x = x1; hi = h1p; lo = l1p; i = (blk - 4096) * 256 + threadIdx.x; }
    else                 { x = x2; hi = h2p; lo = l2p; i = (blk - 7168) * 256 + threadIdx.x; }
    float4 v = ((const float4*)x)[i];
    __nv_bfloat16 a0 = __float2bfloat16(v.x), a1 = __float2bfloat16(v.y);
    __nv_bfloat16 a2 = __float2bfloat16(v.z), a3 = __float2bfloat16(v.w);
    ((__nv_bfloat162*)hi)[2 * i] = __nv_bfloat162(a0, a1);
    ((__nv_bfloat162*)hi)[2 * i + 1] = __nv_bfloat162(a2, a3);
    ((__nv_bfloat162*)lo)[2 * i] = __nv_bfloat162(
        __float2bfloat16(v.x - __bfloat162float(a0)),
        __float2bfloat16(v.y - __bfloat162float(a1)));
    ((__nv_bfloat162*)lo)[2 * i + 1] = __nv_bfloat162(
        __float2bfloat16(v.z - __bfloat162float(a2)),
        __float2bfloat16(v.w - __bfloat162float(a3)));
}

// =============================================================================
// Split-bf16 GEMM core (device function, used by qkv kernel and fused out/norm)
// =============================================================================
#define SSTR  40
#define ARRB  (128*SSTR*2)
#define STAGE (4*ARRB)
#define GEMM_SMEM (2*STAGE)

__device__ __forceinline__ void split_st2(__nv_bfloat16* dh, __nv_bfloat16* dl,
                                          size_t idx, float2 v) {
    __nv_bfloat16 h0 = __float2bfloat16(v.x), h1 = __float2bfloat16(v.y);
    *(__nv_bfloat162*)(dh + idx) = __nv_bfloat162(h0, h1);
    *(__nv_bfloat162*)(dl + idx) = __nv_bfloat162(
        __float2bfloat16(v.x - __bfloat162float(h0)),
        __float2bfloat16(v.y - __bfloat162float(h1)));
}
__device__ __forceinline__ void split_st1(__nv_bfloat16* dh, __nv_bfloat16* dl,
                                          size_t idx, float v) {
    __nv_bfloat16 h = __float2bfloat16(v);
    dh[idx] = h;
    dl[idx] = __float2bfloat16(v - __bfloat162float(h));
}

template<bool QKV>
__device__ __forceinline__ void gemm_body(
        uint32_t sb, int m0, int n0,
        const __nv_bfloat16* __restrict__ Ah_g, const __nv_bfloat16* __restrict__ Al_g,
        const __nv_bfloat16* __restrict__ Bh_g, const __nv_bfloat16* __restrict__ Bl_g,
        const float* __restrict__ bias, float* __restrict__ outp) {
    int tid = threadIdx.x, lane = tid & 31, wid = tid >> 5;
    int wm = wid >> 1, wn = wid & 1;

    const __nv_bfloat16* base[4] = {
        Ah_g + (size_t)m0 * 1024, Al_g + (size_t)m0 * 1024,
        Bh_g + (size_t)n0 * 1024, Bl_g + (size_t)n0 * 1024 };

    float c[2][8][4];
#pragma unroll
    for (int mt = 0; mt < 2; mt++)
#pragma unroll
        for (int nt = 0; nt < 8; nt++)
#pragma unroll
            for (int q = 0; q < 4; q++) c[mt][nt][q] = 0.f;

    int r_ld = tid >> 2, c_ld = (tid & 3) << 3;

    {
#pragma unroll
        for (int arr = 0; arr < 4; arr++)
#pragma unroll
            for (int j = 0; j < 2; j++) {
                int r = r_ld + j * 64;
                cp16(sb + arr * ARRB + (uint32_t)(r * SSTR + c_ld) * 2,
                     base[arr] + (size_t)r * 1024 + c_ld);
            }
        CP_COMMIT;
    }

#pragma unroll 1
    for (int t = 0; t < 32; t++) {
        if (t + 1 < 32) {
            int s = (t + 1) & 1, k0 = (t + 1) << 5;
#pragma unroll
            for (int arr = 0; arr < 4; arr++)
#pragma unroll
                for (int j = 0; j < 2; j++) {
                    int r = r_ld + j * 64;
                    cp16(sb + (uint32_t)s * STAGE + arr * ARRB +
                             (uint32_t)(r * SSTR + c_ld) * 2,
                         base[arr] + (size_t)r * 1024 + k0 + c_ld);
                }
            CP_COMMIT;
            CP_WAIT1;
        } else {
            CP_WAIT0;
        }
        __syncthreads();

        uint32_t st = sb + (uint32_t)(t & 1) * STAGE;
#pragma unroll
        for (int kk = 0; kk < 2; kk++) {
            uint32_t bh[8][2], bl[8][2];
#pragma unroll
            for (int ng = 0; ng < 4; ng++) {
                int brow = wn * 64 + ng * 16 + (lane & 7) + ((lane & 16) >> 1);
                int bcol = kk * 16 + ((lane >> 3) & 1) * 8;
                uint32_t ba = st + 2 * ARRB + (uint32_t)(brow * SSTR + bcol) * 2;
                ldsm4(bh[2 * ng][0], bh[2 * ng][1], bh[2 * ng + 1][0],
                      bh[2 * ng + 1][1], ba);
                ldsm4(bl[2 * ng][0], bl[2 * ng][1], bl[2 * ng + 1][0],
                      bl[2 * ng + 1][1], ba + ARRB);
            }
#pragma unroll
            for (int mt = 0; mt < 2; mt++) {
                int arow = wm * 32 + mt * 16 + (lane & 15);
                int acol = kk * 16 + (lane >> 4) * 8;
                uint32_t aa = st + (uint32_t)(arow * SSTR + acol) * 2;
                uint32_t ah[4], al[4];
                ldsm4(ah[0], ah[1], ah[2], ah[3], aa);
                ldsm4(al[0], al[1], al[2], al[3], aa + ARRB);
#pragma unroll
                for (int nt = 0; nt < 8; nt++) {
                    mma16816(c[mt][nt], ah, bh[nt]);
                    mma16816(c[mt][nt], ah, bl[nt]);
                    mma16816(c[mt][nt], al, bh[nt]);
                }
            }
        }
        __syncthreads();
    }

#pragma unroll
    for (int mt = 0; mt < 2; mt++) {
        int m = m0 + wm * 32 + mt * 16 + (lane >> 2);
#pragma unroll
        for (int nt = 0; nt < 8; nt++) {
            int n = n0 + wn * 64 + nt * 8 + ((lane & 3) << 1);
            float b0 = bias[n], b1 = bias[n + 1];
            float2 v0 = make_float2(c[mt][nt][0] + b0, c[mt][nt][1] + b1);
            float2 v1 = make_float2(c[mt][nt][2] + b0, c[mt][nt][3] + b1);
            if (QKV) {
                int sect = n >> 10;
                int h = (n & 1023) >> 6, hd = n & 63;
                int bb = m >> 11, row = m & 2047;
                int bh_i = bb * H_ + h;
                if (sect < 2) {
                    __nv_bfloat16* dh = sect == 0 ? g_Qh : g_Kh;
                    __nv_bfloat16* dl = sect == 0 ? g_Ql : g_Kl;
                    size_t p = ((size_t)bh_i * N_ + row) * HD_ + hd;
                    split_st2(dh, dl, p, v0);
                    split_st2(dh, dl, p + 8 * HD_, v1);
                } else {
                    size_t pb = ((size_t)bh_i * HD_ + hd) * N_ + row;
                    split_st1(g_Vth, g_Vtl, pb, v0.x);
                    split_st1(g_Vth, g_Vtl, pb + N_, v0.y);
                    split_st1(g_Vth, g_Vtl, pb + 8, v1.x);
                    split_st1(g_Vth, g_Vtl, pb + N_ + 8, v1.y);
                }
            } else {
                float* p = outp + (size_t)m * 1024 + n;
                *(float2*)p = v0;
                *(float2*)(p + 8 * 1024) = v1;
            }
        }
    }
}

__global__ void __launch_bounds__(256) qkv_gemm_k(
        const __nv_bfloat16* __restrict__ Ah_g, const __nv_bfloat16* __restrict__ Al_g,
        const __nv_bfloat16* __restrict__ Bh_g, const __nv_bfloat16* __restrict__ Bl_g,
        const float* __restrict__ bias) {
    extern __shared__ char smem[];
    gemm_body<true>(smem_u32(smem), blockIdx.y << 7, blockIdx.x << 7,
                    Ah_g, Al_g, Bh_g, Bl_g, bias, nullptr);
}

// =============================================================================
// Fused out-projection GEMM + attn normalize. Blocks [0,256): GEMM tiles
// (8 x 32 grid flattened); blocks [256, 256+NN): stream-normalize attn.
// =============================================================================
#define NN_BLOCKS 2048

__global__ void __launch_bounds__(256) out_norm_kernel(
        const __nv_bfloat16* __restrict__ Ah_g, const __nv_bfloat16* __restrict__ Al_g,
        const __nv_bfloat16* __restrict__ Bh_g, const __nv_bfloat16* __restrict__ Bl_g,
        const float* __restrict__ bias, float* __restrict__ outp,
        float* __restrict__ attn, int write_attn) {
    int blk = blockIdx.x;
    if (blk < 256) {
        extern __shared__ char smem[];
        int n0 = (blk & 7) << 7, m0 = (blk >> 3) << 7;
        gemm_body<false>(smem_u32(smem), m0, n0, Ah_g, Al_g, Bh_g, Bl_g, bias, outp);
        return;
    }
    if (!write_attn) return;
    // normalize: each block owns a contiguous chunk of float4s
    const size_t total4 = (size_t)BH_ * N_ * N_ / 4;             // 33554432
    const size_t per_blk = total4 / NN_BLOCKS;                    // 16384
    size_t i0 = (size_t)(blk - 256) * per_blk;
    size_t i1 = i0 + per_blk;
#pragma unroll 1
    for (size_t i = i0 + threadIdx.x; i < i1; i += 256) {
        int row = (int)(i >> 9);                                  // 512 f4 per row
        float inv = 1.0f / g_rowsum[row];
        float4 v = __ldcs((const float4*)attn + i);
        v.x *= inv; v.y *= inv; v.z *= inv; v.w *= inv;
        __stcs((float4*)attn + i, v);
    }
}

// =============================================================================
// HMMA split-bf16 fused attention (R6 structure: 3-stage KV ring, inline AV)
// =============================================================================
#define AT_STR 72
#define AQH 0
#define AQL (128*AT_STR)
#define AKV (2*128*AT_STR)
#define KVSTG (4*64*AT_STR)
#define ABF_END (AKV + 3*KVSTG)
#define ATTN_SMEM (ABF_END*2 + 2048*4)      // 155648 B

__global__ void __launch_bounds__(256, 1) attn_kernel(float* __restrict__ attn,
                                                      const float* __restrict__ rpe,
                                                      int write_attn) {
    extern __shared__ char smc[];
    uint32_t sb = smem_u32(smc);
    float* rc = (float*)(smc + ABF_END * 2);

    int qt = blockIdx.x, h = blockIdx.y, b = blockIdx.z;
    int bh_i = b * H_ + h;
    int tid = threadIdx.x, lane = tid & 31, wm = tid >> 5;
    int q0 = qt << 7;

    for (int i = tid; i < S_; i += 256) rc[i] = rpe[(size_t)i * H_ + h];

    const __nv_bfloat16* qhg = g_Qh + ((size_t)bh_i * N_ + q0) * HD_;
    const __nv_bfloat16* qlg = g_Ql + ((size_t)bh_i * N_ + q0) * HD_;
    const __nv_bfloat16* khg = g_Kh + (size_t)bh_i * N_ * HD_;
    const __nv_bfloat16* klg = g_Kl + (size_t)bh_i * N_ * HD_;
    const __nv_bfloat16* vhg = g_Vth + (size_t)bh_i * HD_ * N_;
    const __nv_bfloat16* vlg = g_Vtl + (size_t)bh_i * HD_ * N_;

#pragma unroll
    for (int j = 0; j < 4; j++) {
        int u = tid + j * 256;
        int r = u >> 3, ch = (u & 7) << 3;
        cp16(sb + (uint32_t)(AQH + r * AT_STR + ch) * 2, qhg + (size_t)r * HD_ + ch);
        cp16(sb + (uint32_t)(AQL + r * AT_STR + ch) * 2, qlg + (size_t)r * HD_ + ch);
    }
    CP_COMMIT;

    int r_ld = tid >> 3, c_ld = (tid & 7) << 3;
    auto issue_kv = [&](int t) {
        int k0g = t * 64;
        uint32_t stg = sb + (uint32_t)(AKV + (t % 3) * KVSTG) * 2;
#pragma unroll
        for (int j = 0; j < 2; j++) {
            int r = r_ld + j * 32, ch = c_ld;
            cp16(stg + (uint32_t)(0 * 4608 + r * AT_STR + ch) * 2,
                 khg + (size_t)(k0g + r) * HD_ + ch);
            cp16(stg + (uint32_t)(1 * 4608 + r * AT_STR + ch) * 2,
                 klg + (size_t)(k0g + r) * HD_ + ch);
            cp16(stg + (uint32_t)(2 * 4608 + r * AT_STR + ch) * 2,
                 vhg + (size_t)r * N_ + k0g + ch);
            cp16(stg + (uint32_t)(3 * 4608 + r * AT_STR + ch) * 2,
                 vlg + (size_t)r * N_ + k0g + ch);
        }
        CP_COMMIT;
    };
    issue_kv(0);
    issue_kv(1);

    float co[8][4];
#pragma unroll
    for (int nh = 0; nh < 8; nh++)
#pragma unroll
        for (int q = 0; q < 4; q++) co[nh][q] = 0.f;
    float rs0 = 0.f, rs1 = 0.f;

    int row_q = q0 + wm * 16 + (lane >> 2);
    const float scale = 0.125f;

#pragma unroll 1
    for (int t = 0; t < N_ / 64; t++) {
        if (t < 31) { CP_WAIT1; } else { CP_WAIT0; }
        __syncthreads();

        int k0g = t * 64;
        uint32_t kb = sb + (uint32_t)(AKV + (t % 3) * KVSTG) * 2;

        float s[8][4];
#pragma unroll
        for (int nt = 0; nt < 8; nt++)
#pragma unroll
            for (int q = 0; q < 4; q++) s[nt][q] = 0.f;
#pragma unroll
        for (int ks = 0; ks < 4; ks++) {
            int arow = wm * 16 + (lane & 15);
            int acol = ks * 16 + (lane >> 4) * 8;
            uint32_t aa = sb + (uint32_t)(AQH + arow * AT_STR + acol) * 2;
            uint32_t ah[4], al[4];
            ldsm4(ah[0], ah[1], ah[2], ah[3], aa);
            ldsm4(al[0], al[1], al[2], al[3], aa + AQL * 2);
            uint32_t bh[8][2], bl[8][2];
#pragma unroll
            for (int ng = 0; ng < 4; ng++) {
                int brow = ng * 16 + (lane & 7) + ((lane & 16) >> 1);
                int bcol = ks * 16 + ((lane >> 3) & 1) * 8;
                uint32_t ba = kb + (uint32_t)(brow * AT_STR + bcol) * 2;
                ldsm4(bh[2 * ng][0], bh[2 * ng][1], bh[2 * ng + 1][0],
                      bh[2 * ng + 1][1], ba);
                ldsm4(bl[2 * ng][0], bl[2 * ng][1], bl[2 * ng + 1][0],
                      bl[2 * ng + 1][1], ba + 4608 * 2);
            }
#pragma unroll
            for (int nt = 0; nt < 8; nt++) {
                mma16816(s[nt], ah, bh[nt]);
                mma16816(s[nt], ah, bl[nt]);
                mma16816(s[nt], al, bh[nt]);
            }
        }

#pragma unroll
        for (int nt = 0; nt < 8; nt++) {
            int col = k0g + nt * 8 + ((lane & 3) << 1);
            int d0 = row_q - col;     if (d0 < 0) d0 = -d0;
            int d1 = row_q - col - 1; if (d1 < 0) d1 = -d1;
            int d2 = row_q + 8 - col;     if (d2 < 0) d2 = -d2;
            int d3 = row_q + 8 - col - 1; if (d3 < 0) d3 = -d3;
            float e0 = __expf(fmaf(s[nt][0], scale, rc[d0]));
            float e1 = __expf(fmaf(s[nt][1], scale, rc[d1]));
            float e2 = __expf(fmaf(s[nt][2], scale, rc[d2]));
            float e3 = __expf(fmaf(s[nt][3], scale, rc[d3]));
            s[nt][0] = e0; s[nt][1] = e1; s[nt][2] = e2; s[nt][3] = e3;
            rs0 += e0 + e1;
            rs1 += e2 + e3;
            if (write_attn) {
                float* ap = attn + ((size_t)bh_i * N_ + row_q) * N_ + col;
                *(float2*)ap = make_float2(e0, e1);
                *(float2*)(ap + 8 * N_) = make_float2(e2, e3);
            }
        }

        uint32_t vb0 = kb + 2 * 4608 * 2;
#pragma unroll
        for (int ks = 0; ks < 4; ks++) {
            uint32_t eah[4], eal[4];
            {
                float c0 = s[2 * ks][0], c1 = s[2 * ks][1];
                float c2 = s[2 * ks][2], c3 = s[2 * ks][3];
                float c4 = s[2 * ks + 1][0], c5 = s[2 * ks + 1][1];
                float c6 = s[2 * ks + 1][2], c7 = s[2 * ks + 1][3];
                eah[0] = pkbf(c0, c1); eah[1] = pkbf(c2, c3);
                eah[2] = pkbf(c4, c5); eah[3] = pkbf(c6, c7);
                float hh;
                hh = __bfloat162float(__float2bfloat16(c0)); c0 -= hh;
                hh = __bfloat162float(__float2bfloat16(c1)); c1 -= hh;
                hh = __bfloat162float(__float2bfloat16(c2)); c2 -= hh;
                hh = __bfloat162float(__float2bfloat16(c3)); c3 -= hh;
                hh = __bfloat162float(__float2bfloat16(c4)); c4 -= hh;
                hh = __bfloat162float(__float2bfloat16(c5)); c5 -= hh;
                hh = __bfloat162float(__float2bfloat16(c6)); c6 -= hh;
                hh = __bfloat162float(__float2bfloat16(c7)); c7 -= hh;
                eal[0] = pkbf(c0, c1); eal[1] = pkbf(c2, c3);
                eal[2] = pkbf(c4, c5); eal[3] = pkbf(c6, c7);
            }
            uint32_t vbh[8][2], vbl[8][2];
#pragma unroll
            for (int ng = 0; ng < 4; ng++) {
                int brow = ng * 16 + (lane & 7) + ((lane & 16) >> 1);
                int bcol = ks * 16 + ((lane >> 3) & 1) * 8;
                uint32_t ba = vb0 + (uint32_t)(brow * AT_STR + bcol) * 2;
                ldsm4(vbh[2 * ng][0], vbh[2 * ng][1], vbh[2 * ng + 1][0],
                      vbh[2 * ng + 1][1], ba);
                ldsm4(vbl[2 * ng][0], vbl[2 * ng][1], vbl[2 * ng + 1][0],
                      vbl[2 * ng + 1][1], ba + 4608 * 2);
            }
#pragma unroll
            for (int nh = 0; nh < 8; nh++) {
                mma16816(co[nh], eah, vbh[nh]);
                mma16816(co[nh], eah, vbl[nh]);
                mma16816(co[nh], eal, vbh[nh]);
            }
        }

        if (t + 2 < N_ / 64) issue_kv(t + 2);
    }

    rs0 += __shfl_xor_sync(0xffffffffu, rs0, 1);
    rs0 += __shfl_xor_sync(0xffffffffu, rs0, 2);
    rs1 += __shfl_xor_sync(0xffffffffu, rs1, 1);
    rs1 += __shfl_xor_sync(0xffffffffu, rs1, 2);
    if ((lane & 3) == 0) {
        g_rowsum[(size_t)bh_i * N_ + row_q] = rs0;
        g_rowsum[(size_t)bh_i * N_ + row_q + 8] = rs1;
    }

    float inv0 = 1.0f / rs0, inv1 = 1.0f / rs1;
#pragma unroll
    for (int nh = 0; nh < 8; nh++) {
        int hd = nh * 8 + ((lane & 3) << 1);
        size_t p = ((size_t)(b * N_ + row_q)) * D_ + h * HD_ + hd;
        split_st2(g_aoh, g_aol, p, make_float2(co[nh][0] * inv0, co[nh][1] * inv0));
        split_st2(g_aoh, g_aol, p + 8 * D_,
                  make_float2(co[nh][2] * inv1, co[nh][3] * inv1));
    }
}

// =============================================================================
extern "C" void kernel_launch(void* const* d_in, const int* in_sizes, int n_in,
                              void* d_out, int out_size) {
    const float* query = (const float*)d_in[0];
    const float* w_in  = (const float*)d_in[4];
    const float* b_in  = (const float*)d_in[5];
    const float* w_out = (const float*)d_in[6];
    const float* b_out = (const float*)d_in[7];
    const float* rpe   = (const float*)d_in[8];

    float* out  = (float*)d_out;
    const long long out_elems  = (long long)B_ * N_ * D_;
    const long long attn_elems = (long long)BH_ * N_ * N_;
    int write_attn = ((long long)out_size >= out_elems + attn_elems) ? 1 : 0;
    float* attn = out + out_elems;

    cudaFuncSetAttribute(attn_kernel, cudaFuncAttributeMaxDynamicSharedMemorySize,
                         ATTN_SMEM);
    cudaFuncSetAttribute(qkv_gemm_k, cudaFuncAttributeMaxDynamicSharedMemorySize,
                         GEMM_SMEM);
    cudaFuncSetAttribute(out_norm_kernel, cudaFuncAttributeMaxDynamicSharedMemorySize,
                         GEMM_SMEM);

    __nv_bfloat16 *xh, *xl, *wih, *wil, *aoh, *aol, *woh, *wol;
    cudaGetSymbolAddress((void**)&xh,  g_xh);
    cudaGetSymbolAddress((void**)&xl,  g_xl);
    cudaGetSymbolAddress((void**)&wih, g_wih);
    cudaGetSymbolAddress((void**)&wil, g_wil);
    cudaGetSymbolAddress((void**)&aoh, g_aoh);
    cudaGetSymbolAddress((void**)&aol, g_aol);
    cudaGetSymbolAddress((void**)&woh, g_woh);
    cudaGetSymbolAddress((void**)&wol, g_wol);

    cvt3_kernel<<<8192, 256>>>(query, xh, xl, w_in, wih, wil, w_out, woh, wol);

    qkv_gemm_k<<<dim3(24, 32), 256, GEMM_SMEM>>>(xh, xl, wih, wil, b_in);

    attn_kernel<<<dim3(16, 16, 2), 256, ATTN_SMEM>>>(attn, rpe, write_attn);

    out_norm_kernel<<<256 + NN_BLOCKS, 256, GEMM_SMEM>>>(
        aoh, aol, woh, wol, b_out, out, attn, write_attn);
}

// round 9
// speedup vs baseline: 1.1326x; 1.1326x over previous
#include <cuda_runtime.h>
#include <cuda_bf16.h>
#include <cstdint>

#define B_  2
#define N_  2048
#define D_  1024
#define H_  16
#define HD_ 64
#define S_  2048
#define BH_ (B_*H_)

// ---------------- scratch ----------------------------------------------------
static __device__ __nv_bfloat16 g_xh[(size_t)4096*1024];
static __device__ __nv_bfloat16 g_xl[(size_t)4096*1024];
static __device__ __nv_bfloat16 g_wih[(size_t)3072*1024];
static __device__ __nv_bfloat16 g_wil[(size_t)3072*1024];
static __device__ __nv_bfloat16 g_aoh[(size_t)4096*1024];
static __device__ __nv_bfloat16 g_aol[(size_t)4096*1024];
static __device__ __nv_bfloat16 g_woh[(size_t)1024*1024];
static __device__ __nv_bfloat16 g_wol[(size_t)1024*1024];

static __device__ __nv_bfloat16 g_Qh[(size_t)BH_*N_*HD_];   // [bh,n,hd]
static __device__ __nv_bfloat16 g_Ql[(size_t)BH_*N_*HD_];
static __device__ __nv_bfloat16 g_Kh[(size_t)BH_*N_*HD_];
static __device__ __nv_bfloat16 g_Kl[(size_t)BH_*N_*HD_];
static __device__ __nv_bfloat16 g_Vth[(size_t)BH_*HD_*N_];  // [bh,hd,n]
static __device__ __nv_bfloat16 g_Vtl[(size_t)BH_*HD_*N_];

// ---------------- helpers ----------------------------------------------------
__device__ __forceinline__ uint32_t smem_u32(const void* p) {
    uint32_t a;
    asm("{ .reg .u64 t; cvta.to.shared.u64 t, %1; cvt.u32.u64 %0, t; }"
        : "=r"(a) : "l"(p));
    return a;
}
__device__ __forceinline__ void cp16(uint32_t dst, const void* src) {
    asm volatile("cp.async.cg.shared.global [%0], [%1], 16;" :: "r"(dst), "l"(src));
}
#define CP_COMMIT asm volatile("cp.async.commit_group;" ::: "memory")
#define CP_WAIT0  asm volatile("cp.async.wait_group 0;" ::: "memory")
#define CP_WAIT1  asm volatile("cp.async.wait_group 1;" ::: "memory")

__device__ __forceinline__ void ldsm4(uint32_t& r0, uint32_t& r1, uint32_t& r2,
                                      uint32_t& r3, uint32_t addr) {
    asm volatile("ldmatrix.sync.aligned.m8n8.x4.shared.b16 {%0,%1,%2,%3}, [%4];"
                 : "=r"(r0), "=r"(r1), "=r"(r2), "=r"(r3) : "r"(addr));
}
__device__ __forceinline__ void mma16816(float* c, const uint32_t* a,
                                         const uint32_t* b) {
    asm volatile(
        "mma.sync.aligned.m16n8k16.row.col.f32.bf16.bf16.f32 "
        "{%0,%1,%2,%3}, {%4,%5,%6,%7}, {%8,%9}, {%0,%1,%2,%3};"
        : "+f"(c[0]), "+f"(c[1]), "+f"(c[2]), "+f"(c[3])
        : "r"(a[0]), "r"(a[1]), "r"(a[2]), "r"(a[3]), "r"(b[0]), "r"(b[1]));
}
__device__ __forceinline__ uint32_t pkbf(float lo, float hi) {
    uint32_t d;
    asm("cvt.rn.bf16x2.f32 %0, %1, %2;" : "=r"(d) : "f"(hi), "f"(lo));
    return d;
}

// =============================================================================
// fp32 -> bf16 hi/lo split, 3 tensors in one launch
// =============================================================================
__global__ void __launch_bounds__(256) cvt3_kernel(
        const float* __restrict__ x0, __nv_bfloat16* __restrict__ h0p,
        __nv_bfloat16* __restrict__ l0p,
        const float* __restrict__ x1, __nv_bfloat16* __restrict__ h1p,
        __nv_bfloat16* __restrict__ l1p,
        const float* __restrict__ x2, __nv_bfloat16* __restrict__ h2p,
        __nv_bfloat16* __restrict__ l2p) {
    int blk = blockIdx.x;
    const float* x; __nv_bfloat16 *hi, *lo; int i;
    if (blk < 4096)      { x = x0; hi = h0p; lo = l0p; i = blk * 256 + threadIdx.x; }
    else if (blk < 7168) { x = x1; hi = h1p; lo = l1p; i = (blk - 4096) * 256 + threadIdx.x; }
    else                 { x = x2; hi = h2p; lo = l2p; i = (blk - 7168) * 256 + threadIdx.x; }
    float4 v = ((const float4*)x)[i];
    __nv_bfloat16 a0 = __float2bfloat16(v.x), a1 = __float2bfloat16(v.y);
    __nv_bfloat16 a2 = __float2bfloat16(v.z), a3 = __float2bfloat16(v.w);
    ((__nv_bfloat162*)hi)[2 * i] = __nv_bfloat162(a0, a1);
    ((__nv_bfloat162*)hi)[2 * i + 1] = __nv_bfloat162(a2, a3);
    ((__nv_bfloat162*)lo)[2 * i] = __nv_bfloat162(
        __float2bfloat16(v.x - __bfloat162float(a0)),
        __float2bfloat16(v.y - __bfloat162float(a1)));
    ((__nv_bfloat162*)lo)[2 * i + 1] = __nv_bfloat162(
        __float2bfloat16(v.z - __bfloat162float(a2)),
        __float2bfloat16(v.w - __bfloat162float(a3)));
}

// =============================================================================
// Split-bf16 GEMM via mma.sync (proven R5 version)
// =============================================================================
#define SSTR  40
#define ARRB  (128*SSTR*2)
#define STAGE (4*ARRB)
#define GEMM_SMEM (2*STAGE)

__device__ __forceinline__ void split_st2(__nv_bfloat16* dh, __nv_bfloat16* dl,
                                          size_t idx, float2 v) {
    __nv_bfloat16 h0 = __float2bfloat16(v.x), h1 = __float2bfloat16(v.y);
    *(__nv_bfloat162*)(dh + idx) = __nv_bfloat162(h0, h1);
    *(__nv_bfloat162*)(dl + idx) = __nv_bfloat162(
        __float2bfloat16(v.x - __bfloat162float(h0)),
        __float2bfloat16(v.y - __bfloat162float(h1)));
}
__device__ __forceinline__ void split_st1(__nv_bfloat16* dh, __nv_bfloat16* dl,
                                          size_t idx, float v) {
    __nv_bfloat16 h = __float2bfloat16(v);
    dh[idx] = h;
    dl[idx] = __float2bfloat16(v - __bfloat162float(h));
}

template<bool QKV>
__global__ void __launch_bounds__(256) mma_gemm(
        const __nv_bfloat16* __restrict__ Ah_g, const __nv_bfloat16* __restrict__ Al_g,
        const __nv_bfloat16* __restrict__ Bh_g, const __nv_bfloat16* __restrict__ Bl_g,
        const float* __restrict__ bias, float* __restrict__ outp) {
    extern __shared__ char smem[];
    uint32_t sb = smem_u32(smem);
    int tid = threadIdx.x, lane = tid & 31, wid = tid >> 5;
    int m0 = blockIdx.y << 7, n0 = blockIdx.x << 7;
    int wm = wid >> 1, wn = wid & 1;

    const __nv_bfloat16* base[4] = {
        Ah_g + (size_t)m0 * 1024, Al_g + (size_t)m0 * 1024,
        Bh_g + (size_t)n0 * 1024, Bl_g + (size_t)n0 * 1024 };

    float c[2][8][4];
#pragma unroll
    for (int mt = 0; mt < 2; mt++)
#pragma unroll
        for (int nt = 0; nt < 8; nt++)
#pragma unroll
            for (int q = 0; q < 4; q++) c[mt][nt][q] = 0.f;

    int r_ld = tid >> 2, c_ld = (tid & 3) << 3;

    {
#pragma unroll
        for (int arr = 0; arr < 4; arr++)
#pragma unroll
            for (int j = 0; j < 2; j++) {
                int r = r_ld + j * 64;
                cp16(sb + arr * ARRB + (uint32_t)(r * SSTR + c_ld) * 2,
                     base[arr] + (size_t)r * 1024 + c_ld);
            }
        CP_COMMIT;
    }

#pragma unroll 1
    for (int t = 0; t < 32; t++) {
        if (t + 1 < 32) {
            int s = (t + 1) & 1, k0 = (t + 1) << 5;
#pragma unroll
            for (int arr = 0; arr < 4; arr++)
#pragma unroll
                for (int j = 0; j < 2; j++) {
                    int r = r_ld + j * 64;
                    cp16(sb + (uint32_t)s * STAGE + arr * ARRB +
                             (uint32_t)(r * SSTR + c_ld) * 2,
                         base[arr] + (size_t)r * 1024 + k0 + c_ld);
                }
            CP_COMMIT;
            CP_WAIT1;
        } else {
            CP_WAIT0;
        }
        __syncthreads();

        uint32_t st = sb + (uint32_t)(t & 1) * STAGE;
#pragma unroll
        for (int kk = 0; kk < 2; kk++) {
            uint32_t bh[8][2], bl[8][2];
#pragma unroll
            for (int ng = 0; ng < 4; ng++) {
                int brow = wn * 64 + ng * 16 + (lane & 7) + ((lane & 16) >> 1);
                int bcol = kk * 16 + ((lane >> 3) & 1) * 8;
                uint32_t ba = st + 2 * ARRB + (uint32_t)(brow * SSTR + bcol) * 2;
                ldsm4(bh[2 * ng][0], bh[2 * ng][1], bh[2 * ng + 1][0],
                      bh[2 * ng + 1][1], ba);
                ldsm4(bl[2 * ng][0], bl[2 * ng][1], bl[2 * ng + 1][0],
                      bl[2 * ng + 1][1], ba + ARRB);
            }
#pragma unroll
            for (int mt = 0; mt < 2; mt++) {
                int arow = wm * 32 + mt * 16 + (lane & 15);
                int acol = kk * 16 + (lane >> 4) * 8;
                uint32_t aa = st + (uint32_t)(arow * SSTR + acol) * 2;
                uint32_t ah[4], al[4];
                ldsm4(ah[0], ah[1], ah[2], ah[3], aa);
                ldsm4(al[0], al[1], al[2], al[3], aa + ARRB);
#pragma unroll
                for (int nt = 0; nt < 8; nt++) {
                    mma16816(c[mt][nt], ah, bh[nt]);
                    mma16816(c[mt][nt], ah, bl[nt]);
                    mma16816(c[mt][nt], al, bh[nt]);
                }
            }
        }
        __syncthreads();
    }

#pragma unroll
    for (int mt = 0; mt < 2; mt++) {
        int m = m0 + wm * 32 + mt * 16 + (lane >> 2);
#pragma unroll
        for (int nt = 0; nt < 8; nt++) {
            int n = n0 + wn * 64 + nt * 8 + ((lane & 3) << 1);
            float b0 = bias[n], b1 = bias[n + 1];
            float2 v0 = make_float2(c[mt][nt][0] + b0, c[mt][nt][1] + b1);
            float2 v1 = make_float2(c[mt][nt][2] + b0, c[mt][nt][3] + b1);
            if (QKV) {
                int sect = n >> 10;
                int h = (n & 1023) >> 6, hd = n & 63;
                int bb = m >> 11, row = m & 2047;
                int bh_i = bb * H_ + h;
                if (sect < 2) {
                    __nv_bfloat16* dh = sect == 0 ? g_Qh : g_Kh;
                    __nv_bfloat16* dl = sect == 0 ? g_Ql : g_Kl;
                    size_t p = ((size_t)bh_i * N_ + row) * HD_ + hd;
                    split_st2(dh, dl, p, v0);
                    split_st2(dh, dl, p + 8 * HD_, v1);
                } else {
                    size_t pb = ((size_t)bh_i * HD_ + hd) * N_ + row;
                    split_st1(g_Vth, g_Vtl, pb, v0.x);
                    split_st1(g_Vth, g_Vtl, pb + N_, v0.y);
                    split_st1(g_Vth, g_Vtl, pb + 8, v1.x);
                    split_st1(g_Vth, g_Vtl, pb + N_ + 8, v1.y);
                }
            } else {
                float* p = outp + (size_t)m * 1024 + n;
                *(float2*)p = v0;
                *(float2*)(p + 8 * 1024) = v1;
            }
        }
    }
}

// =============================================================================
// HMMA split-bf16 fused attention, 3-stage KV ring + in-kernel normalize tail.
// Each block normalizes its own attn stripe after rowsums are known; tails of
// early waves overlap later waves' MMA compute.
// =============================================================================
#define AT_STR 72
#define AQH 0
#define AQL (128*AT_STR)
#define AKV (2*128*AT_STR)
#define KVSTG (4*64*AT_STR)
#define ABF_END (AKV + 3*KVSTG)
#define RC_BYTES (2048*4)
#define ATTN_SMEM (ABF_END*2 + RC_BYTES + 128*4)   // +rinv[128]

__global__ void __launch_bounds__(256, 1) attn_kernel(float* __restrict__ attn,
                                                      const float* __restrict__ rpe,
                                                      int write_attn) {
    extern __shared__ char smc[];
    uint32_t sb = smem_u32(smc);
    float* rc = (float*)(smc + ABF_END * 2);
    float* rinv = (float*)(smc + ABF_END * 2 + RC_BYTES);

    int qt = blockIdx.x, h = blockIdx.y, b = blockIdx.z;
    int bh_i = b * H_ + h;
    int tid = threadIdx.x, lane = tid & 31, wm = tid >> 5;
    int q0 = qt << 7;

    for (int i = tid; i < S_; i += 256) rc[i] = rpe[(size_t)i * H_ + h];

    const __nv_bfloat16* qhg = g_Qh + ((size_t)bh_i * N_ + q0) * HD_;
    const __nv_bfloat16* qlg = g_Ql + ((size_t)bh_i * N_ + q0) * HD_;
    const __nv_bfloat16* khg = g_Kh + (size_t)bh_i * N_ * HD_;
    const __nv_bfloat16* klg = g_Kl + (size_t)bh_i * N_ * HD_;
    const __nv_bfloat16* vhg = g_Vth + (size_t)bh_i * HD_ * N_;
    const __nv_bfloat16* vlg = g_Vtl + (size_t)bh_i * HD_ * N_;

#pragma unroll
    for (int j = 0; j < 4; j++) {
        int u = tid + j * 256;
        int r = u >> 3, ch = (u & 7) << 3;
        cp16(sb + (uint32_t)(AQH + r * AT_STR + ch) * 2, qhg + (size_t)r * HD_ + ch);
        cp16(sb + (uint32_t)(AQL + r * AT_STR + ch) * 2, qlg + (size_t)r * HD_ + ch);
    }
    CP_COMMIT;

    int r_ld = tid >> 3, c_ld = (tid & 7) << 3;
    auto issue_kv = [&](int t) {
        int k0g = t * 64;
        uint32_t stg = sb + (uint32_t)(AKV + (t % 3) * KVSTG) * 2;
#pragma unroll
        for (int j = 0; j < 2; j++) {
            int r = r_ld + j * 32, ch = c_ld;
            cp16(stg + (uint32_t)(0 * 4608 + r * AT_STR + ch) * 2,
                 khg + (size_t)(k0g + r) * HD_ + ch);
            cp16(stg + (uint32_t)(1 * 4608 + r * AT_STR + ch) * 2,
                 klg + (size_t)(k0g + r) * HD_ + ch);
            cp16(stg + (uint32_t)(2 * 4608 + r * AT_STR + ch) * 2,
                 vhg + (size_t)r * N_ + k0g + ch);
            cp16(stg + (uint32_t)(3 * 4608 + r * AT_STR + ch) * 2,
                 vlg + (size_t)r * N_ + k0g + ch);
        }
        CP_COMMIT;
    };
    issue_kv(0);
    issue_kv(1);

    float co[8][4];
#pragma unroll
    for (int nh = 0; nh < 8; nh++)
#pragma unroll
        for (int q = 0; q < 4; q++) co[nh][q] = 0.f;
    float rs0 = 0.f, rs1 = 0.f;

    int row_q = q0 + wm * 16 + (lane >> 2);
    const float scale = 0.125f;

#pragma unroll 1
    for (int t = 0; t < N_ / 64; t++) {
        if (t < 31) { CP_WAIT1; } else { CP_WAIT0; }
        __syncthreads();

        int k0g = t * 64;
        uint32_t kb = sb + (uint32_t)(AKV + (t % 3) * KVSTG) * 2;

        float s[8][4];
#pragma unroll
        for (int nt = 0; nt < 8; nt++)
#pragma unroll
            for (int q = 0; q < 4; q++) s[nt][q] = 0.f;
#pragma unroll
        for (int ks = 0; ks < 4; ks++) {
            int arow = wm * 16 + (lane & 15);
            int acol = ks * 16 + (lane >> 4) * 8;
            uint32_t aa = sb + (uint32_t)(AQH + arow * AT_STR + acol) * 2;
            uint32_t ah[4], al[4];
            ldsm4(ah[0], ah[1], ah[2], ah[3], aa);
            ldsm4(al[0], al[1], al[2], al[3], aa + AQL * 2);
            uint32_t bh[8][2], bl[8][2];
#pragma unroll
            for (int ng = 0; ng < 4; ng++) {
                int brow = ng * 16 + (lane & 7) + ((lane & 16) >> 1);
                int bcol = ks * 16 + ((lane >> 3) & 1) * 8;
                uint32_t ba = kb + (uint32_t)(brow * AT_STR + bcol) * 2;
                ldsm4(bh[2 * ng][0], bh[2 * ng][1], bh[2 * ng + 1][0],
                      bh[2 * ng + 1][1], ba);
                ldsm4(bl[2 * ng][0], bl[2 * ng][1], bl[2 * ng + 1][0],
                      bl[2 * ng + 1][1], ba + 4608 * 2);
            }
#pragma unroll
            for (int nt = 0; nt < 8; nt++) {
                mma16816(s[nt], ah, bh[nt]);
                mma16816(s[nt], ah, bl[nt]);
                mma16816(s[nt], al, bh[nt]);
            }
        }

#pragma unroll
        for (int nt = 0; nt < 8; nt++) {
            int col = k0g + nt * 8 + ((lane & 3) << 1);
            int d0 = row_q - col;     if (d0 < 0) d0 = -d0;
            int d1 = row_q - col - 1; if (d1 < 0) d1 = -d1;
            int d2 = row_q + 8 - col;     if (d2 < 0) d2 = -d2;
            int d3 = row_q + 8 - col - 1; if (d3 < 0) d3 = -d3;
            float e0 = __expf(fmaf(s[nt][0], scale, rc[d0]));
            float e1 = __expf(fmaf(s[nt][1], scale, rc[d1]));
            float e2 = __expf(fmaf(s[nt][2], scale, rc[d2]));
            float e3 = __expf(fmaf(s[nt][3], scale, rc[d3]));
            s[nt][0] = e0; s[nt][1] = e1; s[nt][2] = e2; s[nt][3] = e3;
            rs0 += e0 + e1;
            rs1 += e2 + e3;
            if (write_attn) {
                float* ap = attn + ((size_t)bh_i * N_ + row_q) * N_ + col;
                *(float2*)ap = make_float2(e0, e1);
                *(float2*)(ap + 8 * N_) = make_float2(e2, e3);
            }
        }

        uint32_t vb0 = kb + 2 * 4608 * 2;
#pragma unroll
        for (int ks = 0; ks < 4; ks++) {
            uint32_t eah[4], eal[4];
            {
                float c0 = s[2 * ks][0], c1 = s[2 * ks][1];
                float c2 = s[2 * ks][2], c3 = s[2 * ks][3];
                float c4 = s[2 * ks + 1][0], c5 = s[2 * ks + 1][1];
                float c6 = s[2 * ks + 1][2], c7 = s[2 * ks + 1][3];
                eah[0] = pkbf(c0, c1); eah[1] = pkbf(c2, c3);
                eah[2] = pkbf(c4, c5); eah[3] = pkbf(c6, c7);
                float hh;
                hh = __bfloat162float(__float2bfloat16(c0)); c0 -= hh;
                hh = __bfloat162float(__float2bfloat16(c1)); c1 -= hh;
                hh = __bfloat162float(__float2bfloat16(c2)); c2 -= hh;
                hh = __bfloat162float(__float2bfloat16(c3)); c3 -= hh;
                hh = __bfloat162float(__float2bfloat16(c4)); c4 -= hh;
                hh = __bfloat162float(__float2bfloat16(c5)); c5 -= hh;
                hh = __bfloat162float(__float2bfloat16(c6)); c6 -= hh;
                hh = __bfloat162float(__float2bfloat16(c7)); c7 -= hh;
                eal[0] = pkbf(c0, c1); eal[1] = pkbf(c2, c3);
                eal[2] = pkbf(c4, c5); eal[3] = pkbf(c6, c7);
            }
            uint32_t vbh[8][2], vbl[8][2];
#pragma unroll
            for (int ng = 0; ng < 4; ng++) {
                int brow = ng * 16 + (lane & 7) + ((lane & 16) >> 1);
                int bcol = ks * 16 + ((lane >> 3) & 1) * 8;
                uint32_t ba = vb0 + (uint32_t)(brow * AT_STR + bcol) * 2;
                ldsm4(vbh[2 * ng][0], vbh[2 * ng][1], vbh[2 * ng + 1][0],
                      vbh[2 * ng + 1][1], ba);
                ldsm4(vbl[2 * ng][0], vbl[2 * ng][1], vbl[2 * ng + 1][0],
                      vbl[2 * ng + 1][1], ba + 4608 * 2);
            }
#pragma unroll
            for (int nh = 0; nh < 8; nh++) {
                mma16816(co[nh], eah, vbh[nh]);
                mma16816(co[nh], eah, vbl[nh]);
                mma16816(co[nh], eal, vbh[nh]);
            }
        }

        if (t + 2 < N_ / 64) issue_kv(t + 2);
    }

    // ---- rowsum reduce over quad lanes; publish 1/rowsum to smem ----
    rs0 += __shfl_xor_sync(0xffffffffu, rs0, 1);
    rs0 += __shfl_xor_sync(0xffffffffu, rs0, 2);
    rs1 += __shfl_xor_sync(0xffffffffu, rs1, 1);
    rs1 += __shfl_xor_sync(0xffffffffu, rs1, 2);
    int lrow = wm * 16 + (lane >> 2);
    if ((lane & 3) == 0) {
        rinv[lrow] = 1.0f / rs0;
        rinv[lrow + 8] = 1.0f / rs1;
    }

    // ---- normalized attention output -> split-bf16 aoh/aol ----
    float inv0 = 1.0f / rs0, inv1 = 1.0f / rs1;
#pragma unroll
    for (int nh = 0; nh < 8; nh++) {
        int hd = nh * 8 + ((lane & 3) << 1);
        size_t p = ((size_t)(b * N_ + row_q)) * D_ + h * HD_ + hd;
        split_st2(g_aoh, g_aol, p, make_float2(co[nh][0] * inv0, co[nh][1] * inv0));
        split_st2(g_aoh, g_aol, p + 8 * D_,
                  make_float2(co[nh][2] * inv1, co[nh][3] * inv1));
    }

    // ---- normalize this block's attn stripe in place ----
    __syncthreads();        // rinv visible + this block's attn stores ordered
    if (write_attn) {
        float4* base4 = (float4*)(attn + ((size_t)bh_i * N_ + q0) * N_);
#pragma unroll 1
        for (int i = tid; i < 128 * (N_ / 4); i += 256) {
            int r = i >> 9;                     // 512 float4 per row
            float inv = rinv[r];
            float4 v = __ldcs(base4 + i);
            v.x *= inv; v.y *= inv; v.z *= inv; v.w *= inv;
            __stcs(base4 + i, v);
        }
    }
}

// =============================================================================
extern "C" void kernel_launch(void* const* d_in, const int* in_sizes, int n_in,
                              void* d_out, int out_size) {
    const float* query = (const float*)d_in[0];
    const float* w_in  = (const float*)d_in[4];
    const float* b_in  = (const float*)d_in[5];
    const float* w_out = (const float*)d_in[6];
    const float* b_out = (const float*)d_in[7];
    const float* rpe   = (const float*)d_in[8];

    float* out  = (float*)d_out;
    const long long out_elems  = (long long)B_ * N_ * D_;
    const long long attn_elems = (long long)BH_ * N_ * N_;
    int write_attn = ((long long)out_size >= out_elems + attn_elems) ? 1 : 0;
    float* attn = out + out_elems;

    cudaFuncSetAttribute(attn_kernel, cudaFuncAttributeMaxDynamicSharedMemorySize,
                         ATTN_SMEM);
    cudaFuncSetAttribute(mma_gemm<true>, cudaFuncAttributeMaxDynamicSharedMemorySize,
                         GEMM_SMEM);
    cudaFuncSetAttribute(mma_gemm<false>, cudaFuncAttributeMaxDynamicSharedMemorySize,
                         GEMM_SMEM);

    __nv_bfloat16 *xh, *xl, *wih, *wil, *aoh, *aol, *woh, *wol;
    cudaGetSymbolAddress((void**)&xh,  g_xh);
    cudaGetSymbolAddress((void**)&xl,  g_xl);
    cudaGetSymbolAddress((void**)&wih, g_wih);
    cudaGetSymbolAddress((void**)&wil, g_wil);
    cudaGetSymbolAddress((void**)&aoh, g_aoh);
    cudaGetSymbolAddress((void**)&aol, g_aol);
    cudaGetSymbolAddress((void**)&woh, g_woh);
    cudaGetSymbolAddress((void**)&wol, g_wol);

    cvt3_kernel<<<8192, 256>>>(query, xh, xl, w_in, wih, wil, w_out, woh, wol);

    mma_gemm<true><<<dim3(24, 32), 256, GEMM_SMEM>>>(xh, xl, wih, wil, b_in, nullptr);

    attn_kernel<<<dim3(16, 16, 2), 256, ATTN_SMEM>>>(attn, rpe, write_attn);

    mma_gemm<false><<<dim3(8, 32), 256, GEMM_SMEM>>>(aoh, aol, woh, wol, b_out, out);
}

// round 11
// speedup vs baseline: 1.4668x; 1.2951x over previous
#include <cuda_runtime.h>
#include <cuda_bf16.h>
#include <cstdint>

#define B_  2
#define N_  2048
#define D_  1024
#define H_  16
#define HD_ 64
#define S_  2048
#define BH_ (B_*H_)

// ---------------- scratch ----------------------------------------------------
static __device__ float g_rowsum[(size_t)BH_*N_];

static __device__ __nv_bfloat16 g_xh[(size_t)4096*1024];
static __device__ __nv_bfloat16 g_xl[(size_t)4096*1024];
static __device__ __nv_bfloat16 g_wih[(size_t)3072*1024];
static __device__ __nv_bfloat16 g_wil[(size_t)3072*1024];
static __device__ __nv_bfloat16 g_aoh[(size_t)4096*1024];
static __device__ __nv_bfloat16 g_aol[(size_t)4096*1024];
static __device__ __nv_bfloat16 g_woh[(size_t)1024*1024];
static __device__ __nv_bfloat16 g_wol[(size_t)1024*1024];

static __device__ __nv_bfloat16 g_Qh[(size_t)BH_*N_*HD_];   // [bh,n,hd]
static __device__ __nv_bfloat16 g_Ql[(size_t)BH_*N_*HD_];
static __device__ __nv_bfloat16 g_Kh[(size_t)BH_*N_*HD_];
static __device__ __nv_bfloat16 g_Kl[(size_t)BH_*N_*HD_];
static __device__ __nv_bfloat16 g_Vth[(size_t)BH_*HD_*N_];  // [bh,hd,n]
static __device__ __nv_bfloat16 g_Vtl[(size_t)BH_*HD_*N_];

// ---------------- helpers ----------------------------------------------------
__device__ __forceinline__ uint32_t smem_u32(const void* p) {
    uint32_t a;
    asm("{ .reg .u64 t; cvta.to.shared.u64 t, %1; cvt.u32.u64 %0, t; }"
        : "=r"(a) : "l"(p));
    return a;
}
__device__ __forceinline__ void cp16(uint32_t dst, const void* src) {
    asm volatile("cp.async.cg.shared.global [%0], [%1], 16;" :: "r"(dst), "l"(src));
}
#define CP_COMMIT asm volatile("cp.async.commit_group;" ::: "memory")
#define CP_WAIT0  asm volatile("cp.async.wait_group 0;" ::: "memory")
#define CP_WAIT1  asm volatile("cp.async.wait_group 1;" ::: "memory")

__device__ __forceinline__ void ldsm4(uint32_t& r0, uint32_t& r1, uint32_t& r2,
                                      uint32_t& r3, uint32_t addr) {
    asm volatile("ldmatrix.sync.aligned.m8n8.x4.shared.b16 {%0,%1,%2,%3}, [%4];"
                 : "=r"(r0), "=r"(r1), "=r"(r2), "=r"(r3) : "r"(addr));
}
__device__ __forceinline__ void mma16816(float* c, const uint32_t* a,
                                         const uint32_t* b) {
    asm volatile(
        "mma.sync.aligned.m16n8k16.row.col.f32.bf16.bf16.f32 "
        "{%0,%1,%2,%3}, {%4,%5,%6,%7}, {%8,%9}, {%0,%1,%2,%3};"
        : "+f"(c[0]), "+f"(c[1]), "+f"(c[2]), "+f"(c[3])
        : "r"(a[0]), "r"(a[1]), "r"(a[2]), "r"(a[3]), "r"(b[0]), "r"(b[1]));
}
__device__ __forceinline__ uint32_t pkbf(float lo, float hi) {
    uint32_t d;
    asm("cvt.rn.bf16x2.f32 %0, %1, %2;" : "=r"(d) : "f"(hi), "f"(lo));
    return d;
}

// =============================================================================
// fp32 -> bf16 hi/lo split, 3 tensors in one launch
// =============================================================================
__global__ void __launch_bounds__(256) cvt3_kernel(
        const float* __restrict__ x0, __nv_bfloat16* __restrict__ h0p,
        __nv_bfloat16* __restrict__ l0p,
        const float* __restrict__ x1, __nv_bfloat16* __restrict__ h1p,
        __nv_bfloat16* __restrict__ l1p,
        const float* __restrict__ x2, __nv_bfloat16* __restrict__ h2p,
        __nv_bfloat16* __restrict__ l2p) {
    int blk = blockIdx.x;
    const float* x; __nv_bfloat16 *hi, *lo; int i;
    if (blk < 4096)      { x = x0; hi = h0p; lo = l0p; i = blk * 256 + threadIdx.x; }
    else if (blk < 7168) { x = x1; hi = h1p; lo = l1p; i = (blk - 4096) * 256 + threadIdx.x; }
    else                 { x = x2; hi = h2p; lo = l2p; i = (blk - 7168) * 256 + threadIdx.x; }
    float4 v = ((const float4*)x)[i];
    __nv_bfloat16 a0 = __float2bfloat16(v.x), a1 = __float2bfloat16(v.y);
    __nv_bfloat16 a2 = __float2bfloat16(v.z), a3 = __float2bfloat16(v.w);
    ((__nv_bfloat162*)hi)[2 * i] = __nv_bfloat162(a0, a1);
    ((__nv_bfloat162*)hi)[2 * i + 1] = __nv_bfloat162(a2, a3);
    ((__nv_bfloat162*)lo)[2 * i] = __nv_bfloat162(
        __float2bfloat16(v.x - __bfloat162float(a0)),
        __float2bfloat16(v.y - __bfloat162float(a1)));
    ((__nv_bfloat162*)lo)[2 * i + 1] = __nv_bfloat162(
        __float2bfloat16(v.z - __bfloat162float(a2)),
        __float2bfloat16(v.w - __bfloat162float(a3)));
}

// =============================================================================
// Split-bf16 GEMM core (device function)
// =============================================================================
#define SSTR  40
#define ARRB  (128*SSTR*2)
#define STAGE (4*ARRB)
#define GEMM_SMEM (2*STAGE)

__device__ __forceinline__ void split_st2(__nv_bfloat16* dh, __nv_bfloat16* dl,
                                          size_t idx, float2 v) {
    __nv_bfloat16 h0 = __float2bfloat16(v.x), h1 = __float2bfloat16(v.y);
    *(__nv_bfloat162*)(dh + idx) = __nv_bfloat162(h0, h1);
    *(__nv_bfloat162*)(dl + idx) = __nv_bfloat162(
        __float2bfloat16(v.x - __bfloat162float(h0)),
        __float2bfloat16(v.y - __bfloat162float(h1)));
}
__device__ __forceinline__ void split_st1(__nv_bfloat16* dh, __nv_bfloat16* dl,
                                          size_t idx, float v) {
    __nv_bfloat16 h = __float2bfloat16(v);
    dh[idx] = h;
    dl[idx] = __float2bfloat16(v - __bfloat162float(h));
}

template<bool QKV>
__device__ __forceinline__ void gemm_body(
        uint32_t sb, int m0, int n0,
        const __nv_bfloat16* __restrict__ Ah_g, const __nv_bfloat16* __restrict__ Al_g,
        const __nv_bfloat16* __restrict__ Bh_g, const __nv_bfloat16* __restrict__ Bl_g,
        const float* __restrict__ bias, float* __restrict__ outp) {
    int tid = threadIdx.x, lane = tid & 31, wid = tid >> 5;
    int wm = wid >> 1, wn = wid & 1;

    const __nv_bfloat16* base[4] = {
        Ah_g + (size_t)m0 * 1024, Al_g + (size_t)m0 * 1024,
        Bh_g + (size_t)n0 * 1024, Bl_g + (size_t)n0 * 1024 };

    float c[2][8][4];
#pragma unroll
    for (int mt = 0; mt < 2; mt++)
#pragma unroll
        for (int nt = 0; nt < 8; nt++)
#pragma unroll
            for (int q = 0; q < 4; q++) c[mt][nt][q] = 0.f;

    int r_ld = tid >> 2, c_ld = (tid & 3) << 3;

    {
#pragma unroll
        for (int arr = 0; arr < 4; arr++)
#pragma unroll
            for (int j = 0; j < 2; j++) {
                int r = r_ld + j * 64;
                cp16(sb + arr * ARRB + (uint32_t)(r * SSTR + c_ld) * 2,
                     base[arr] + (size_t)r * 1024 + c_ld);
            }
        CP_COMMIT;
    }

#pragma unroll 1
    for (int t = 0; t < 32; t++) {
        if (t + 1 < 32) {
            int s = (t + 1) & 1, k0 = (t + 1) << 5;
#pragma unroll
            for (int arr = 0; arr < 4; arr++)
#pragma unroll
                for (int j = 0; j < 2; j++) {
                    int r = r_ld + j * 64;
                    cp16(sb + (uint32_t)s * STAGE + arr * ARRB +
                             (uint32_t)(r * SSTR + c_ld) * 2,
                         base[arr] + (size_t)r * 1024 + k0 + c_ld);
                }
            CP_COMMIT;
            CP_WAIT1;
        } else {
            CP_WAIT0;
        }
        __syncthreads();

        uint32_t st = sb + (uint32_t)(t & 1) * STAGE;
#pragma unroll
        for (int kk = 0; kk < 2; kk++) {
            uint32_t bh[8][2], bl[8][2];
#pragma unroll
            for (int ng = 0; ng < 4; ng++) {
                int brow = wn * 64 + ng * 16 + (lane & 7) + ((lane & 16) >> 1);
                int bcol = kk * 16 + ((lane >> 3) & 1) * 8;
                uint32_t ba = st + 2 * ARRB + (uint32_t)(brow * SSTR + bcol) * 2;
                ldsm4(bh[2 * ng][0], bh[2 * ng][1], bh[2 * ng + 1][0],
                      bh[2 * ng + 1][1], ba);
                ldsm4(bl[2 * ng][0], bl[2 * ng][1], bl[2 * ng + 1][0],
                      bl[2 * ng + 1][1], ba + ARRB);
            }
#pragma unroll
            for (int mt = 0; mt < 2; mt++) {
                int arow = wm * 32 + mt * 16 + (lane & 15);
                int acol = kk * 16 + (lane >> 4) * 8;
                uint32_t aa = st + (uint32_t)(arow * SSTR + acol) * 2;
                uint32_t ah[4], al[4];
                ldsm4(ah[0], ah[1], ah[2], ah[3], aa);
                ldsm4(al[0], al[1], al[2], al[3], aa + ARRB);
#pragma unroll
                for (int nt = 0; nt < 8; nt++) {
                    mma16816(c[mt][nt], ah, bh[nt]);
                    mma16816(c[mt][nt], ah, bl[nt]);
                    mma16816(c[mt][nt], al, bh[nt]);
                }
            }
        }
        __syncthreads();
    }

#pragma unroll
    for (int mt = 0; mt < 2; mt++) {
        int m = m0 + wm * 32 + mt * 16 + (lane >> 2);
#pragma unroll
        for (int nt = 0; nt < 8; nt++) {
            int n = n0 + wn * 64 + nt * 8 + ((lane & 3) << 1);
            float b0 = bias[n], b1 = bias[n + 1];
            float2 v0 = make_float2(c[mt][nt][0] + b0, c[mt][nt][1] + b1);
            float2 v1 = make_float2(c[mt][nt][2] + b0, c[mt][nt][3] + b1);
            if (QKV) {
                int sect = n >> 10;
                int h = (n & 1023) >> 6, hd = n & 63;
                int bb = m >> 11, row = m & 2047;
                int bh_i = bb * H_ + h;
                if (sect < 2) {
                    __nv_bfloat16* dh = sect == 0 ? g_Qh : g_Kh;
                    __nv_bfloat16* dl = sect == 0 ? g_Ql : g_Kl;
                    size_t p = ((size_t)bh_i * N_ + row) * HD_ + hd;
                    split_st2(dh, dl, p, v0);
                    split_st2(dh, dl, p + 8 * HD_, v1);
                } else {
                    size_t pb = ((size_t)bh_i * HD_ + hd) * N_ + row;
                    split_st1(g_Vth, g_Vtl, pb, v0.x);
                    split_st1(g_Vth, g_Vtl, pb + N_, v0.y);
                    split_st1(g_Vth, g_Vtl, pb + 8, v1.x);
                    split_st1(g_Vth, g_Vtl, pb + N_ + 8, v1.y);
                }
            } else {
                float* p = outp + (size_t)m * 1024 + n;
                *(float2*)p = v0;
                *(float2*)(p + 8 * 1024) = v1;
            }
        }
    }
}

__global__ void __launch_bounds__(256) qkv_gemm_k(
        const __nv_bfloat16* __restrict__ Ah_g, const __nv_bfloat16* __restrict__ Al_g,
        const __nv_bfloat16* __restrict__ Bh_g, const __nv_bfloat16* __restrict__ Bl_g,
        const float* __restrict__ bias) {
    extern __shared__ char smem[];
    gemm_body<true>(smem_u32(smem), blockIdx.y << 7, blockIdx.x << 7,
                    Ah_g, Al_g, Bh_g, Bl_g, bias, nullptr);
}

// =============================================================================
// Fused out-projection GEMM + attn normalize.
// launch_bounds(256, 2) caps regs at 128 -> 2 CTAs/SM. Norm path uses MLP-8
// batched streaming loads so 512 threads/SM still saturate HBM.
// =============================================================================
#define NN_BLOCKS 2048

__global__ void __launch_bounds__(256, 2) out_norm_kernel(
        const __nv_bfloat16* __restrict__ Ah_g, const __nv_bfloat16* __restrict__ Al_g,
        const __nv_bfloat16* __restrict__ Bh_g, const __nv_bfloat16* __restrict__ Bl_g,
        const float* __restrict__ bias, float* __restrict__ outp,
        float* __restrict__ attn, int write_attn) {
    int blk = blockIdx.x;
    if (blk < 256) {
        extern __shared__ char smem[];
        int n0 = (blk & 7) << 7, m0 = (blk >> 3) << 7;
        gemm_body<false>(smem_u32(smem), m0, n0, Ah_g, Al_g, Bh_g, Bl_g, bias, outp);
        return;
    }
    if (!write_attn) return;
    const size_t total4 = (size_t)BH_ * N_ * N_ / 4;             // 33554432
    const size_t per_blk = total4 / NN_BLOCKS;                    // 16384
    size_t i0 = (size_t)(blk - 256) * per_blk;
    int tid = threadIdx.x;
    // 64 float4 per thread, batched 8-wide for MLP
#pragma unroll 1
    for (int it = 0; it < 8; it++) {
        size_t idx[8];
        float4 v[8];
#pragma unroll
        for (int u = 0; u < 8; u++) {
            idx[u] = i0 + (size_t)(it * 8 + u) * 256 + tid;
            v[u] = __ldcs((const float4*)attn + idx[u]);
        }
#pragma unroll
        for (int u = 0; u < 8; u++) {
            int row = (int)(idx[u] >> 9);                         // 512 f4 per row
            float inv = 1.0f / g_rowsum[row];
            v[u].x *= inv; v[u].y *= inv; v[u].z *= inv; v[u].w *= inv;
            __stcs((float4*)attn + idx[u], v[u]);
        }
    }
}

// =============================================================================
// HMMA split-bf16 fused attention (R6: 3-stage KV ring, inline AV, g_rowsum)
// =============================================================================
#define AT_STR 72
#define AQH 0
#define AQL (128*AT_STR)
#define AKV (2*128*AT_STR)
#define KVSTG (4*64*AT_STR)
#define ABF_END (AKV + 3*KVSTG)
#define ATTN_SMEM (ABF_END*2 + 2048*4)      // 155648 B

__global__ void __launch_bounds__(256, 1) attn_kernel(float* __restrict__ attn,
                                                      const float* __restrict__ rpe,
                                                      int write_attn) {
    extern __shared__ char smc[];
    uint32_t sb = smem_u32(smc);
    float* rc = (float*)(smc + ABF_END * 2);

    int qt = blockIdx.x, h = blockIdx.y, b = blockIdx.z;
    int bh_i = b * H_ + h;
    int tid = threadIdx.x, lane = tid & 31, wm = tid >> 5;
    int q0 = qt << 7;

    for (int i = tid; i < S_; i += 256) rc[i] = rpe[(size_t)i * H_ + h];

    const __nv_bfloat16* qhg = g_Qh + ((size_t)bh_i * N_ + q0) * HD_;
    const __nv_bfloat16* qlg = g_Ql + ((size_t)bh_i * N_ + q0) * HD_;
    const __nv_bfloat16* khg = g_Kh + (size_t)bh_i * N_ * HD_;
    const __nv_bfloat16* klg = g_Kl + (size_t)bh_i * N_ * HD_;
    const __nv_bfloat16* vhg = g_Vth + (size_t)bh_i * HD_ * N_;
    const __nv_bfloat16* vlg = g_Vtl + (size_t)bh_i * HD_ * N_;

#pragma unroll
    for (int j = 0; j < 4; j++) {
        int u = tid + j * 256;
        int r = u >> 3, ch = (u & 7) << 3;
        cp16(sb + (uint32_t)(AQH + r * AT_STR + ch) * 2, qhg + (size_t)r * HD_ + ch);
        cp16(sb + (uint32_t)(AQL + r * AT_STR + ch) * 2, qlg + (size_t)r * HD_ + ch);
    }
    CP_COMMIT;

    int r_ld = tid >> 3, c_ld = (tid & 7) << 3;
    auto issue_kv = [&](int t) {
        int k0g = t * 64;
        uint32_t stg = sb + (uint32_t)(AKV + (t % 3) * KVSTG) * 2;
#pragma unroll
        for (int j = 0; j < 2; j++) {
            int r = r_ld + j * 32, ch = c_ld;
            cp16(stg + (uint32_t)(0 * 4608 + r * AT_STR + ch) * 2,
                 khg + (size_t)(k0g + r) * HD_ + ch);
            cp16(stg + (uint32_t)(1 * 4608 + r * AT_STR + ch) * 2,
                 klg + (size_t)(k0g + r) * HD_ + ch);
            cp16(stg + (uint32_t)(2 * 4608 + r * AT_STR + ch) * 2,
                 vhg + (size_t)r * N_ + k0g + ch);
            cp16(stg + (uint32_t)(3 * 4608 + r * AT_STR + ch) * 2,
                 vlg + (size_t)r * N_ + k0g + ch);
        }
        CP_COMMIT;
    };
    issue_kv(0);
    issue_kv(1);

    float co[8][4];
#pragma unroll
    for (int nh = 0; nh < 8; nh++)
#pragma unroll
        for (int q = 0; q < 4; q++) co[nh][q] = 0.f;
    float rs0 = 0.f, rs1 = 0.f;

    int row_q = q0 + wm * 16 + (lane >> 2);
    const float scale = 0.125f;

#pragma unroll 1
    for (int t = 0; t < N_ / 64; t++) {
        if (t < 31) { CP_WAIT1; } else { CP_WAIT0; }
        __syncthreads();

        int k0g = t * 64;
        uint32_t kb = sb + (uint32_t)(AKV + (t % 3) * KVSTG) * 2;

        float s[8][4];
#pragma unroll
        for (int nt = 0; nt < 8; nt++)
#pragma unroll
            for (int q = 0; q < 4; q++) s[nt][q] = 0.f;
#pragma unroll
        for (int ks = 0; ks < 4; ks++) {
            int arow = wm * 16 + (lane & 15);
            int acol = ks * 16 + (lane >> 4) * 8;
            uint32_t aa = sb + (uint32_t)(AQH + arow * AT_STR + acol) * 2;
            uint32_t ah[4], al[4];
            ldsm4(ah[0], ah[1], ah[2], ah[3], aa);
            ldsm4(al[0], al[1], al[2], al[3], aa + AQL * 2);
            uint32_t bh[8][2], bl[8][2];
#pragma unroll
            for (int ng = 0; ng < 4; ng++) {
                int brow = ng * 16 + (lane & 7) + ((lane & 16) >> 1);
                int bcol = ks * 16 + ((lane >> 3) & 1) * 8;
                uint32_t ba = kb + (uint32_t)(brow * AT_STR + bcol) * 2;
                ldsm4(bh[2 * ng][0], bh[2 * ng][1], bh[2 * ng + 1][0],
                      bh[2 * ng + 1][1], ba);
                ldsm4(bl[2 * ng][0], bl[2 * ng][1], bl[2 * ng + 1][0],
                      bl[2 * ng + 1][1], ba + 4608 * 2);
            }
#pragma unroll
            for (int nt = 0; nt < 8; nt++) {
                mma16816(s[nt], ah, bh[nt]);
                mma16816(s[nt], ah, bl[nt]);
                mma16816(s[nt], al, bh[nt]);
            }
        }

#pragma unroll
        for (int nt = 0; nt < 8; nt++) {
            int col = k0g + nt * 8 + ((lane & 3) << 1);
            int d0 = row_q - col;     if (d0 < 0) d0 = -d0;
            int d1 = row_q - col - 1; if (d1 < 0) d1 = -d1;
            int d2 = row_q + 8 - col;     if (d2 < 0) d2 = -d2;
            int d3 = row_q + 8 - col - 1; if (d3 < 0) d3 = -d3;
            float e0 = __expf(fmaf(s[nt][0], scale, rc[d0]));
            float e1 = __expf(fmaf(s[nt][1], scale, rc[d1]));
            float e2 = __expf(fmaf(s[nt][2], scale, rc[d2]));
            float e3 = __expf(fmaf(s[nt][3], scale, rc[d3]));
            s[nt][0] = e0; s[nt][1] = e1; s[nt][2] = e2; s[nt][3] = e3;
            rs0 += e0 + e1;
            rs1 += e2 + e3;
            if (write_attn) {
                float* ap = attn + ((size_t)bh_i * N_ + row_q) * N_ + col;
                *(float2*)ap = make_float2(e0, e1);
                *(float2*)(ap + 8 * N_) = make_float2(e2, e3);
            }
        }

        uint32_t vb0 = kb + 2 * 4608 * 2;
#pragma unroll
        for (int ks = 0; ks < 4; ks++) {
            uint32_t eah[4], eal[4];
            {
                float c0 = s[2 * ks][0], c1 = s[2 * ks][1];
                float c2 = s[2 * ks][2], c3 = s[2 * ks][3];
                float c4 = s[2 * ks + 1][0], c5 = s[2 * ks + 1][1];
                float c6 = s[2 * ks + 1][2], c7 = s[2 * ks + 1][3];
                eah[0] = pkbf(c0, c1); eah[1] = pkbf(c2, c3);
                eah[2] = pkbf(c4, c5); eah[3] = pkbf(c6, c7);
                float hh;
                hh = __bfloat162float(__float2bfloat16(c0)); c0 -= hh;
                hh = __bfloat162float(__float2bfloat16(c1)); c1 -= hh;
                hh = __bfloat162float(__float2bfloat16(c2)); c2 -= hh;
                hh = __bfloat162float(__float2bfloat16(c3)); c3 -= hh;
                hh = __bfloat162float(__float2bfloat16(c4)); c4 -= hh;
                hh = __bfloat162float(__float2bfloat16(c5)); c5 -= hh;
                hh = __bfloat162float(__float2bfloat16(c6)); c6 -= hh;
                hh = __bfloat162float(__float2bfloat16(c7)); c7 -= hh;
                eal[0] = pkbf(c0, c1); eal[1] = pkbf(c2, c3);
                eal[2] = pkbf(c4, c5); eal[3] = pkbf(c6, c7);
            }
            uint32_t vbh[8][2], vbl[8][2];
#pragma unroll
            for (int ng = 0; ng < 4; ng++) {
                int brow = ng * 16 + (lane & 7) + ((lane & 16) >> 1);
                int bcol = ks * 16 + ((lane >> 3) & 1) * 8;
                uint32_t ba = vb0 + (uint32_t)(brow * AT_STR + bcol) * 2;
                ldsm4(vbh[2 * ng][0], vbh[2 * ng][1], vbh[2 * ng + 1][0],
                      vbh[2 * ng + 1][1], ba);
                ldsm4(vbl[2 * ng][0], vbl[2 * ng][1], vbl[2 * ng + 1][0],
                      vbl[2 * ng + 1][1], ba + 4608 * 2);
            }
#pragma unroll
            for (int nh = 0; nh < 8; nh++) {
                mma16816(co[nh], eah, vbh[nh]);
                mma16816(co[nh], eah, vbl[nh]);
                mma16816(co[nh], eal, vbh[nh]);
            }
        }

        if (t + 2 < N_ / 64) issue_kv(t + 2);
    }

    rs0 += __shfl_xor_sync(0xffffffffu, rs0, 1);
    rs0 += __shfl_xor_sync(0xffffffffu, rs0, 2);
    rs1 += __shfl_xor_sync(0xffffffffu, rs1, 1);
    rs1 += __shfl_xor_sync(0xffffffffu, rs1, 2);
    if ((lane & 3) == 0) {
        g_rowsum[(size_t)bh_i * N_ + row_q] = rs0;
        g_rowsum[(size_t)bh_i * N_ + row_q + 8] = rs1;
    }

    float inv0 = 1.0f / rs0, inv1 = 1.0f / rs1;
#pragma unroll
    for (int nh = 0; nh < 8; nh++) {
        int hd = nh * 8 + ((lane & 3) << 1);
        size_t p = ((size_t)(b * N_ + row_q)) * D_ + h * HD_ + hd;
        split_st2(g_aoh, g_aol, p, make_float2(co[nh][0] * inv0, co[nh][1] * inv0));
        split_st2(g_aoh, g_aol, p + 8 * D_,
                  make_float2(co[nh][2] * inv1, co[nh][3] * inv1));
    }
}

// =============================================================================
extern "C" void kernel_launch(void* const* d_in, const int* in_sizes, int n_in,
                              void* d_out, int out_size) {
    const float* query = (const float*)d_in[0];
    const float* w_in  = (const float*)d_in[4];
    const float* b_in  = (const float*)d_in[5];
    const float* w_out = (const float*)d_in[6];
    const float* b_out = (const float*)d_in[7];
    const float* rpe   = (const float*)d_in[8];

    float* out  = (float*)d_out;
    const long long out_elems  = (long long)B_ * N_ * D_;
    const long long attn_elems = (long long)BH_ * N_ * N_;
    int write_attn = ((long long)out_size >= out_elems + attn_elems) ? 1 : 0;
    float* attn = out + out_elems;

    cudaFuncSetAttribute(attn_kernel, cudaFuncAttributeMaxDynamicSharedMemorySize,
                         ATTN_SMEM);
    cudaFuncSetAttribute(qkv_gemm_k, cudaFuncAttributeMaxDynamicSharedMemorySize,
                         GEMM_SMEM);
    cudaFuncSetAttribute(out_norm_kernel, cudaFuncAttributeMaxDynamicSharedMemorySize,
                         GEMM_SMEM);

    __nv_bfloat16 *xh, *xl, *wih, *wil, *aoh, *aol, *woh, *wol;
    cudaGetSymbolAddress((void**)&xh,  g_xh);
    cudaGetSymbolAddress((void**)&xl,  g_xl);
    cudaGetSymbolAddress((void**)&wih, g_wih);
    cudaGetSymbolAddress((void**)&wil, g_wil);
    cudaGetSymbolAddress((void**)&aoh, g_aoh);
    cudaGetSymbolAddress((void**)&aol, g_aol);
    cudaGetSymbolAddress((void**)&woh, g_woh);
    cudaGetSymbolAddress((void**)&wol, g_wol);

    cvt3_kernel<<<8192, 256>>>(query, xh, xl, w_in, wih, wil, w_out, woh, wol);

    qkv_gemm_k<<<dim3(24, 32), 256, GEMM_SMEM>>>(xh, xl, wih, wil, b_in);

    attn_kernel<<<dim3(16, 16, 2), 256, ATTN_SMEM>>>(attn, rpe, write_attn);

    out_norm_kernel<<<256 + NN_BLOCKS, 256, GEMM_SMEM>>>(
        aoh, aol, woh, wol, b_out, out, attn, write_attn);
}

// round 12
// speedup vs baseline: 1.4981x; 1.0213x over previous
#include <cuda_runtime.h>
#include <cuda_bf16.h>
#include <cstdint>

#define B_  2
#define N_  2048
#define D_  1024
#define H_  16
#define HD_ 64
#define S_  2048
#define BH_ (B_*H_)

// ---------------- scratch ----------------------------------------------------
static __device__ float g_rowsum[(size_t)BH_*N_];

static __device__ __nv_bfloat16 g_xh[(size_t)4096*1024];
static __device__ __nv_bfloat16 g_xl[(size_t)4096*1024];
static __device__ __nv_bfloat16 g_wih[(size_t)3072*1024];
static __device__ __nv_bfloat16 g_wil[(size_t)3072*1024];
static __device__ __nv_bfloat16 g_aoh[(size_t)4096*1024];
static __device__ __nv_bfloat16 g_aol[(size_t)4096*1024];
static __device__ __nv_bfloat16 g_woh[(size_t)1024*1024];
static __device__ __nv_bfloat16 g_wol[(size_t)1024*1024];

static __device__ __nv_bfloat16 g_Qh[(size_t)BH_*N_*HD_];   // [bh,n,hd]
static __device__ __nv_bfloat16 g_Ql[(size_t)BH_*N_*HD_];
static __device__ __nv_bfloat16 g_Kh[(size_t)BH_*N_*HD_];
static __device__ __nv_bfloat16 g_Kl[(size_t)BH_*N_*HD_];
static __device__ __nv_bfloat16 g_Vth[(size_t)BH_*HD_*N_];  // [bh,hd,n]
static __device__ __nv_bfloat16 g_Vtl[(size_t)BH_*HD_*N_];

// ---------------- helpers ----------------------------------------------------
__device__ __forceinline__ uint32_t smem_u32(const void* p) {
    uint32_t a;
    asm("{ .reg .u64 t; cvta.to.shared.u64 t, %1; cvt.u32.u64 %0, t; }"
        : "=r"(a) : "l"(p));
    return a;
}
__device__ __forceinline__ void cp16(uint32_t dst, const void* src) {
    asm volatile("cp.async.cg.shared.global [%0], [%1], 16;" :: "r"(dst), "l"(src));
}
#define CP_COMMIT asm volatile("cp.async.commit_group;" ::: "memory")
#define CP_WAIT0  asm volatile("cp.async.wait_group 0;" ::: "memory")
#define CP_WAIT1  asm volatile("cp.async.wait_group 1;" ::: "memory")

__device__ __forceinline__ void ldsm4(uint32_t& r0, uint32_t& r1, uint32_t& r2,
                                      uint32_t& r3, uint32_t addr) {
    asm volatile("ldmatrix.sync.aligned.m8n8.x4.shared.b16 {%0,%1,%2,%3}, [%4];"
                 : "=r"(r0), "=r"(r1), "=r"(r2), "=r"(r3) : "r"(addr));
}
__device__ __forceinline__ void mma16816(float* c, const uint32_t* a,
                                         const uint32_t* b) {
    asm volatile(
        "mma.sync.aligned.m16n8k16.row.col.f32.bf16.bf16.f32 "
        "{%0,%1,%2,%3}, {%4,%5,%6,%7}, {%8,%9}, {%0,%1,%2,%3};"
        : "+f"(c[0]), "+f"(c[1]), "+f"(c[2]), "+f"(c[3])
        : "r"(a[0]), "r"(a[1]), "r"(a[2]), "r"(a[3]), "r"(b[0]), "r"(b[1]));
}
__device__ __forceinline__ uint32_t pkbf(float lo, float hi) {
    uint32_t d;
    asm("cvt.rn.bf16x2.f32 %0, %1, %2;" : "=r"(d) : "f"(hi), "f"(lo));
    return d;
}

// =============================================================================
// fp32 -> bf16 hi/lo split, 3 tensors in one launch
// =============================================================================
__global__ void __launch_bounds__(256) cvt3_kernel(
        const float* __restrict__ x0, __nv_bfloat16* __restrict__ h0p,
        __nv_bfloat16* __restrict__ l0p,
        const float* __restrict__ x1, __nv_bfloat16* __restrict__ h1p,
        __nv_bfloat16* __restrict__ l1p,
        const float* __restrict__ x2, __nv_bfloat16* __restrict__ h2p,
        __nv_bfloat16* __restrict__ l2p) {
    int blk = blockIdx.x;
    const float* x; __nv_bfloat16 *hi, *lo; int i;
    if (blk < 4096)      { x = x0; hi = h0p; lo = l0p; i = blk * 256 + threadIdx.x; }
    else if (blk < 7168) { x = x1; hi = h1p; lo = l1p; i = (blk - 4096) * 256 + threadIdx.x; }
    else                 { x = x2; hi = h2p; lo = l2p; i = (blk - 7168) * 256 + threadIdx.x; }
    float4 v = ((const float4*)x)[i];
    __nv_bfloat16 a0 = __float2bfloat16(v.x), a1 = __float2bfloat16(v.y);
    __nv_bfloat16 a2 = __float2bfloat16(v.z), a3 = __float2bfloat16(v.w);
    ((__nv_bfloat162*)hi)[2 * i] = __nv_bfloat162(a0, a1);
    ((__nv_bfloat162*)hi)[2 * i + 1] = __nv_bfloat162(a2, a3);
    ((__nv_bfloat162*)lo)[2 * i] = __nv_bfloat162(
        __float2bfloat16(v.x - __bfloat162float(a0)),
        __float2bfloat16(v.y - __bfloat162float(a1)));
    ((__nv_bfloat162*)lo)[2 * i + 1] = __nv_bfloat162(
        __float2bfloat16(v.z - __bfloat162float(a2)),
        __float2bfloat16(v.w - __bfloat162float(a3)));
}

// =============================================================================
// Split-bf16 GEMM core (device function)
// =============================================================================
#define SSTR  40
#define ARRB  (128*SSTR*2)
#define STAGE (4*ARRB)
#define GEMM_SMEM (2*STAGE)

__device__ __forceinline__ void split_st2(__nv_bfloat16* dh, __nv_bfloat16* dl,
                                          size_t idx, float2 v) {
    __nv_bfloat16 h0 = __float2bfloat16(v.x), h1 = __float2bfloat16(v.y);
    *(__nv_bfloat162*)(dh + idx) = __nv_bfloat162(h0, h1);
    *(__nv_bfloat162*)(dl + idx) = __nv_bfloat162(
        __float2bfloat16(v.x - __bfloat162float(h0)),
        __float2bfloat16(v.y - __bfloat162float(h1)));
}
__device__ __forceinline__ void split_st1(__nv_bfloat16* dh, __nv_bfloat16* dl,
                                          size_t idx, float v) {
    __nv_bfloat16 h = __float2bfloat16(v);
    dh[idx] = h;
    dl[idx] = __float2bfloat16(v - __bfloat162float(h));
}

template<bool QKV>
__device__ __forceinline__ void gemm_body(
        uint32_t sb, int m0, int n0,
        const __nv_bfloat16* __restrict__ Ah_g, const __nv_bfloat16* __restrict__ Al_g,
        const __nv_bfloat16* __restrict__ Bh_g, const __nv_bfloat16* __restrict__ Bl_g,
        const float* __restrict__ bias, float* __restrict__ outp) {
    int tid = threadIdx.x, lane = tid & 31, wid = tid >> 5;
    int wm = wid >> 1, wn = wid & 1;

    const __nv_bfloat16* base[4] = {
        Ah_g + (size_t)m0 * 1024, Al_g + (size_t)m0 * 1024,
        Bh_g + (size_t)n0 * 1024, Bl_g + (size_t)n0 * 1024 };

    float c[2][8][4];
#pragma unroll
    for (int mt = 0; mt < 2; mt++)
#pragma unroll
        for (int nt = 0; nt < 8; nt++)
#pragma unroll
            for (int q = 0; q < 4; q++) c[mt][nt][q] = 0.f;

    int r_ld = tid >> 2, c_ld = (tid & 3) << 3;

    {
#pragma unroll
        for (int arr = 0; arr < 4; arr++)
#pragma unroll
            for (int j = 0; j < 2; j++) {
                int r = r_ld + j * 64;
                cp16(sb + arr * ARRB + (uint32_t)(r * SSTR + c_ld) * 2,
                     base[arr] + (size_t)r * 1024 + c_ld);
            }
        CP_COMMIT;
    }

#pragma unroll 1
    for (int t = 0; t < 32; t++) {
        if (t + 1 < 32) {
            int s = (t + 1) & 1, k0 = (t + 1) << 5;
#pragma unroll
            for (int arr = 0; arr < 4; arr++)
#pragma unroll
                for (int j = 0; j < 2; j++) {
                    int r = r_ld + j * 64;
                    cp16(sb + (uint32_t)s * STAGE + arr * ARRB +
                             (uint32_t)(r * SSTR + c_ld) * 2,
                         base[arr] + (size_t)r * 1024 + k0 + c_ld);
                }
            CP_COMMIT;
            CP_WAIT1;
        } else {
            CP_WAIT0;
        }
        __syncthreads();

        uint32_t st = sb + (uint32_t)(t & 1) * STAGE;
#pragma unroll
        for (int kk = 0; kk < 2; kk++) {
            uint32_t bh[8][2], bl[8][2];
#pragma unroll
            for (int ng = 0; ng < 4; ng++) {
                int brow = wn * 64 + ng * 16 + (lane & 7) + ((lane & 16) >> 1);
                int bcol = kk * 16 + ((lane >> 3) & 1) * 8;
                uint32_t ba = st + 2 * ARRB + (uint32_t)(brow * SSTR + bcol) * 2;
                ldsm4(bh[2 * ng][0], bh[2 * ng][1], bh[2 * ng + 1][0],
                      bh[2 * ng + 1][1], ba);
                ldsm4(bl[2 * ng][0], bl[2 * ng][1], bl[2 * ng + 1][0],
                      bl[2 * ng + 1][1], ba + ARRB);
            }
#pragma unroll
            for (int mt = 0; mt < 2; mt++) {
                int arow = wm * 32 + mt * 16 + (lane & 15);
                int acol = kk * 16 + (lane >> 4) * 8;
                uint32_t aa = st + (uint32_t)(arow * SSTR + acol) * 2;
                uint32_t ah[4], al[4];
                ldsm4(ah[0], ah[1], ah[2], ah[3], aa);
                ldsm4(al[0], al[1], al[2], al[3], aa + ARRB);
#pragma unroll
                for (int nt = 0; nt < 8; nt++) {
                    mma16816(c[mt][nt], ah, bh[nt]);
                    mma16816(c[mt][nt], ah, bl[nt]);
                    mma16816(c[mt][nt], al, bh[nt]);
                }
            }
        }
        __syncthreads();
    }

#pragma unroll
    for (int mt = 0; mt < 2; mt++) {
        int m = m0 + wm * 32 + mt * 16 + (lane >> 2);
#pragma unroll
        for (int nt = 0; nt < 8; nt++) {
            int n = n0 + wn * 64 + nt * 8 + ((lane & 3) << 1);
            float b0 = bias[n], b1 = bias[n + 1];
            float2 v0 = make_float2(c[mt][nt][0] + b0, c[mt][nt][1] + b1);
            float2 v1 = make_float2(c[mt][nt][2] + b0, c[mt][nt][3] + b1);
            if (QKV) {
                int sect = n >> 10;
                int h = (n & 1023) >> 6, hd = n & 63;
                int bb = m >> 11, row = m & 2047;
                int bh_i = bb * H_ + h;
                if (sect < 2) {
                    __nv_bfloat16* dh = sect == 0 ? g_Qh : g_Kh;
                    __nv_bfloat16* dl = sect == 0 ? g_Ql : g_Kl;
                    size_t p = ((size_t)bh_i * N_ + row) * HD_ + hd;
                    split_st2(dh, dl, p, v0);
                    split_st2(dh, dl, p + 8 * HD_, v1);
                } else {
                    size_t pb = ((size_t)bh_i * HD_ + hd) * N_ + row;
                    split_st1(g_Vth, g_Vtl, pb, v0.x);
                    split_st1(g_Vth, g_Vtl, pb + N_, v0.y);
                    split_st1(g_Vth, g_Vtl, pb + 8, v1.x);
                    split_st1(g_Vth, g_Vtl, pb + N_ + 8, v1.y);
                }
            } else {
                float* p = outp + (size_t)m * 1024 + n;
                *(float2*)p = v0;
                *(float2*)(p + 8 * 1024) = v1;
            }
        }
    }
}

__global__ void __launch_bounds__(256) qkv_gemm_k(
        const __nv_bfloat16* __restrict__ Ah_g, const __nv_bfloat16* __restrict__ Al_g,
        const __nv_bfloat16* __restrict__ Bh_g, const __nv_bfloat16* __restrict__ Bl_g,
        const float* __restrict__ bias) {
    extern __shared__ char smem[];
    gemm_body<true>(smem_u32(smem), blockIdx.y << 7, blockIdx.x << 7,
                    Ah_g, Al_g, Bh_g, Bl_g, bias, nullptr);
}

// =============================================================================
// Fused out-projection GEMM + attn normalize (proven R10 version)
// =============================================================================
#define NN_BLOCKS 2048

__global__ void __launch_bounds__(256, 2) out_norm_kernel(
        const __nv_bfloat16* __restrict__ Ah_g, const __nv_bfloat16* __restrict__ Al_g,
        const __nv_bfloat16* __restrict__ Bh_g, const __nv_bfloat16* __restrict__ Bl_g,
        const float* __restrict__ bias, float* __restrict__ outp,
        float* __restrict__ attn, int write_attn) {
    int blk = blockIdx.x;
    if (blk < 256) {
        extern __shared__ char smem[];
        int n0 = (blk & 7) << 7, m0 = (blk >> 3) << 7;
        gemm_body<false>(smem_u32(smem), m0, n0, Ah_g, Al_g, Bh_g, Bl_g, bias, outp);
        return;
    }
    if (!write_attn) return;
    const size_t total4 = (size_t)BH_ * N_ * N_ / 4;
    const size_t per_blk = total4 / NN_BLOCKS;
    size_t i0 = (size_t)(blk - 256) * per_blk;
    int tid = threadIdx.x;
#pragma unroll 1
    for (int it = 0; it < 8; it++) {
        size_t idx[8];
        float4 v[8];
#pragma unroll
        for (int u = 0; u < 8; u++) {
            idx[u] = i0 + (size_t)(it * 8 + u) * 256 + tid;
            v[u] = __ldcs((const float4*)attn + idx[u]);
        }
#pragma unroll
        for (int u = 0; u < 8; u++) {
            int row = (int)(idx[u] >> 9);
            float inv = 1.0f / g_rowsum[row];
            v[u].x *= inv; v[u].y *= inv; v[u].z *= inv; v[u].w *= inv;
            __stcs((float4*)attn + idx[u], v[u]);
        }
    }
}

// =============================================================================
// HMMA split-bf16 fused attention: 2-stage KV ring (extra sync before reuse),
// bf16 rpe column, 2 CTAs/SM via launch_bounds(256,2).
// =============================================================================
#define AT_STR 72
#define AQH 0
#define AQL (128*AT_STR)
#define AKV (2*128*AT_STR)
#define KVSTG (4*64*AT_STR)
#define ABF_END (AKV + 2*KVSTG)             // 55296 bf16 units
#define ATTN_SMEM (ABF_END*2 + 2048*2)      // 114688 B  (2 CTAs/SM)

__global__ void __launch_bounds__(256, 2) attn_kernel(float* __restrict__ attn,
                                                      const float* __restrict__ rpe,
                                                      int write_attn) {
    extern __shared__ char smc[];
    uint32_t sb = smem_u32(smc);
    __nv_bfloat16* rc = (__nv_bfloat16*)(smc + ABF_END * 2);

    int qt = blockIdx.x, h = blockIdx.y, b = blockIdx.z;
    int bh_i = b * H_ + h;
    int tid = threadIdx.x, lane = tid & 31, wm = tid >> 5;
    int q0 = qt << 7;

    for (int i = tid; i < S_; i += 256)
        rc[i] = __float2bfloat16(rpe[(size_t)i * H_ + h]);

    const __nv_bfloat16* qhg = g_Qh + ((size_t)bh_i * N_ + q0) * HD_;
    const __nv_bfloat16* qlg = g_Ql + ((size_t)bh_i * N_ + q0) * HD_;
    const __nv_bfloat16* khg = g_Kh + (size_t)bh_i * N_ * HD_;
    const __nv_bfloat16* klg = g_Kl + (size_t)bh_i * N_ * HD_;
    const __nv_bfloat16* vhg = g_Vth + (size_t)bh_i * HD_ * N_;
    const __nv_bfloat16* vlg = g_Vtl + (size_t)bh_i * HD_ * N_;

#pragma unroll
    for (int j = 0; j < 4; j++) {
        int u = tid + j * 256;
        int r = u >> 3, ch = (u & 7) << 3;
        cp16(sb + (uint32_t)(AQH + r * AT_STR + ch) * 2, qhg + (size_t)r * HD_ + ch);
        cp16(sb + (uint32_t)(AQL + r * AT_STR + ch) * 2, qlg + (size_t)r * HD_ + ch);
    }
    CP_COMMIT;

    int r_ld = tid >> 3, c_ld = (tid & 7) << 3;
    auto issue_kv = [&](int t) {
        int k0g = t * 64;
        uint32_t stg = sb + (uint32_t)(AKV + (t & 1) * KVSTG) * 2;
#pragma unroll
        for (int j = 0; j < 2; j++) {
            int r = r_ld + j * 32, ch = c_ld;
            cp16(stg + (uint32_t)(0 * 4608 + r * AT_STR + ch) * 2,
                 khg + (size_t)(k0g + r) * HD_ + ch);
            cp16(stg + (uint32_t)(1 * 4608 + r * AT_STR + ch) * 2,
                 klg + (size_t)(k0g + r) * HD_ + ch);
            cp16(stg + (uint32_t)(2 * 4608 + r * AT_STR + ch) * 2,
                 vhg + (size_t)r * N_ + k0g + ch);
            cp16(stg + (uint32_t)(3 * 4608 + r * AT_STR + ch) * 2,
                 vlg + (size_t)r * N_ + k0g + ch);
        }
        CP_COMMIT;
    };
    issue_kv(0);
    issue_kv(1);

    float co[8][4];
#pragma unroll
    for (int nh = 0; nh < 8; nh++)
#pragma unroll
        for (int q = 0; q < 4; q++) co[nh][q] = 0.f;
    float rs0 = 0.f, rs1 = 0.f;

    int row_q = q0 + wm * 16 + (lane >> 2);
    const float scale = 0.125f;

#pragma unroll 1
    for (int t = 0; t < N_ / 64; t++) {
        if (t < 31) { CP_WAIT1; } else { CP_WAIT0; }
        __syncthreads();

        int k0g = t * 64;
        uint32_t kb = sb + (uint32_t)(AKV + (t & 1) * KVSTG) * 2;

        float s[8][4];
#pragma unroll
        for (int nt = 0; nt < 8; nt++)
#pragma unroll
            for (int q = 0; q < 4; q++) s[nt][q] = 0.f;
#pragma unroll
        for (int ks = 0; ks < 4; ks++) {
            int arow = wm * 16 + (lane & 15);
            int acol = ks * 16 + (lane >> 4) * 8;
            uint32_t aa = sb + (uint32_t)(AQH + arow * AT_STR + acol) * 2;
            uint32_t ah[4], al[4];
            ldsm4(ah[0], ah[1], ah[2], ah[3], aa);
            ldsm4(al[0], al[1], al[2], al[3], aa + AQL * 2);
            uint32_t bh[8][2], bl[8][2];
#pragma unroll
            for (int ng = 0; ng < 4; ng++) {
                int brow = ng * 16 + (lane & 7) + ((lane & 16) >> 1);
                int bcol = ks * 16 + ((lane >> 3) & 1) * 8;
                uint32_t ba = kb + (uint32_t)(brow * AT_STR + bcol) * 2;
                ldsm4(bh[2 * ng][0], bh[2 * ng][1], bh[2 * ng + 1][0],
                      bh[2 * ng + 1][1], ba);
                ldsm4(bl[2 * ng][0], bl[2 * ng][1], bl[2 * ng + 1][0],
                      bl[2 * ng + 1][1], ba + 4608 * 2);
            }
#pragma unroll
            for (int nt = 0; nt < 8; nt++) {
                mma16816(s[nt], ah, bh[nt]);
                mma16816(s[nt], ah, bl[nt]);
                mma16816(s[nt], al, bh[nt]);
            }
        }

#pragma unroll
        for (int nt = 0; nt < 8; nt++) {
            int col = k0g + nt * 8 + ((lane & 3) << 1);
            int d0 = row_q - col;     if (d0 < 0) d0 = -d0;
            int d1 = row_q - col - 1; if (d1 < 0) d1 = -d1;
            int d2 = row_q + 8 - col;     if (d2 < 0) d2 = -d2;
            int d3 = row_q + 8 - col - 1; if (d3 < 0) d3 = -d3;
            float e0 = __expf(fmaf(s[nt][0], scale, __bfloat162float(rc[d0])));
            float e1 = __expf(fmaf(s[nt][1], scale, __bfloat162float(rc[d1])));
            float e2 = __expf(fmaf(s[nt][2], scale, __bfloat162float(rc[d2])));
            float e3 = __expf(fmaf(s[nt][3], scale, __bfloat162float(rc[d3])));
            s[nt][0] = e0; s[nt][1] = e1; s[nt][2] = e2; s[nt][3] = e3;
            rs0 += e0 + e1;
            rs1 += e2 + e3;
            if (write_attn) {
                float* ap = attn + ((size_t)bh_i * N_ + row_q) * N_ + col;
                *(float2*)ap = make_float2(e0, e1);
                *(float2*)(ap + 8 * N_) = make_float2(e2, e3);
            }
        }

        uint32_t vb0 = kb + 2 * 4608 * 2;
#pragma unroll
        for (int ks = 0; ks < 4; ks++) {
            uint32_t eah[4], eal[4];
            {
                float c0 = s[2 * ks][0], c1 = s[2 * ks][1];
                float c2 = s[2 * ks][2], c3 = s[2 * ks][3];
                float c4 = s[2 * ks + 1][0], c5 = s[2 * ks + 1][1];
                float c6 = s[2 * ks + 1][2], c7 = s[2 * ks + 1][3];
                eah[0] = pkbf(c0, c1); eah[1] = pkbf(c2, c3);
                eah[2] = pkbf(c4, c5); eah[3] = pkbf(c6, c7);
                float hh;
                hh = __bfloat162float(__float2bfloat16(c0)); c0 -= hh;
                hh = __bfloat162float(__float2bfloat16(c1)); c1 -= hh;
                hh = __bfloat162float(__float2bfloat16(c2)); c2 -= hh;
                hh = __bfloat162float(__float2bfloat16(c3)); c3 -= hh;
                hh = __bfloat162float(__float2bfloat16(c4)); c4 -= hh;
                hh = __bfloat162float(__float2bfloat16(c5)); c5 -= hh;
                hh = __bfloat162float(__float2bfloat16(c6)); c6 -= hh;
                hh = __bfloat162float(__float2bfloat16(c7)); c7 -= hh;
                eal[0] = pkbf(c0, c1); eal[1] = pkbf(c2, c3);
                eal[2] = pkbf(c4, c5); eal[3] = pkbf(c6, c7);
            }
            uint32_t vbh[8][2], vbl[8][2];
#pragma unroll
            for (int ng = 0; ng < 4; ng++) {
                int brow = ng * 16 + (lane & 7) + ((lane & 16) >> 1);
                int bcol = ks * 16 + ((lane >> 3) & 1) * 8;
                uint32_t ba = vb0 + (uint32_t)(brow * AT_STR + bcol) * 2;
                ldsm4(vbh[2 * ng][0], vbh[2 * ng][1], vbh[2 * ng + 1][0],
                      vbh[2 * ng + 1][1], ba);
                ldsm4(vbl[2 * ng][0], vbl[2 * ng][1], vbl[2 * ng + 1][0],
                      vbl[2 * ng + 1][1], ba + 4608 * 2);
            }
#pragma unroll
            for (int nh = 0; nh < 8; nh++) {
                mma16816(co[nh], eah, vbh[nh]);
                mma16816(co[nh], eah, vbl[nh]);
                mma16816(co[nh], eal, vbh[nh]);
            }
        }

        // stage (t) fully consumed by all warps before reuse by t+2
        __syncthreads();
        if (t + 2 < N_ / 64) issue_kv(t + 2);
    }

    rs0 += __shfl_xor_sync(0xffffffffu, rs0, 1);
    rs0 += __shfl_xor_sync(0xffffffffu, rs0, 2);
    rs1 += __shfl_xor_sync(0xffffffffu, rs1, 1);
    rs1 += __shfl_xor_sync(0xffffffffu, rs1, 2);
    if ((lane & 3) == 0) {
        g_rowsum[(size_t)bh_i * N_ + row_q] = rs0;
        g_rowsum[(size_t)bh_i * N_ + row_q + 8] = rs1;
    }

    float inv0 = 1.0f / rs0, inv1 = 1.0f / rs1;
#pragma unroll
    for (int nh = 0; nh < 8; nh++) {
        int hd = nh * 8 + ((lane & 3) << 1);
        size_t p = ((size_t)(b * N_ + row_q)) * D_ + h * HD_ + hd;
        split_st2(g_aoh, g_aol, p, make_float2(co[nh][0] * inv0, co[nh][1] * inv0));
        split_st2(g_aoh, g_aol, p + 8 * D_,
                  make_float2(co[nh][2] * inv1, co[nh][3] * inv1));
    }
}

// =============================================================================
extern "C" void kernel_launch(void* const* d_in, const int* in_sizes, int n_in,
                              void* d_out, int out_size) {
    const float* query = (const float*)d_in[0];
    const float* w_in  = (const float*)d_in[4];
    const float* b_in  = (const float*)d_in[5];
    const float* w_out = (const float*)d_in[6];
    const float* b_out = (const float*)d_in[7];
    const float* rpe   = (const float*)d_in[8];

    float* out  = (float*)d_out;
    const long long out_elems  = (long long)B_ * N_ * D_;
    const long long attn_elems = (long long)BH_ * N_ * N_;
    int write_attn = ((long long)out_size >= out_elems + attn_elems) ? 1 : 0;
    float* attn = out + out_elems;

    cudaFuncSetAttribute(attn_kernel, cudaFuncAttributeMaxDynamicSharedMemorySize,
                         ATTN_SMEM);
    cudaFuncSetAttribute(qkv_gemm_k, cudaFuncAttributeMaxDynamicSharedMemorySize,
                         GEMM_SMEM);
    cudaFuncSetAttribute(out_norm_kernel, cudaFuncAttributeMaxDynamicSharedMemorySize,
                         GEMM_SMEM);

    __nv_bfloat16 *xh, *xl, *wih, *wil, *aoh, *aol, *woh, *wol;
    cudaGetSymbolAddress((void**)&xh,  g_xh);
    cudaGetSymbolAddress((void**)&xl,  g_xl);
    cudaGetSymbolAddress((void**)&wih, g_wih);
    cudaGetSymbolAddress((void**)&wil, g_wil);
    cudaGetSymbolAddress((void**)&aoh, g_aoh);
    cudaGetSymbolAddress((void**)&aol, g_aol);
    cudaGetSymbolAddress((void**)&woh, g_woh);
    cudaGetSymbolAddress((void**)&wol, g_wol);

    cvt3_kernel<<<8192, 256>>>(query, xh, xl, w_in, wih, wil, w_out, woh, wol);

    qkv_gemm_k<<<dim3(24, 32), 256, GEMM_SMEM>>>(xh, xl, wih, wil, b_in);

    attn_kernel<<<dim3(16, 16, 2), 256, ATTN_SMEM>>>(attn, rpe, write_attn);

    out_norm_kernel<<<256 + NN_BLOCKS, 256, GEMM_SMEM>>>(
        aoh, aol, woh, wol, b_out, out, attn, write_attn);
}

// round 13
// speedup vs baseline: 1.6802x; 1.1215x over previous
#include <cuda_runtime.h>
#include <cuda_bf16.h>
#include <cuda_fp16.h>
#include <cstdint>

#define B_  2
#define N_  2048
#define D_  1024
#define H_  16
#define HD_ 64
#define S_  2048
#define BH_ (B_*H_)

// ---------------- scratch ----------------------------------------------------
static __device__ float g_rowsum[(size_t)BH_*N_];

static __device__ __nv_bfloat16 g_xh[(size_t)4096*1024];
static __device__ __nv_bfloat16 g_xl[(size_t)4096*1024];
static __device__ __nv_bfloat16 g_wih[(size_t)3072*1024];
static __device__ __nv_bfloat16 g_wil[(size_t)3072*1024];
static __device__ __nv_bfloat16 g_aoh[(size_t)4096*1024];
static __device__ __nv_bfloat16 g_aol[(size_t)4096*1024];
static __device__ __nv_bfloat16 g_woh[(size_t)1024*1024];
static __device__ __nv_bfloat16 g_wol[(size_t)1024*1024];

static __device__ __nv_bfloat16 g_Qh[(size_t)BH_*N_*HD_];   // [bh,n,hd]
static __device__ __nv_bfloat16 g_Ql[(size_t)BH_*N_*HD_];
static __device__ __nv_bfloat16 g_Kh[(size_t)BH_*N_*HD_];
static __device__ __nv_bfloat16 g_Kl[(size_t)BH_*N_*HD_];
static __device__ __half      g_Vt[(size_t)BH_*HD_*N_];     // fp16, [bh,hd,n]

// ---------------- helpers ----------------------------------------------------
__device__ __forceinline__ uint32_t smem_u32(const void* p) {
    uint32_t a;
    asm("{ .reg .u64 t; cvta.to.shared.u64 t, %1; cvt.u32.u64 %0, t; }"
        : "=r"(a) : "l"(p));
    return a;
}
__device__ __forceinline__ void cp16(uint32_t dst, const void* src) {
    asm volatile("cp.async.cg.shared.global [%0], [%1], 16;" :: "r"(dst), "l"(src));
}
#define CP_COMMIT asm volatile("cp.async.commit_group;" ::: "memory")
#define CP_WAIT0  asm volatile("cp.async.wait_group 0;" ::: "memory")
#define CP_WAIT1  asm volatile("cp.async.wait_group 1;" ::: "memory")

__device__ __forceinline__ void ldsm4(uint32_t& r0, uint32_t& r1, uint32_t& r2,
                                      uint32_t& r3, uint32_t addr) {
    asm volatile("ldmatrix.sync.aligned.m8n8.x4.shared.b16 {%0,%1,%2,%3}, [%4];"
                 : "=r"(r0), "=r"(r1), "=r"(r2), "=r"(r3) : "r"(addr));
}
__device__ __forceinline__ void mma16816(float* c, const uint32_t* a,
                                         const uint32_t* b) {
    asm volatile(
        "mma.sync.aligned.m16n8k16.row.col.f32.bf16.bf16.f32 "
        "{%0,%1,%2,%3}, {%4,%5,%6,%7}, {%8,%9}, {%0,%1,%2,%3};"
        : "+f"(c[0]), "+f"(c[1]), "+f"(c[2]), "+f"(c[3])
        : "r"(a[0]), "r"(a[1]), "r"(a[2]), "r"(a[3]), "r"(b[0]), "r"(b[1]));
}
__device__ __forceinline__ void mma16816h(float* c, const uint32_t* a,
                                          const uint32_t* b) {
    asm volatile(
        "mma.sync.aligned.m16n8k16.row.col.f32.f16.f16.f32 "
        "{%0,%1,%2,%3}, {%4,%5,%6,%7}, {%8,%9}, {%0,%1,%2,%3};"
        : "+f"(c[0]), "+f"(c[1]), "+f"(c[2]), "+f"(c[3])
        : "r"(a[0]), "r"(a[1]), "r"(a[2]), "r"(a[3]), "r"(b[0]), "r"(b[1]));
}
__device__ __forceinline__ uint32_t pkbf(float lo, float hi) {
    uint32_t d;
    asm("cvt.rn.bf16x2.f32 %0, %1, %2;" : "=r"(d) : "f"(hi), "f"(lo));
    return d;
}
__device__ __forceinline__ uint32_t pkhf(float lo, float hi) {
    uint32_t d;
    asm("cvt.rn.f16x2.f32 %0, %1, %2;" : "=r"(d) : "f"(hi), "f"(lo));
    return d;
}

// =============================================================================
// fp32 -> bf16 hi/lo split, 3 tensors in one launch
// =============================================================================
__global__ void __launch_bounds__(256) cvt3_kernel(
        const float* __restrict__ x0, __nv_bfloat16* __restrict__ h0p,
        __nv_bfloat16* __restrict__ l0p,
        const float* __restrict__ x1, __nv_bfloat16* __restrict__ h1p,
        __nv_bfloat16* __restrict__ l1p,
        const float* __restrict__ x2, __nv_bfloat16* __restrict__ h2p,
        __nv_bfloat16* __restrict__ l2p) {
    int blk = blockIdx.x;
    const float* x; __nv_bfloat16 *hi, *lo; int i;
    if (blk < 4096)      { x = x0; hi = h0p; lo = l0p; i = blk * 256 + threadIdx.x; }
    else if (blk < 7168) { x = x1; hi = h1p; lo = l1p; i = (blk - 4096) * 256 + threadIdx.x; }
    else                 { x = x2; hi = h2p; lo = l2p; i = (blk - 7168) * 256 + threadIdx.x; }
    float4 v = ((const float4*)x)[i];
    __nv_bfloat16 a0 = __float2bfloat16(v.x), a1 = __float2bfloat16(v.y);
    __nv_bfloat16 a2 = __float2bfloat16(v.z), a3 = __float2bfloat16(v.w);
    ((__nv_bfloat162*)hi)[2 * i] = __nv_bfloat162(a0, a1);
    ((__nv_bfloat162*)hi)[2 * i + 1] = __nv_bfloat162(a2, a3);
    ((__nv_bfloat162*)lo)[2 * i] = __nv_bfloat162(
        __float2bfloat16(v.x - __bfloat162float(a0)),
        __float2bfloat16(v.y - __bfloat162float(a1)));
    ((__nv_bfloat162*)lo)[2 * i + 1] = __nv_bfloat162(
        __float2bfloat16(v.z - __bfloat162float(a2)),
        __float2bfloat16(v.w - __bfloat162float(a3)));
}

// =============================================================================
// Split-bf16 GEMM core (device function)
// =============================================================================
#define SSTR  40
#define ARRB  (128*SSTR*2)
#define STAGE (4*ARRB)
#define GEMM_SMEM (2*STAGE)

__device__ __forceinline__ void split_st2(__nv_bfloat16* dh, __nv_bfloat16* dl,
                                          size_t idx, float2 v) {
    __nv_bfloat16 h0 = __float2bfloat16(v.x), h1 = __float2bfloat16(v.y);
    *(__nv_bfloat162*)(dh + idx) = __nv_bfloat162(h0, h1);
    *(__nv_bfloat162*)(dl + idx) = __nv_bfloat162(
        __float2bfloat16(v.x - __bfloat162float(h0)),
        __float2bfloat16(v.y - __bfloat162float(h1)));
}

template<bool QKV>
__device__ __forceinline__ void gemm_body(
        uint32_t sb, int m0, int n0,
        const __nv_bfloat16* __restrict__ Ah_g, const __nv_bfloat16* __restrict__ Al_g,
        const __nv_bfloat16* __restrict__ Bh_g, const __nv_bfloat16* __restrict__ Bl_g,
        const float* __restrict__ bias, float* __restrict__ outp) {
    int tid = threadIdx.x, lane = tid & 31, wid = tid >> 5;
    int wm = wid >> 1, wn = wid & 1;

    const __nv_bfloat16* base[4] = {
        Ah_g + (size_t)m0 * 1024, Al_g + (size_t)m0 * 1024,
        Bh_g + (size_t)n0 * 1024, Bl_g + (size_t)n0 * 1024 };

    float c[2][8][4];
#pragma unroll
    for (int mt = 0; mt < 2; mt++)
#pragma unroll
        for (int nt = 0; nt < 8; nt++)
#pragma unroll
            for (int q = 0; q < 4; q++) c[mt][nt][q] = 0.f;

    int r_ld = tid >> 2, c_ld = (tid & 3) << 3;

    {
#pragma unroll
        for (int arr = 0; arr < 4; arr++)
#pragma unroll
            for (int j = 0; j < 2; j++) {
                int r = r_ld + j * 64;
                cp16(sb + arr * ARRB + (uint32_t)(r * SSTR + c_ld) * 2,
                     base[arr] + (size_t)r * 1024 + c_ld);
            }
        CP_COMMIT;
    }

#pragma unroll 1
    for (int t = 0; t < 32; t++) {
        if (t + 1 < 32) {
            int s = (t + 1) & 1, k0 = (t + 1) << 5;
#pragma unroll
            for (int arr = 0; arr < 4; arr++)
#pragma unroll
                for (int j = 0; j < 2; j++) {
                    int r = r_ld + j * 64;
                    cp16(sb + (uint32_t)s * STAGE + arr * ARRB +
                             (uint32_t)(r * SSTR + c_ld) * 2,
                         base[arr] + (size_t)r * 1024 + k0 + c_ld);
                }
            CP_COMMIT;
            CP_WAIT1;
        } else {
            CP_WAIT0;
        }
        __syncthreads();

        uint32_t st = sb + (uint32_t)(t & 1) * STAGE;
#pragma unroll
        for (int kk = 0; kk < 2; kk++) {
            uint32_t bh[8][2], bl[8][2];
#pragma unroll
            for (int ng = 0; ng < 4; ng++) {
                int brow = wn * 64 + ng * 16 + (lane & 7) + ((lane & 16) >> 1);
                int bcol = kk * 16 + ((lane >> 3) & 1) * 8;
                uint32_t ba = st + 2 * ARRB + (uint32_t)(brow * SSTR + bcol) * 2;
                ldsm4(bh[2 * ng][0], bh[2 * ng][1], bh[2 * ng + 1][0],
                      bh[2 * ng + 1][1], ba);
                ldsm4(bl[2 * ng][0], bl[2 * ng][1], bl[2 * ng + 1][0],
                      bl[2 * ng + 1][1], ba + ARRB);
            }
#pragma unroll
            for (int mt = 0; mt < 2; mt++) {
                int arow = wm * 32 + mt * 16 + (lane & 15);
                int acol = kk * 16 + (lane >> 4) * 8;
                uint32_t aa = st + (uint32_t)(arow * SSTR + acol) * 2;
                uint32_t ah[4], al[4];
                ldsm4(ah[0], ah[1], ah[2], ah[3], aa);
                ldsm4(al[0], al[1], al[2], al[3], aa + ARRB);
#pragma unroll
                for (int nt = 0; nt < 8; nt++) {
                    mma16816(c[mt][nt], ah, bh[nt]);
                    mma16816(c[mt][nt], ah, bl[nt]);
                    mma16816(c[mt][nt], al, bh[nt]);
                }
            }
        }
        __syncthreads();
    }

#pragma unroll
    for (int mt = 0; mt < 2; mt++) {
        int m = m0 + wm * 32 + mt * 16 + (lane >> 2);
#pragma unroll
        for (int nt = 0; nt < 8; nt++) {
            int n = n0 + wn * 64 + nt * 8 + ((lane & 3) << 1);
            float b0 = bias[n], b1 = bias[n + 1];
            float2 v0 = make_float2(c[mt][nt][0] + b0, c[mt][nt][1] + b1);
            float2 v1 = make_float2(c[mt][nt][2] + b0, c[mt][nt][3] + b1);
            if (QKV) {
                int sect = n >> 10;
                int h = (n & 1023) >> 6, hd = n & 63;
                int bb = m >> 11, row = m & 2047;
                int bh_i = bb * H_ + h;
                if (sect < 2) {
                    __nv_bfloat16* dh = sect == 0 ? g_Qh : g_Kh;
                    __nv_bfloat16* dl = sect == 0 ? g_Ql : g_Kl;
                    size_t p = ((size_t)bh_i * N_ + row) * HD_ + hd;
                    split_st2(dh, dl, p, v0);
                    split_st2(dh, dl, p + 8 * HD_, v1);
                } else {
                    size_t pb = ((size_t)bh_i * HD_ + hd) * N_ + row;
                    g_Vt[pb]          = __float2half(v0.x);
                    g_Vt[pb + N_]     = __float2half(v0.y);
                    g_Vt[pb + 8]      = __float2half(v1.x);
                    g_Vt[pb + N_ + 8] = __float2half(v1.y);
                }
            } else {
                float* p = outp + (size_t)m * 1024 + n;
                *(float2*)p = v0;
                *(float2*)(p + 8 * 1024) = v1;
            }
        }
    }
}

__global__ void __launch_bounds__(256) qkv_gemm_k(
        const __nv_bfloat16* __restrict__ Ah_g, const __nv_bfloat16* __restrict__ Al_g,
        const __nv_bfloat16* __restrict__ Bh_g, const __nv_bfloat16* __restrict__ Bl_g,
        const float* __restrict__ bias) {
    extern __shared__ char smem[];
    gemm_body<true>(smem_u32(smem), blockIdx.y << 7, blockIdx.x << 7,
                    Ah_g, Al_g, Bh_g, Bl_g, bias, nullptr);
}

// =============================================================================
// Fused out-projection GEMM + attn normalize (proven R10 version)
// =============================================================================
#define NN_BLOCKS 2048

__global__ void __launch_bounds__(256, 2) out_norm_kernel(
        const __nv_bfloat16* __restrict__ Ah_g, const __nv_bfloat16* __restrict__ Al_g,
        const __nv_bfloat16* __restrict__ Bh_g, const __nv_bfloat16* __restrict__ Bl_g,
        const float* __restrict__ bias, float* __restrict__ outp,
        float* __restrict__ attn, int write_attn) {
    int blk = blockIdx.x;
    if (blk < 256) {
        extern __shared__ char smem[];
        int n0 = (blk & 7) << 7, m0 = (blk >> 3) << 7;
        gemm_body<false>(smem_u32(smem), m0, n0, Ah_g, Al_g, Bh_g, Bl_g, bias, outp);
        return;
    }
    if (!write_attn) return;
    const size_t total4 = (size_t)BH_ * N_ * N_ / 4;
    const size_t per_blk = total4 / NN_BLOCKS;
    size_t i0 = (size_t)(blk - 256) * per_blk;
    int tid = threadIdx.x;
#pragma unroll 1
    for (int it = 0; it < 8; it++) {
        size_t idx[8];
        float4 v[8];
#pragma unroll
        for (int u = 0; u < 8; u++) {
            idx[u] = i0 + (size_t)(it * 8 + u) * 256 + tid;
            v[u] = __ldcs((const float4*)attn + idx[u]);
        }
#pragma unroll
        for (int u = 0; u < 8; u++) {
            int row = (int)(idx[u] >> 9);
            float inv = 1.0f / g_rowsum[row];
            v[u].x *= inv; v[u].y *= inv; v[u].z *= inv; v[u].w *= inv;
            __stcs((float4*)attn + idx[u], v[u]);
        }
    }
}

// =============================================================================
// Fused attention: split-bf16 QK^T (3 MMAs) + single-fp16 AV (1 MMA).
// 2-stage KV ring (Kh, Kl, V-fp16), bf16 rpe column, 2 CTAs/SM.
// =============================================================================
#define AT_STR 72
#define AQH 0
#define AQL (128*AT_STR)
#define AKV (2*128*AT_STR)
#define KVSTG (3*64*AT_STR)                 // Kh + Kl + V(fp16)
#define ABF_END (AKV + 2*KVSTG)             // 46080 b16 units
#define ATTN_SMEM (ABF_END*2 + 2048*2)      // 96256 B  (2 CTAs/SM)

__global__ void __launch_bounds__(256, 2) attn_kernel(float* __restrict__ attn,
                                                      const float* __restrict__ rpe,
                                                      int write_attn) {
    extern __shared__ char smc[];
    uint32_t sb = smem_u32(smc);
    __nv_bfloat16* rc = (__nv_bfloat16*)(smc + ABF_END * 2);

    int qt = blockIdx.x, h = blockIdx.y, b = blockIdx.z;
    int bh_i = b * H_ + h;
    int tid = threadIdx.x, lane = tid & 31, wm = tid >> 5;
    int q0 = qt << 7;

    for (int i = tid; i < S_; i += 256)
        rc[i] = __float2bfloat16(rpe[(size_t)i * H_ + h]);

    const __nv_bfloat16* qhg = g_Qh + ((size_t)bh_i * N_ + q0) * HD_;
    const __nv_bfloat16* qlg = g_Ql + ((size_t)bh_i * N_ + q0) * HD_;
    const __nv_bfloat16* khg = g_Kh + (size_t)bh_i * N_ * HD_;
    const __nv_bfloat16* klg = g_Kl + (size_t)bh_i * N_ * HD_;
    const __half*        vg  = g_Vt + (size_t)bh_i * HD_ * N_;

#pragma unroll
    for (int j = 0; j < 4; j++) {
        int u = tid + j * 256;
        int r = u >> 3, ch = (u & 7) << 3;
        cp16(sb + (uint32_t)(AQH + r * AT_STR + ch) * 2, qhg + (size_t)r * HD_ + ch);
        cp16(sb + (uint32_t)(AQL + r * AT_STR + ch) * 2, qlg + (size_t)r * HD_ + ch);
    }
    CP_COMMIT;

    int r_ld = tid >> 3, c_ld = (tid & 7) << 3;
    auto issue_kv = [&](int t) {
        int k0g = t * 64;
        uint32_t stg = sb + (uint32_t)(AKV + (t & 1) * KVSTG) * 2;
#pragma unroll
        for (int j = 0; j < 2; j++) {
            int r = r_ld + j * 32, ch = c_ld;
            cp16(stg + (uint32_t)(0 * 4608 + r * AT_STR + ch) * 2,
                 khg + (size_t)(k0g + r) * HD_ + ch);
            cp16(stg + (uint32_t)(1 * 4608 + r * AT_STR + ch) * 2,
                 klg + (size_t)(k0g + r) * HD_ + ch);
            cp16(stg + (uint32_t)(2 * 4608 + r * AT_STR + ch) * 2,
                 vg + (size_t)r * N_ + k0g + ch);
        }
        CP_COMMIT;
    };
    issue_kv(0);
    issue_kv(1);

    float co[8][4];
#pragma unroll
    for (int nh = 0; nh < 8; nh++)
#pragma unroll
        for (int q = 0; q < 4; q++) co[nh][q] = 0.f;
    float rs0 = 0.f, rs1 = 0.f;

    int row_q = q0 + wm * 16 + (lane >> 2);
    const float scale = 0.125f;

#pragma unroll 1
    for (int t = 0; t < N_ / 64; t++) {
        if (t < 31) { CP_WAIT1; } else { CP_WAIT0; }
        __syncthreads();

        int k0g = t * 64;
        uint32_t kb = sb + (uint32_t)(AKV + (t & 1) * KVSTG) * 2;

        // ---- S = Q.K^T (split bf16, 3 MMAs) ----
        float s[8][4];
#pragma unroll
        for (int nt = 0; nt < 8; nt++)
#pragma unroll
            for (int q = 0; q < 4; q++) s[nt][q] = 0.f;
#pragma unroll
        for (int ks = 0; ks < 4; ks++) {
            int arow = wm * 16 + (lane & 15);
            int acol = ks * 16 + (lane >> 4) * 8;
            uint32_t aa = sb + (uint32_t)(AQH + arow * AT_STR + acol) * 2;
            uint32_t ah[4], al[4];
            ldsm4(ah[0], ah[1], ah[2], ah[3], aa);
            ldsm4(al[0], al[1], al[2], al[3], aa + AQL * 2);
            uint32_t bh[8][2], bl[8][2];
#pragma unroll
            for (int ng = 0; ng < 4; ng++) {
                int brow = ng * 16 + (lane & 7) + ((lane & 16) >> 1);
                int bcol = ks * 16 + ((lane >> 3) & 1) * 8;
                uint32_t ba = kb + (uint32_t)(brow * AT_STR + bcol) * 2;
                ldsm4(bh[2 * ng][0], bh[2 * ng][1], bh[2 * ng + 1][0],
                      bh[2 * ng + 1][1], ba);
                ldsm4(bl[2 * ng][0], bl[2 * ng][1], bl[2 * ng + 1][0],
                      bl[2 * ng + 1][1], ba + 4608 * 2);
            }
#pragma unroll
            for (int nt = 0; nt < 8; nt++) {
                mma16816(s[nt], ah, bh[nt]);
                mma16816(s[nt], ah, bl[nt]);
                mma16816(s[nt], al, bh[nt]);
            }
        }

        // ---- bias + exp + rowsum + attn store ----
#pragma unroll
        for (int nt = 0; nt < 8; nt++) {
            int col = k0g + nt * 8 + ((lane & 3) << 1);
            int d0 = row_q - col;     if (d0 < 0) d0 = -d0;
            int d1 = row_q - col - 1; if (d1 < 0) d1 = -d1;
            int d2 = row_q + 8 - col;     if (d2 < 0) d2 = -d2;
            int d3 = row_q + 8 - col - 1; if (d3 < 0) d3 = -d3;
            float e0 = __expf(fmaf(s[nt][0], scale, __bfloat162float(rc[d0])));
            float e1 = __expf(fmaf(s[nt][1], scale, __bfloat162float(rc[d1])));
            float e2 = __expf(fmaf(s[nt][2], scale, __bfloat162float(rc[d2])));
            float e3 = __expf(fmaf(s[nt][3], scale, __bfloat162float(rc[d3])));
            s[nt][0] = e0; s[nt][1] = e1; s[nt][2] = e2; s[nt][3] = e3;
            rs0 += e0 + e1;
            rs1 += e2 + e3;
            if (write_attn) {
                float* ap = attn + ((size_t)bh_i * N_ + row_q) * N_ + col;
                *(float2*)ap = make_float2(e0, e1);
                *(float2*)(ap + 8 * N_) = make_float2(e2, e3);
            }
        }

        // ---- O += e.V  (single fp16 MMA) ----
        uint32_t vb0 = kb + 2 * 4608 * 2;
#pragma unroll
        for (int ks = 0; ks < 4; ks++) {
            uint32_t ea[4];
            ea[0] = pkhf(s[2 * ks][0], s[2 * ks][1]);
            ea[1] = pkhf(s[2 * ks][2], s[2 * ks][3]);
            ea[2] = pkhf(s[2 * ks + 1][0], s[2 * ks + 1][1]);
            ea[3] = pkhf(s[2 * ks + 1][2], s[2 * ks + 1][3]);
            uint32_t vb[8][2];
#pragma unroll
            for (int ng = 0; ng < 4; ng++) {
                int brow = ng * 16 + (lane & 7) + ((lane & 16) >> 1);
                int bcol = ks * 16 + ((lane >> 3) & 1) * 8;
                uint32_t ba = vb0 + (uint32_t)(brow * AT_STR + bcol) * 2;
                ldsm4(vb[2 * ng][0], vb[2 * ng][1], vb[2 * ng + 1][0],
                      vb[2 * ng + 1][1], ba);
            }
#pragma unroll
            for (int nh = 0; nh < 8; nh++)
                mma16816h(co[nh], ea, vb[nh]);
        }

        // stage (t) fully consumed by all warps before reuse by t+2
        __syncthreads();
        if (t + 2 < N_ / 64) issue_kv(t + 2);
    }

    rs0 += __shfl_xor_sync(0xffffffffu, rs0, 1);
    rs0 += __shfl_xor_sync(0xffffffffu, rs0, 2);
    rs1 += __shfl_xor_sync(0xffffffffu, rs1, 1);
    rs1 += __shfl_xor_sync(0xffffffffu, rs1, 2);
    if ((lane & 3) == 0) {
        g_rowsum[(size_t)bh_i * N_ + row_q] = rs0;
        g_rowsum[(size_t)bh_i * N_ + row_q + 8] = rs1;
    }

    float inv0 = 1.0f / rs0, inv1 = 1.0f / rs1;
#pragma unroll
    for (int nh = 0; nh < 8; nh++) {
        int hd = nh * 8 + ((lane & 3) << 1);
        size_t p = ((size_t)(b * N_ + row_q)) * D_ + h * HD_ + hd;
        split_st2(g_aoh, g_aol, p, make_float2(co[nh][0] * inv0, co[nh][1] * inv0));
        split_st2(g_aoh, g_aol, p + 8 * D_,
                  make_float2(co[nh][2] * inv1, co[nh][3] * inv1));
    }
}

// =============================================================================
extern "C" void kernel_launch(void* const* d_in, const int* in_sizes, int n_in,
                              void* d_out, int out_size) {
    const float* query = (const float*)d_in[0];
    const float* w_in  = (const float*)d_in[4];
    const float* b_in  = (const float*)d_in[5];
    const float* w_out = (const float*)d_in[6];
    const float* b_out = (const float*)d_in[7];
    const float* rpe   = (const float*)d_in[8];

    float* out  = (float*)d_out;
    const long long out_elems  = (long long)B_ * N_ * D_;
    const long long attn_elems = (long long)BH_ * N_ * N_;
    int write_attn = ((long long)out_size >= out_elems + attn_elems) ? 1 : 0;
    float* attn = out + out_elems;

    cudaFuncSetAttribute(attn_kernel, cudaFuncAttributeMaxDynamicSharedMemorySize,
                         ATTN_SMEM);
    cudaFuncSetAttribute(qkv_gemm_k, cudaFuncAttributeMaxDynamicSharedMemorySize,
                         GEMM_SMEM);
    cudaFuncSetAttribute(out_norm_kernel, cudaFuncAttributeMaxDynamicSharedMemorySize,
                         GEMM_SMEM);

    __nv_bfloat16 *xh, *xl, *wih, *wil, *aoh, *aol, *woh, *wol;
    cudaGetSymbolAddress((void**)&xh,  g_xh);
    cudaGetSymbolAddress((void**)&xl,  g_xl);
    cudaGetSymbolAddress((void**)&wih, g_wih);
    cudaGetSymbolAddress((void**)&wil, g_wil);
    cudaGetSymbolAddress((void**)&aoh, g_aoh);
    cudaGetSymbolAddress((void**)&aol, g_aol);
    cudaGetSymbolAddress((void**)&woh, g_woh);
    cudaGetSymbolAddress((void**)&wol, g_wol);

    cvt3_kernel<<<8192, 256>>>(query, xh, xl, w_in, wih, wil, w_out, woh, wol);

    qkv_gemm_k<<<dim3(24, 32), 256, GEMM_SMEM>>>(xh, xl, wih, wil, b_in);

    attn_kernel<<<dim3(16, 16, 2), 256, ATTN_SMEM>>>(attn, rpe, write_attn);

    out_norm_kernel<<<256 + NN_BLOCKS, 256, GEMM_SMEM>>>(
        aoh, aol, woh, wol, b_out, out, attn, write_attn);
}

// round 14
// speedup vs baseline: 1.8481x; 1.1000x over previous
#include <cuda_runtime.h>
#include <cuda_bf16.h>
#include <cuda_fp16.h>
#include <cstdint>

#define B_  2
#define N_  2048
#define D_  1024
#define H_  16
#define HD_ 64
#define S_  2048
#define BH_ (B_*H_)

// ---------------- scratch ----------------------------------------------------
static __device__ float g_rowsum[(size_t)BH_*N_];

static __device__ __nv_bfloat16 g_xh[(size_t)4096*1024];
static __device__ __nv_bfloat16 g_xl[(size_t)4096*1024];
static __device__ __half        g_xf[(size_t)4096*1024];      // fp16 x (for V gemm)
static __device__ __nv_bfloat16 g_wih[(size_t)3072*1024];
static __device__ __nv_bfloat16 g_wil[(size_t)3072*1024];
static __device__ __half        g_wvf[(size_t)1024*1024];     // fp16 W_v
static __device__ __nv_bfloat16 g_aoh[(size_t)4096*1024];
static __device__ __nv_bfloat16 g_aol[(size_t)4096*1024];
static __device__ __nv_bfloat16 g_woh[(size_t)1024*1024];
static __device__ __nv_bfloat16 g_wol[(size_t)1024*1024];

static __device__ __nv_bfloat16 g_Qh[(size_t)BH_*N_*HD_];   // [bh,n,hd]
static __device__ __nv_bfloat16 g_Ql[(size_t)BH_*N_*HD_];
static __device__ __nv_bfloat16 g_Kh[(size_t)BH_*N_*HD_];
static __device__ __nv_bfloat16 g_Kl[(size_t)BH_*N_*HD_];
static __device__ __half      g_Vt[(size_t)BH_*HD_*N_];     // fp16, [bh,hd,n]
static __device__ __half      g_escr[(size_t)BH_*N_*N_];    // fp16 unnormalized e

// ---------------- helpers ----------------------------------------------------
__device__ __forceinline__ uint32_t smem_u32(const void* p) {
    uint32_t a;
    asm("{ .reg .u64 t; cvta.to.shared.u64 t, %1; cvt.u32.u64 %0, t; }"
        : "=r"(a) : "l"(p));
    return a;
}
__device__ __forceinline__ void cp16(uint32_t dst, const void* src) {
    asm volatile("cp.async.cg.shared.global [%0], [%1], 16;" :: "r"(dst), "l"(src));
}
#define CP_COMMIT asm volatile("cp.async.commit_group;" ::: "memory")
#define CP_WAIT0  asm volatile("cp.async.wait_group 0;" ::: "memory")
#define CP_WAIT1  asm volatile("cp.async.wait_group 1;" ::: "memory")

__device__ __forceinline__ void ldsm4(uint32_t& r0, uint32_t& r1, uint32_t& r2,
                                      uint32_t& r3, uint32_t addr) {
    asm volatile("ldmatrix.sync.aligned.m8n8.x4.shared.b16 {%0,%1,%2,%3}, [%4];"
                 : "=r"(r0), "=r"(r1), "=r"(r2), "=r"(r3) : "r"(addr));
}
__device__ __forceinline__ void mma16816(float* c, const uint32_t* a,
                                         const uint32_t* b) {
    asm volatile(
        "mma.sync.aligned.m16n8k16.row.col.f32.bf16.bf16.f32 "
        "{%0,%1,%2,%3}, {%4,%5,%6,%7}, {%8,%9}, {%0,%1,%2,%3};"
        : "+f"(c[0]), "+f"(c[1]), "+f"(c[2]), "+f"(c[3])
        : "r"(a[0]), "r"(a[1]), "r"(a[2]), "r"(a[3]), "r"(b[0]), "r"(b[1]));
}
__device__ __forceinline__ void mma16816h(float* c, const uint32_t* a,
                                          const uint32_t* b) {
    asm volatile(
        "mma.sync.aligned.m16n8k16.row.col.f32.f16.f16.f32 "
        "{%0,%1,%2,%3}, {%4,%5,%6,%7}, {%8,%9}, {%0,%1,%2,%3};"
        : "+f"(c[0]), "+f"(c[1]), "+f"(c[2]), "+f"(c[3])
        : "r"(a[0]), "r"(a[1]), "r"(a[2]), "r"(a[3]), "r"(b[0]), "r"(b[1]));
}
__device__ __forceinline__ uint32_t pkhf(float lo, float hi) {
    uint32_t d;
    asm("cvt.rn.f16x2.f32 %0, %1, %2;" : "=r"(d) : "f"(hi), "f"(lo));
    return d;
}

// =============================================================================
// fp32 -> bf16 hi/lo split (+ fp16 copies of x and W_v), 3 tensors, one launch
// =============================================================================
__global__ void __launch_bounds__(256) cvt3_kernel(
        const float* __restrict__ x0, __nv_bfloat16* __restrict__ h0p,
        __nv_bfloat16* __restrict__ l0p, __half* __restrict__ xf,
        const float* __restrict__ x1, __nv_bfloat16* __restrict__ h1p,
        __nv_bfloat16* __restrict__ l1p, __half* __restrict__ wvf,
        const float* __restrict__ x2, __nv_bfloat16* __restrict__ h2p,
        __nv_bfloat16* __restrict__ l2p) {
    int blk = blockIdx.x;
    const float* x; __nv_bfloat16 *hi, *lo; int i; int which;
    if (blk < 4096)      { x = x0; hi = h0p; lo = l0p; i = blk * 256 + threadIdx.x; which = 0; }
    else if (blk < 7168) { x = x1; hi = h1p; lo = l1p; i = (blk - 4096) * 256 + threadIdx.x; which = 1; }
    else                 { x = x2; hi = h2p; lo = l2p; i = (blk - 7168) * 256 + threadIdx.x; which = 2; }
    float4 v = ((const float4*)x)[i];
    __nv_bfloat16 a0 = __float2bfloat16(v.x), a1 = __float2bfloat16(v.y);
    __nv_bfloat16 a2 = __float2bfloat16(v.z), a3 = __float2bfloat16(v.w);
    ((__nv_bfloat162*)hi)[2 * i] = __nv_bfloat162(a0, a1);
    ((__nv_bfloat162*)hi)[2 * i + 1] = __nv_bfloat162(a2, a3);
    ((__nv_bfloat162*)lo)[2 * i] = __nv_bfloat162(
        __float2bfloat16(v.x - __bfloat162float(a0)),
        __float2bfloat16(v.y - __bfloat162float(a1)));
    ((__nv_bfloat162*)lo)[2 * i + 1] = __nv_bfloat162(
        __float2bfloat16(v.z - __bfloat162float(a2)),
        __float2bfloat16(v.w - __bfloat162float(a3)));
    if (which == 0) {
        ((__half2*)xf)[2 * i] = __floats2half2_rn(v.x, v.y);
        ((__half2*)xf)[2 * i + 1] = __floats2half2_rn(v.z, v.w);
    } else if (which == 1 && i >= 524288) {     // W rows [2048,3072) = W_v
        int j = i - 524288;
        ((__half2*)wvf)[2 * j] = __floats2half2_rn(v.x, v.y);
        ((__half2*)wvf)[2 * j + 1] = __floats2half2_rn(v.z, v.w);
    }
}

// =============================================================================
// Split-bf16 GEMM core (Q/K projection + out projection)
// =============================================================================
#define SSTR  40
#define ARRB  (128*SSTR*2)
#define STAGE (4*ARRB)
#define GEMM_SMEM (2*STAGE)

__device__ __forceinline__ void split_st2(__nv_bfloat16* dh, __nv_bfloat16* dl,
                                          size_t idx, float2 v) {
    __nv_bfloat16 h0 = __float2bfloat16(v.x), h1 = __float2bfloat16(v.y);
    *(__nv_bfloat162*)(dh + idx) = __nv_bfloat162(h0, h1);
    *(__nv_bfloat162*)(dl + idx) = __nv_bfloat162(
        __float2bfloat16(v.x - __bfloat162float(h0)),
        __float2bfloat16(v.y - __bfloat162float(h1)));
}

template<bool QKV>
__device__ __forceinline__ void gemm_body(
        uint32_t sb, int m0, int n0,
        const __nv_bfloat16* __restrict__ Ah_g, const __nv_bfloat16* __restrict__ Al_g,
        const __nv_bfloat16* __restrict__ Bh_g, const __nv_bfloat16* __restrict__ Bl_g,
        const float* __restrict__ bias, float* __restrict__ outp) {
    int tid = threadIdx.x, lane = tid & 31, wid = tid >> 5;
    int wm = wid >> 1, wn = wid & 1;

    const __nv_bfloat16* base[4] = {
        Ah_g + (size_t)m0 * 1024, Al_g + (size_t)m0 * 1024,
        Bh_g + (size_t)n0 * 1024, Bl_g + (size_t)n0 * 1024 };

    float c[2][8][4];
#pragma unroll
    for (int mt = 0; mt < 2; mt++)
#pragma unroll
        for (int nt = 0; nt < 8; nt++)
#pragma unroll
            for (int q = 0; q < 4; q++) c[mt][nt][q] = 0.f;

    int r_ld = tid >> 2, c_ld = (tid & 3) << 3;

    {
#pragma unroll
        for (int arr = 0; arr < 4; arr++)
#pragma unroll
            for (int j = 0; j < 2; j++) {
                int r = r_ld + j * 64;
                cp16(sb + arr * ARRB + (uint32_t)(r * SSTR + c_ld) * 2,
                     base[arr] + (size_t)r * 1024 + c_ld);
            }
        CP_COMMIT;
    }

#pragma unroll 1
    for (int t = 0; t < 32; t++) {
        if (t + 1 < 32) {
            int s = (t + 1) & 1, k0 = (t + 1) << 5;
#pragma unroll
            for (int arr = 0; arr < 4; arr++)
#pragma unroll
                for (int j = 0; j < 2; j++) {
                    int r = r_ld + j * 64;
                    cp16(sb + (uint32_t)s * STAGE + arr * ARRB +
                             (uint32_t)(r * SSTR + c_ld) * 2,
                         base[arr] + (size_t)r * 1024 + k0 + c_ld);
                }
            CP_COMMIT;
            CP_WAIT1;
        } else {
            CP_WAIT0;
        }
        __syncthreads();

        uint32_t st = sb + (uint32_t)(t & 1) * STAGE;
#pragma unroll
        for (int kk = 0; kk < 2; kk++) {
            uint32_t bh[8][2], bl[8][2];
#pragma unroll
            for (int ng = 0; ng < 4; ng++) {
                int brow = wn * 64 + ng * 16 + (lane & 7) + ((lane & 16) >> 1);
                int bcol = kk * 16 + ((lane >> 3) & 1) * 8;
                uint32_t ba = st + 2 * ARRB + (uint32_t)(brow * SSTR + bcol) * 2;
                ldsm4(bh[2 * ng][0], bh[2 * ng][1], bh[2 * ng + 1][0],
                      bh[2 * ng + 1][1], ba);
                ldsm4(bl[2 * ng][0], bl[2 * ng][1], bl[2 * ng + 1][0],
                      bl[2 * ng + 1][1], ba + ARRB);
            }
#pragma unroll
            for (int mt = 0; mt < 2; mt++) {
                int arow = wm * 32 + mt * 16 + (lane & 15);
                int acol = kk * 16 + (lane >> 4) * 8;
                uint32_t aa = st + (uint32_t)(arow * SSTR + acol) * 2;
                uint32_t ah[4], al[4];
                ldsm4(ah[0], ah[1], ah[2], ah[3], aa);
                ldsm4(al[0], al[1], al[2], al[3], aa + ARRB);
#pragma unroll
                for (int nt = 0; nt < 8; nt++) {
                    mma16816(c[mt][nt], ah, bh[nt]);
                    mma16816(c[mt][nt], ah, bl[nt]);
                    mma16816(c[mt][nt], al, bh[nt]);
                }
            }
        }
        __syncthreads();
    }

#pragma unroll
    for (int mt = 0; mt < 2; mt++) {
        int m = m0 + wm * 32 + mt * 16 + (lane >> 2);
#pragma unroll
        for (int nt = 0; nt < 8; nt++) {
            int n = n0 + wn * 64 + nt * 8 + ((lane & 3) << 1);
            float b0 = bias[n], b1 = bias[n + 1];
            float2 v0 = make_float2(c[mt][nt][0] + b0, c[mt][nt][1] + b1);
            float2 v1 = make_float2(c[mt][nt][2] + b0, c[mt][nt][3] + b1);
            if (QKV) {         // Q and K sections only (n < 2048)
                int sect = n >> 10;
                int h = (n & 1023) >> 6, hd = n & 63;
                int bb = m >> 11, row = m & 2047;
                int bh_i = bb * H_ + h;
                __nv_bfloat16* dh = sect == 0 ? g_Qh : g_Kh;
                __nv_bfloat16* dl = sect == 0 ? g_Ql : g_Kl;
                size_t p = ((size_t)bh_i * N_ + row) * HD_ + hd;
                split_st2(dh, dl, p, v0);
                split_st2(dh, dl, p + 8 * HD_, v1);
            } else {
                float* p = outp + (size_t)m * 1024 + n;
                *(float2*)p = v0;
                *(float2*)(p + 8 * 1024) = v1;
            }
        }
    }
}

__global__ void __launch_bounds__(256) qkv_gemm_k(
        const __nv_bfloat16* __restrict__ Ah_g, const __nv_bfloat16* __restrict__ Al_g,
        const __nv_bfloat16* __restrict__ Bh_g, const __nv_bfloat16* __restrict__ Bl_g,
        const float* __restrict__ bias) {
    extern __shared__ char smem[];
    gemm_body<true>(smem_u32(smem), blockIdx.y << 7, blockIdx.x << 7,
                    Ah_g, Al_g, Bh_g, Bl_g, bias, nullptr);
}

// =============================================================================
// V projection: single-fp16 GEMM (1 MMA), scatter transposed into g_Vt.
// =============================================================================
#define VSTAGE (2*ARRB)
#define VGEMM_SMEM (2*VSTAGE)

__global__ void __launch_bounds__(256) v_gemm_k(
        const __half* __restrict__ A_g, const __half* __restrict__ B_g,
        const float* __restrict__ bias) {
    extern __shared__ char smem[];
    uint32_t sb = smem_u32(smem);
    int tid = threadIdx.x, lane = tid & 31, wid = tid >> 5;
    int m0 = blockIdx.y << 7, n0 = blockIdx.x << 7;
    int wm = wid >> 1, wn = wid & 1;

    const __half* base[2] = { A_g + (size_t)m0 * 1024, B_g + (size_t)n0 * 1024 };

    float c[2][8][4];
#pragma unroll
    for (int mt = 0; mt < 2; mt++)
#pragma unroll
        for (int nt = 0; nt < 8; nt++)
#pragma unroll
            for (int q = 0; q < 4; q++) c[mt][nt][q] = 0.f;

    int r_ld = tid >> 2, c_ld = (tid & 3) << 3;
    {
#pragma unroll
        for (int arr = 0; arr < 2; arr++)
#pragma unroll
            for (int j = 0; j < 2; j++) {
                int r = r_ld + j * 64;
                cp16(sb + arr * ARRB + (uint32_t)(r * SSTR + c_ld) * 2,
                     base[arr] + (size_t)r * 1024 + c_ld);
            }
        CP_COMMIT;
    }

#pragma unroll 1
    for (int t = 0; t < 32; t++) {
        if (t + 1 < 32) {
            int s = (t + 1) & 1, k0 = (t + 1) << 5;
#pragma unroll
            for (int arr = 0; arr < 2; arr++)
#pragma unroll
                for (int j = 0; j < 2; j++) {
                    int r = r_ld + j * 64;
                    cp16(sb + (uint32_t)s * VSTAGE + arr * ARRB +
                             (uint32_t)(r * SSTR + c_ld) * 2,
                         base[arr] + (size_t)r * 1024 + k0 + c_ld);
                }
            CP_COMMIT;
            CP_WAIT1;
        } else {
            CP_WAIT0;
        }
        __syncthreads();

        uint32_t st = sb + (uint32_t)(t & 1) * VSTAGE;
#pragma unroll
        for (int kk = 0; kk < 2; kk++) {
            uint32_t bb[8][2];
#pragma unroll
            for (int ng = 0; ng < 4; ng++) {
                int brow = wn * 64 + ng * 16 + (lane & 7) + ((lane & 16) >> 1);
                int bcol = kk * 16 + ((lane >> 3) & 1) * 8;
                uint32_t ba = st + ARRB + (uint32_t)(brow * SSTR + bcol) * 2;
                ldsm4(bb[2 * ng][0], bb[2 * ng][1], bb[2 * ng + 1][0],
                      bb[2 * ng + 1][1], ba);
            }
#pragma unroll
            for (int mt = 0; mt < 2; mt++) {
                int arow = wm * 32 + mt * 16 + (lane & 15);
                int acol = kk * 16 + (lane >> 4) * 8;
                uint32_t aa = st + (uint32_t)(arow * SSTR + acol) * 2;
                uint32_t ah[4];
                ldsm4(ah[0], ah[1], ah[2], ah[3], aa);
#pragma unroll
                for (int nt = 0; nt < 8; nt++)
                    mma16816h(c[mt][nt], ah, bb[nt]);
            }
        }
        __syncthreads();
    }

#pragma unroll
    for (int mt = 0; mt < 2; mt++) {
        int m = m0 + wm * 32 + mt * 16 + (lane >> 2);
#pragma unroll
        for (int nt = 0; nt < 8; nt++) {
            int n = n0 + wn * 64 + nt * 8 + ((lane & 3) << 1);
            float b0 = bias[2048 + n], b1 = bias[2048 + n + 1];
            int h = n >> 6, hd = n & 63;
            int bb = m >> 11, row = m & 2047;
            int bh_i = bb * H_ + h;
            size_t pb = ((size_t)bh_i * HD_ + hd) * N_ + row;
            g_Vt[pb]          = __float2half(c[mt][nt][0] + b0);
            g_Vt[pb + N_]     = __float2half(c[mt][nt][1] + b1);
            g_Vt[pb + 8]      = __float2half(c[mt][nt][2] + b0);
            g_Vt[pb + N_ + 8] = __float2half(c[mt][nt][3] + b1);
        }
    }
}

// =============================================================================
// Fused out-projection GEMM + attn normalize (reads fp16 escr, writes fp32)
// =============================================================================
#define NN_BLOCKS 2048

__global__ void __launch_bounds__(256, 2) out_norm_kernel(
        const __nv_bfloat16* __restrict__ Ah_g, const __nv_bfloat16* __restrict__ Al_g,
        const __nv_bfloat16* __restrict__ Bh_g, const __nv_bfloat16* __restrict__ Bl_g,
        const float* __restrict__ bias, float* __restrict__ outp,
        const __half* __restrict__ escr, float* __restrict__ attn, int write_attn) {
    int blk = blockIdx.x;
    if (blk < 256) {
        extern __shared__ char smem[];
        int n0 = (blk & 7) << 7, m0 = (blk >> 3) << 7;
        gemm_body<false>(smem_u32(smem), m0, n0, Ah_g, Al_g, Bh_g, Bl_g, bias, outp);
        return;
    }
    if (!write_attn) return;
    const size_t total4 = (size_t)BH_ * N_ * N_ / 4;
    const size_t per_blk = total4 / NN_BLOCKS;
    size_t i0 = (size_t)(blk - 256) * per_blk;
    int tid = threadIdx.x;
#pragma unroll 1
    for (int it = 0; it < 8; it++) {
        size_t idx[8];
        uint2 ev[8];
#pragma unroll
        for (int u = 0; u < 8; u++) {
            idx[u] = i0 + (size_t)(it * 8 + u) * 256 + tid;
            ev[u] = __ldcs((const uint2*)escr + idx[u]);
        }
#pragma unroll
        for (int u = 0; u < 8; u++) {
            int row = (int)(idx[u] >> 9);
            float inv = 1.0f / g_rowsum[row];
            __half2 p0 = *(__half2*)&ev[u].x;
            __half2 p1 = *(__half2*)&ev[u].y;
            float4 v = make_float4(__low2float(p0) * inv, __high2float(p0) * inv,
                                   __low2float(p1) * inv, __high2float(p1) * inv);
            __stcs((float4*)attn + idx[u], v);
        }
    }
}

// =============================================================================
// Fused attention: split-bf16 QK^T + single-fp16 AV; e stored fp16 to escr.
// =============================================================================
#define AT_STR 72
#define AQH 0
#define AQL (128*AT_STR)
#define AKV (2*128*AT_STR)
#define KVSTG (3*64*AT_STR)
#define ABF_END (AKV + 2*KVSTG)
#define ATTN_SMEM (ABF_END*2 + 2048*2)      // 96256 B  (2 CTAs/SM)

__global__ void __launch_bounds__(256, 2) attn_kernel(__half* __restrict__ escr,
                                                      const float* __restrict__ rpe,
                                                      int write_attn) {
    extern __shared__ char smc[];
    uint32_t sb = smem_u32(smc);
    __nv_bfloat16* rc = (__nv_bfloat16*)(smc + ABF_END * 2);

    int qt = blockIdx.x, h = blockIdx.y, b = blockIdx.z;
    int bh_i = b * H_ + h;
    int tid = threadIdx.x, lane = tid & 31, wm = tid >> 5;
    int q0 = qt << 7;

    for (int i = tid; i < S_; i += 256)
        rc[i] = __float2bfloat16(rpe[(size_t)i * H_ + h]);

    const __nv_bfloat16* qhg = g_Qh + ((size_t)bh_i * N_ + q0) * HD_;
    const __nv_bfloat16* qlg = g_Ql + ((size_t)bh_i * N_ + q0) * HD_;
    const __nv_bfloat16* khg = g_Kh + (size_t)bh_i * N_ * HD_;
    const __nv_bfloat16* klg = g_Kl + (size_t)bh_i * N_ * HD_;
    const __half*        vg  = g_Vt + (size_t)bh_i * HD_ * N_;

#pragma unroll
    for (int j = 0; j < 4; j++) {
        int u = tid + j * 256;
        int r = u >> 3, ch = (u & 7) << 3;
        cp16(sb + (uint32_t)(AQH + r * AT_STR + ch) * 2, qhg + (size_t)r * HD_ + ch);
        cp16(sb + (uint32_t)(AQL + r * AT_STR + ch) * 2, qlg + (size_t)r * HD_ + ch);
    }
    CP_COMMIT;

    int r_ld = tid >> 3, c_ld = (tid & 7) << 3;
    auto issue_kv = [&](int t) {
        int k0g = t * 64;
        uint32_t stg = sb + (uint32_t)(AKV + (t & 1) * KVSTG) * 2;
#pragma unroll
        for (int j = 0; j < 2; j++) {
            int r = r_ld + j * 32, ch = c_ld;
            cp16(stg + (uint32_t)(0 * 4608 + r * AT_STR + ch) * 2,
                 khg + (size_t)(k0g + r) * HD_ + ch);
            cp16(stg + (uint32_t)(1 * 4608 + r * AT_STR + ch) * 2,
                 klg + (size_t)(k0g + r) * HD_ + ch);
            cp16(stg + (uint32_t)(2 * 4608 + r * AT_STR + ch) * 2,
                 vg + (size_t)r * N_ + k0g + ch);
        }
        CP_COMMIT;
    };
    issue_kv(0);
    issue_kv(1);

    float co[8][4];
#pragma unroll
    for (int nh = 0; nh < 8; nh++)
#pragma unroll
        for (int q = 0; q < 4; q++) co[nh][q] = 0.f;
    float rs0 = 0.f, rs1 = 0.f;

    int row_q = q0 + wm * 16 + (lane >> 2);
    const float scale = 0.125f;

#pragma unroll 1
    for (int t = 0; t < N_ / 64; t++) {
        if (t < 31) { CP_WAIT1; } else { CP_WAIT0; }
        __syncthreads();

        int k0g = t * 64;
        uint32_t kb = sb + (uint32_t)(AKV + (t & 1) * KVSTG) * 2;

        // ---- S = Q.K^T (split bf16, 3 MMAs) ----
        float s[8][4];
#pragma unroll
        for (int nt = 0; nt < 8; nt++)
#pragma unroll
            for (int q = 0; q < 4; q++) s[nt][q] = 0.f;
#pragma unroll
        for (int ks = 0; ks < 4; ks++) {
            int arow = wm * 16 + (lane & 15);
            int acol = ks * 16 + (lane >> 4) * 8;
            uint32_t aa = sb + (uint32_t)(AQH + arow * AT_STR + acol) * 2;
            uint32_t ah[4], al[4];
            ldsm4(ah[0], ah[1], ah[2], ah[3], aa);
            ldsm4(al[0], al[1], al[2], al[3], aa + AQL * 2);
            uint32_t bh[8][2], bl[8][2];
#pragma unroll
            for (int ng = 0; ng < 4; ng++) {
                int brow = ng * 16 + (lane & 7) + ((lane & 16) >> 1);
                int bcol = ks * 16 + ((lane >> 3) & 1) * 8;
                uint32_t ba = kb + (uint32_t)(brow * AT_STR + bcol) * 2;
                ldsm4(bh[2 * ng][0], bh[2 * ng][1], bh[2 * ng + 1][0],
                      bh[2 * ng + 1][1], ba);
                ldsm4(bl[2 * ng][0], bl[2 * ng][1], bl[2 * ng + 1][0],
                      bl[2 * ng + 1][1], ba + 4608 * 2);
            }
#pragma unroll
            for (int nt = 0; nt < 8; nt++) {
                mma16816(s[nt], ah, bh[nt]);
                mma16816(s[nt], ah, bl[nt]);
                mma16816(s[nt], al, bh[nt]);
            }
        }

        // ---- bias + exp + rowsum + fp16 e store ----
#pragma unroll
        for (int nt = 0; nt < 8; nt++) {
            int col = k0g + nt * 8 + ((lane & 3) << 1);
            int d0 = row_q - col;     if (d0 < 0) d0 = -d0;
            int d1 = row_q - col - 1; if (d1 < 0) d1 = -d1;
            int d2 = row_q + 8 - col;     if (d2 < 0) d2 = -d2;
            int d3 = row_q + 8 - col - 1; if (d3 < 0) d3 = -d3;
            float e0 = __expf(fmaf(s[nt][0], scale, __bfloat162float(rc[d0])));
            float e1 = __expf(fmaf(s[nt][1], scale, __bfloat162float(rc[d1])));
            float e2 = __expf(fmaf(s[nt][2], scale, __bfloat162float(rc[d2])));
            float e3 = __expf(fmaf(s[nt][3], scale, __bfloat162float(rc[d3])));
            s[nt][0] = e0; s[nt][1] = e1; s[nt][2] = e2; s[nt][3] = e3;
            rs0 += e0 + e1;
            rs1 += e2 + e3;
            if (write_attn) {
                __half* ep = escr + ((size_t)bh_i * N_ + row_q) * N_ + col;
                *(uint32_t*)ep = pkhf(e0, e1);
                *(uint32_t*)(ep + 8 * N_) = pkhf(e2, e3);
            }
        }

        // ---- O += e.V  (single fp16 MMA) ----
        uint32_t vb0 = kb + 2 * 4608 * 2;
#pragma unroll
        for (int ks = 0; ks < 4; ks++) {
            uint32_t ea[4];
            ea[0] = pkhf(s[2 * ks][0], s[2 * ks][1]);
            ea[1] = pkhf(s[2 * ks][2], s[2 * ks][3]);
            ea[2] = pkhf(s[2 * ks + 1][0], s[2 * ks + 1][1]);
            ea[3] = pkhf(s[2 * ks + 1][2], s[2 * ks + 1][3]);
            uint32_t vb[8][2];
#pragma unroll
            for (int ng = 0; ng < 4; ng++) {
                int brow = ng * 16 + (lane & 7) + ((lane & 16) >> 1);
                int bcol = ks * 16 + ((lane >> 3) & 1) * 8;
                uint32_t ba = vb0 + (uint32_t)(brow * AT_STR + bcol) * 2;
                ldsm4(vb[2 * ng][0], vb[2 * ng][1], vb[2 * ng + 1][0],
                      vb[2 * ng + 1][1], ba);
            }
#pragma unroll
            for (int nh = 0; nh < 8; nh++)
                mma16816h(co[nh], ea, vb[nh]);
        }

        __syncthreads();
        if (t + 2 < N_ / 64) issue_kv(t + 2);
    }

    rs0 += __shfl_xor_sync(0xffffffffu, rs0, 1);
    rs0 += __shfl_xor_sync(0xffffffffu, rs0, 2);
    rs1 += __shfl_xor_sync(0xffffffffu, rs1, 1);
    rs1 += __shfl_xor_sync(0xffffffffu, rs1, 2);
    if ((lane & 3) == 0) {
        g_rowsum[(size_t)bh_i * N_ + row_q] = rs0;
        g_rowsum[(size_t)bh_i * N_ + row_q + 8] = rs1;
    }

    float inv0 = 1.0f / rs0, inv1 = 1.0f / rs1;
#pragma unroll
    for (int nh = 0; nh < 8; nh++) {
        int hd = nh * 8 + ((lane & 3) << 1);
        size_t p = ((size_t)(b * N_ + row_q)) * D_ + h * HD_ + hd;
        split_st2(g_aoh, g_aol, p, make_float2(co[nh][0] * inv0, co[nh][1] * inv0));
        split_st2(g_aoh, g_aol, p + 8 * D_,
                  make_float2(co[nh][2] * inv1, co[nh][3] * inv1));
    }
}

// =============================================================================
extern "C" void kernel_launch(void* const* d_in, const int* in_sizes, int n_in,
                              void* d_out, int out_size) {
    const float* query = (const float*)d_in[0];
    const float* w_in  = (const float*)d_in[4];
    const float* b_in  = (const float*)d_in[5];
    const float* w_out = (const float*)d_in[6];
    const float* b_out = (const float*)d_in[7];
    const float* rpe   = (const float*)d_in[8];

    float* out  = (float*)d_out;
    const long long out_elems  = (long long)B_ * N_ * D_;
    const long long attn_elems = (long long)BH_ * N_ * N_;
    int write_attn = ((long long)out_size >= out_elems + attn_elems) ? 1 : 0;
    float* attn = out + out_elems;

    cudaFuncSetAttribute(attn_kernel, cudaFuncAttributeMaxDynamicSharedMemorySize,
                         ATTN_SMEM);
    cudaFuncSetAttribute(qkv_gemm_k, cudaFuncAttributeMaxDynamicSharedMemorySize,
                         GEMM_SMEM);
    cudaFuncSetAttribute(v_gemm_k, cudaFuncAttributeMaxDynamicSharedMemorySize,
                         VGEMM_SMEM);
    cudaFuncSetAttribute(out_norm_kernel, cudaFuncAttributeMaxDynamicSharedMemorySize,
                         GEMM_SMEM);

    __nv_bfloat16 *xh, *xl, *wih, *wil, *aoh, *aol, *woh, *wol;
    __half *xf, *wvf, *escr;
    cudaGetSymbolAddress((void**)&xh,  g_xh);
    cudaGetSymbolAddress((void**)&xl,  g_xl);
    cudaGetSymbolAddress((void**)&xf,  g_xf);
    cudaGetSymbolAddress((void**)&wih, g_wih);
    cudaGetSymbolAddress((void**)&wil, g_wil);
    cudaGetSymbolAddress((void**)&wvf, g_wvf);
    cudaGetSymbolAddress((void**)&aoh, g_aoh);
    cudaGetSymbolAddress((void**)&aol, g_aol);
    cudaGetSymbolAddress((void**)&woh, g_woh);
    cudaGetSymbolAddress((void**)&wol, g_wol);
    cudaGetSymbolAddress((void**)&escr, g_escr);

    cvt3_kernel<<<8192, 256>>>(query, xh, xl, xf, w_in, wih, wil, wvf,
                               w_out, woh, wol);

    qkv_gemm_k<<<dim3(16, 32), 256, GEMM_SMEM>>>(xh, xl, wih, wil, b_in);
    v_gemm_k<<<dim3(8, 32), 256, VGEMM_SMEM>>>(xf, wvf, b_in);

    attn_kernel<<<dim3(16, 16, 2), 256, ATTN_SMEM>>>(escr, rpe, write_attn);

    out_norm_kernel<<<256 + NN_BLOCKS, 256, GEMM_SMEM>>>(
        aoh, aol, woh, wol, b_out, out, escr, attn, write_attn);
}

// round 15
// speedup vs baseline: 1.9545x; 1.0575x over previous
#include <cuda_runtime.h>
#include <cuda_bf16.h>
#include <cuda_fp16.h>
#include <cstdint>

#define B_  2
#define N_  2048
#define D_  1024
#define H_  16
#define HD_ 64
#define S_  2048
#define BH_ (B_*H_)

// ---------------- scratch ----------------------------------------------------
static __device__ float g_rowsum[(size_t)BH_*N_];

static __device__ __nv_bfloat16 g_xh[(size_t)4096*1024];
static __device__ __nv_bfloat16 g_xl[(size_t)4096*1024];
static __device__ __half        g_xf[(size_t)4096*1024];
static __device__ __nv_bfloat16 g_wih[(size_t)3072*1024];
static __device__ __nv_bfloat16 g_wil[(size_t)3072*1024];
static __device__ __half        g_wvf[(size_t)1024*1024];
static __device__ __nv_bfloat16 g_aoh[(size_t)4096*1024];
static __device__ __nv_bfloat16 g_aol[(size_t)4096*1024];
static __device__ __nv_bfloat16 g_woh[(size_t)1024*1024];
static __device__ __nv_bfloat16 g_wol[(size_t)1024*1024];

static __device__ __nv_bfloat16 g_Qh[(size_t)BH_*N_*HD_];   // [bh,n,hd]
static __device__ __nv_bfloat16 g_Ql[(size_t)BH_*N_*HD_];
static __device__ __nv_bfloat16 g_Kh[(size_t)BH_*N_*HD_];
static __device__ __nv_bfloat16 g_Kl[(size_t)BH_*N_*HD_];
static __device__ __half      g_Vt[(size_t)BH_*HD_*N_];     // fp16, [bh,hd,n]
static __device__ __half      g_escr[(size_t)BH_*N_*N_];    // fp16 unnormalized e

// ---------------- helpers ----------------------------------------------------
__device__ __forceinline__ uint32_t smem_u32(const void* p) {
    uint32_t a;
    asm("{ .reg .u64 t; cvta.to.shared.u64 t, %1; cvt.u32.u64 %0, t; }"
        : "=r"(a) : "l"(p));
    return a;
}
__device__ __forceinline__ void cp16(uint32_t dst, const void* src) {
    asm volatile("cp.async.cg.shared.global [%0], [%1], 16;" :: "r"(dst), "l"(src));
}
#define CP_COMMIT asm volatile("cp.async.commit_group;" ::: "memory")
#define CP_WAIT0  asm volatile("cp.async.wait_group 0;" ::: "memory")
#define CP_WAIT1  asm volatile("cp.async.wait_group 1;" ::: "memory")

__device__ __forceinline__ void ldsm4(uint32_t& r0, uint32_t& r1, uint32_t& r2,
                                      uint32_t& r3, uint32_t addr) {
    asm volatile("ldmatrix.sync.aligned.m8n8.x4.shared.b16 {%0,%1,%2,%3}, [%4];"
                 : "=r"(r0), "=r"(r1), "=r"(r2), "=r"(r3) : "r"(addr));
}
__device__ __forceinline__ void mma16816(float* c, const uint32_t* a,
                                         const uint32_t* b) {
    asm volatile(
        "mma.sync.aligned.m16n8k16.row.col.f32.bf16.bf16.f32 "
        "{%0,%1,%2,%3}, {%4,%5,%6,%7}, {%8,%9}, {%0,%1,%2,%3};"
        : "+f"(c[0]), "+f"(c[1]), "+f"(c[2]), "+f"(c[3])
        : "r"(a[0]), "r"(a[1]), "r"(a[2]), "r"(a[3]), "r"(b[0]), "r"(b[1]));
}
__device__ __forceinline__ void mma16816h(float* c, const uint32_t* a,
                                          const uint32_t* b) {
    asm volatile(
        "mma.sync.aligned.m16n8k16.row.col.f32.f16.f16.f32 "
        "{%0,%1,%2,%3}, {%4,%5,%6,%7}, {%8,%9}, {%0,%1,%2,%3};"
        : "+f"(c[0]), "+f"(c[1]), "+f"(c[2]), "+f"(c[3])
        : "r"(a[0]), "r"(a[1]), "r"(a[2]), "r"(a[3]), "r"(b[0]), "r"(b[1]));
}
__device__ __forceinline__ uint32_t pkhf(float lo, float hi) {
    uint32_t d;
    asm("cvt.rn.f16x2.f32 %0, %1, %2;" : "=r"(d) : "f"(hi), "f"(lo));
    return d;
}

// =============================================================================
// fp32 -> bf16 hi/lo split (+ fp16 copies of x and W_v), 3 tensors, one launch
// =============================================================================
__global__ void __launch_bounds__(256) cvt3_kernel(
        const float* __restrict__ x0, __nv_bfloat16* __restrict__ h0p,
        __nv_bfloat16* __restrict__ l0p, __half* __restrict__ xf,
        const float* __restrict__ x1, __nv_bfloat16* __restrict__ h1p,
        __nv_bfloat16* __restrict__ l1p, __half* __restrict__ wvf,
        const float* __restrict__ x2, __nv_bfloat16* __restrict__ h2p,
        __nv_bfloat16* __restrict__ l2p) {
    int blk = blockIdx.x;
    const float* x; __nv_bfloat16 *hi, *lo; int i; int which;
    if (blk < 4096)      { x = x0; hi = h0p; lo = l0p; i = blk * 256 + threadIdx.x; which = 0; }
    else if (blk < 7168) { x = x1; hi = h1p; lo = l1p; i = (blk - 4096) * 256 + threadIdx.x; which = 1; }
    else                 { x = x2; hi = h2p; lo = l2p; i = (blk - 7168) * 256 + threadIdx.x; which = 2; }
    float4 v = ((const float4*)x)[i];
    __nv_bfloat16 a0 = __float2bfloat16(v.x), a1 = __float2bfloat16(v.y);
    __nv_bfloat16 a2 = __float2bfloat16(v.z), a3 = __float2bfloat16(v.w);
    ((__nv_bfloat162*)hi)[2 * i] = __nv_bfloat162(a0, a1);
    ((__nv_bfloat162*)hi)[2 * i + 1] = __nv_bfloat162(a2, a3);
    ((__nv_bfloat162*)lo)[2 * i] = __nv_bfloat162(
        __float2bfloat16(v.x - __bfloat162float(a0)),
        __float2bfloat16(v.y - __bfloat162float(a1)));
    ((__nv_bfloat162*)lo)[2 * i + 1] = __nv_bfloat162(
        __float2bfloat16(v.z - __bfloat162float(a2)),
        __float2bfloat16(v.w - __bfloat162float(a3)));
    if (which == 0) {
        ((__half2*)xf)[2 * i] = __floats2half2_rn(v.x, v.y);
        ((__half2*)xf)[2 * i + 1] = __floats2half2_rn(v.z, v.w);
    } else if (which == 1 && i >= 524288) {     // W rows [2048,3072) = W_v
        int j = i - 524288;
        ((__half2*)wvf)[2 * j] = __floats2half2_rn(v.x, v.y);
        ((__half2*)wvf)[2 * j + 1] = __floats2half2_rn(v.z, v.w);
    }
}

// =============================================================================
// Split-bf16 GEMM core (Q/K projection + out projection)
// =============================================================================
#define SSTR  40
#define ARRB  (128*SSTR*2)
#define STAGE (4*ARRB)
#define GEMM_SMEM (2*STAGE)

__device__ __forceinline__ void split_st2(__nv_bfloat16* dh, __nv_bfloat16* dl,
                                          size_t idx, float2 v) {
    __nv_bfloat16 h0 = __float2bfloat16(v.x), h1 = __float2bfloat16(v.y);
    *(__nv_bfloat162*)(dh + idx) = __nv_bfloat162(h0, h1);
    *(__nv_bfloat162*)(dl + idx) = __nv_bfloat162(
        __float2bfloat16(v.x - __bfloat162float(h0)),
        __float2bfloat16(v.y - __bfloat162float(h1)));
}

template<bool QKV>
__device__ __forceinline__ void gemm_body(
        uint32_t sb, int m0, int n0,
        const __nv_bfloat16* __restrict__ Ah_g, const __nv_bfloat16* __restrict__ Al_g,
        const __nv_bfloat16* __restrict__ Bh_g, const __nv_bfloat16* __restrict__ Bl_g,
        const float* __restrict__ bias, float* __restrict__ outp) {
    int tid = threadIdx.x, lane = tid & 31, wid = tid >> 5;
    int wm = wid >> 1, wn = wid & 1;

    const __nv_bfloat16* base[4] = {
        Ah_g + (size_t)m0 * 1024, Al_g + (size_t)m0 * 1024,
        Bh_g + (size_t)n0 * 1024, Bl_g + (size_t)n0 * 1024 };

    float c[2][8][4];
#pragma unroll
    for (int mt = 0; mt < 2; mt++)
#pragma unroll
        for (int nt = 0; nt < 8; nt++)
#pragma unroll
            for (int q = 0; q < 4; q++) c[mt][nt][q] = 0.f;

    int r_ld = tid >> 2, c_ld = (tid & 3) << 3;

    {
#pragma unroll
        for (int arr = 0; arr < 4; arr++)
#pragma unroll
            for (int j = 0; j < 2; j++) {
                int r = r_ld + j * 64;
                cp16(sb + arr * ARRB + (uint32_t)(r * SSTR + c_ld) * 2,
                     base[arr] + (size_t)r * 1024 + c_ld);
            }
        CP_COMMIT;
    }

#pragma unroll 1
    for (int t = 0; t < 32; t++) {
        if (t + 1 < 32) {
            int s = (t + 1) & 1, k0 = (t + 1) << 5;
#pragma unroll
            for (int arr = 0; arr < 4; arr++)
#pragma unroll
                for (int j = 0; j < 2; j++) {
                    int r = r_ld + j * 64;
                    cp16(sb + (uint32_t)s * STAGE + arr * ARRB +
                             (uint32_t)(r * SSTR + c_ld) * 2,
                         base[arr] + (size_t)r * 1024 + k0 + c_ld);
                }
            CP_COMMIT;
            CP_WAIT1;
        } else {
            CP_WAIT0;
        }
        __syncthreads();

        uint32_t st = sb + (uint32_t)(t & 1) * STAGE;
#pragma unroll
        for (int kk = 0; kk < 2; kk++) {
            uint32_t bh[8][2], bl[8][2];
#pragma unroll
            for (int ng = 0; ng < 4; ng++) {
                int brow = wn * 64 + ng * 16 + (lane & 7) + ((lane & 16) >> 1);
                int bcol = kk * 16 + ((lane >> 3) & 1) * 8;
                uint32_t ba = st + 2 * ARRB + (uint32_t)(brow * SSTR + bcol) * 2;
                ldsm4(bh[2 * ng][0], bh[2 * ng][1], bh[2 * ng + 1][0],
                      bh[2 * ng + 1][1], ba);
                ldsm4(bl[2 * ng][0], bl[2 * ng][1], bl[2 * ng + 1][0],
                      bl[2 * ng + 1][1], ba + ARRB);
            }
#pragma unroll
            for (int mt = 0; mt < 2; mt++) {
                int arow = wm * 32 + mt * 16 + (lane & 15);
                int acol = kk * 16 + (lane >> 4) * 8;
                uint32_t aa = st + (uint32_t)(arow * SSTR + acol) * 2;
                uint32_t ah[4], al[4];
                ldsm4(ah[0], ah[1], ah[2], ah[3], aa);
                ldsm4(al[0], al[1], al[2], al[3], aa + ARRB);
#pragma unroll
                for (int nt = 0; nt < 8; nt++) {
                    mma16816(c[mt][nt], ah, bh[nt]);
                    mma16816(c[mt][nt], ah, bl[nt]);
                    mma16816(c[mt][nt], al, bh[nt]);
                }
            }
        }
        __syncthreads();
    }

#pragma unroll
    for (int mt = 0; mt < 2; mt++) {
        int m = m0 + wm * 32 + mt * 16 + (lane >> 2);
#pragma unroll
        for (int nt = 0; nt < 8; nt++) {
            int n = n0 + wn * 64 + nt * 8 + ((lane & 3) << 1);
            float b0 = bias[n], b1 = bias[n + 1];
            float2 v0 = make_float2(c[mt][nt][0] + b0, c[mt][nt][1] + b1);
            float2 v1 = make_float2(c[mt][nt][2] + b0, c[mt][nt][3] + b1);
            if (QKV) {
                int sect = n >> 10;
                int h = (n & 1023) >> 6, hd = n & 63;
                int bb = m >> 11, row = m & 2047;
                int bh_i = bb * H_ + h;
                __nv_bfloat16* dh = sect == 0 ? g_Qh : g_Kh;
                __nv_bfloat16* dl = sect == 0 ? g_Ql : g_Kl;
                size_t p = ((size_t)bh_i * N_ + row) * HD_ + hd;
                split_st2(dh, dl, p, v0);
                split_st2(dh, dl, p + 8 * HD_, v1);
            } else {
                float* p = outp + (size_t)m * 1024 + n;
                *(float2*)p = v0;
                *(float2*)(p + 8 * 1024) = v1;
            }
        }
    }
}

__global__ void __launch_bounds__(256) qkv_gemm_k(
        const __nv_bfloat16* __restrict__ Ah_g, const __nv_bfloat16* __restrict__ Al_g,
        const __nv_bfloat16* __restrict__ Bh_g, const __nv_bfloat16* __restrict__ Bl_g,
        const float* __restrict__ bias) {
    extern __shared__ char smem[];
    gemm_body<true>(smem_u32(smem), blockIdx.y << 7, blockIdx.x << 7,
                    Ah_g, Al_g, Bh_g, Bl_g, bias, nullptr);
}

// =============================================================================
// V projection: single-fp16 GEMM, scatter transposed into g_Vt.
// =============================================================================
#define VSTAGE (2*ARRB)
#define VGEMM_SMEM (2*VSTAGE)

__global__ void __launch_bounds__(256) v_gemm_k(
        const __half* __restrict__ A_g, const __half* __restrict__ B_g,
        const float* __restrict__ bias) {
    extern __shared__ char smem[];
    uint32_t sb = smem_u32(smem);
    int tid = threadIdx.x, lane = tid & 31, wid = tid >> 5;
    int m0 = blockIdx.y << 7, n0 = blockIdx.x << 7;
    int wm = wid >> 1, wn = wid & 1;

    const __half* base[2] = { A_g + (size_t)m0 * 1024, B_g + (size_t)n0 * 1024 };

    float c[2][8][4];
#pragma unroll
    for (int mt = 0; mt < 2; mt++)
#pragma unroll
        for (int nt = 0; nt < 8; nt++)
#pragma unroll
            for (int q = 0; q < 4; q++) c[mt][nt][q] = 0.f;

    int r_ld = tid >> 2, c_ld = (tid & 3) << 3;
    {
#pragma unroll
        for (int arr = 0; arr < 2; arr++)
#pragma unroll
            for (int j = 0; j < 2; j++) {
                int r = r_ld + j * 64;
                cp16(sb + arr * ARRB + (uint32_t)(r * SSTR + c_ld) * 2,
                     base[arr] + (size_t)r * 1024 + c_ld);
            }
        CP_COMMIT;
    }

#pragma unroll 1
    for (int t = 0; t < 32; t++) {
        if (t + 1 < 32) {
            int s = (t + 1) & 1, k0 = (t + 1) << 5;
#pragma unroll
            for (int arr = 0; arr < 2; arr++)
#pragma unroll
                for (int j = 0; j < 2; j++) {
                    int r = r_ld + j * 64;
                    cp16(sb + (uint32_t)s * VSTAGE + arr * ARRB +
                             (uint32_t)(r * SSTR + c_ld) * 2,
                         base[arr] + (size_t)r * 1024 + k0 + c_ld);
                }
            CP_COMMIT;
            CP_WAIT1;
        } else {
            CP_WAIT0;
        }
        __syncthreads();

        uint32_t st = sb + (uint32_t)(t & 1) * VSTAGE;
#pragma unroll
        for (int kk = 0; kk < 2; kk++) {
            uint32_t bb[8][2];
#pragma unroll
            for (int ng = 0; ng < 4; ng++) {
                int brow = wn * 64 + ng * 16 + (lane & 7) + ((lane & 16) >> 1);
                int bcol = kk * 16 + ((lane >> 3) & 1) * 8;
                uint32_t ba = st + ARRB + (uint32_t)(brow * SSTR + bcol) * 2;
                ldsm4(bb[2 * ng][0], bb[2 * ng][1], bb[2 * ng + 1][0],
                      bb[2 * ng + 1][1], ba);
            }
#pragma unroll
            for (int mt = 0; mt < 2; mt++) {
                int arow = wm * 32 + mt * 16 + (lane & 15);
                int acol = kk * 16 + (lane >> 4) * 8;
                uint32_t aa = st + (uint32_t)(arow * SSTR + acol) * 2;
                uint32_t ah[4];
                ldsm4(ah[0], ah[1], ah[2], ah[3], aa);
#pragma unroll
                for (int nt = 0; nt < 8; nt++)
                    mma16816h(c[mt][nt], ah, bb[nt]);
            }
        }
        __syncthreads();
    }

#pragma unroll
    for (int mt = 0; mt < 2; mt++) {
        int m = m0 + wm * 32 + mt * 16 + (lane >> 2);
#pragma unroll
        for (int nt = 0; nt < 8; nt++) {
            int n = n0 + wn * 64 + nt * 8 + ((lane & 3) << 1);
            float b0 = bias[2048 + n], b1 = bias[2048 + n + 1];
            int h = n >> 6, hd = n & 63;
            int bb = m >> 11, row = m & 2047;
            int bh_i = bb * H_ + h;
            size_t pb = ((size_t)bh_i * HD_ + hd) * N_ + row;
            g_Vt[pb]          = __float2half(c[mt][nt][0] + b0);
            g_Vt[pb + N_]     = __float2half(c[mt][nt][1] + b1);
            g_Vt[pb + 8]      = __float2half(c[mt][nt][2] + b0);
            g_Vt[pb + N_ + 8] = __float2half(c[mt][nt][3] + b1);
        }
    }
}

// =============================================================================
// Fused out-projection GEMM + attn normalize (reads fp16 escr, writes fp32)
// =============================================================================
#define NN_BLOCKS 2048

__global__ void __launch_bounds__(256, 2) out_norm_kernel(
        const __nv_bfloat16* __restrict__ Ah_g, const __nv_bfloat16* __restrict__ Al_g,
        const __nv_bfloat16* __restrict__ Bh_g, const __nv_bfloat16* __restrict__ Bl_g,
        const float* __restrict__ bias, float* __restrict__ outp,
        const __half* __restrict__ escr, float* __restrict__ attn, int write_attn) {
    int blk = blockIdx.x;
    if (blk < 256) {
        extern __shared__ char smem[];
        int n0 = (blk & 7) << 7, m0 = (blk >> 3) << 7;
        gemm_body<false>(smem_u32(smem), m0, n0, Ah_g, Al_g, Bh_g, Bl_g, bias, outp);
        return;
    }
    if (!write_attn) return;
    const size_t total4 = (size_t)BH_ * N_ * N_ / 4;
    const size_t per_blk = total4 / NN_BLOCKS;
    size_t i0 = (size_t)(blk - 256) * per_blk;
    int tid = threadIdx.x;
#pragma unroll 1
    for (int it = 0; it < 8; it++) {
        size_t idx[8];
        uint2 ev[8];
#pragma unroll
        for (int u = 0; u < 8; u++) {
            idx[u] = i0 + (size_t)(it * 8 + u) * 256 + tid;
            ev[u] = __ldcs((const uint2*)escr + idx[u]);
        }
#pragma unroll
        for (int u = 0; u < 8; u++) {
            int row = (int)(idx[u] >> 9);
            float inv = 1.0f / g_rowsum[row];
            __half2 p0 = *(__half2*)&ev[u].x;
            __half2 p1 = *(__half2*)&ev[u].y;
            float4 v = make_float4(__low2float(p0) * inv, __high2float(p0) * inv,
                                   __low2float(p1) * inv, __high2float(p1) * inv);
            __stcs((float4*)attn + idx[u], v);
        }
    }
}

// =============================================================================
// Fused attention, 2 m-frags/warp (32 rows x 64 keys), 256-row Q tile,
// 3-stage KV ring, 1 CTA/SM. K/V frag loads amortized over 2x MMAs.
// =============================================================================
#define AT_STR 72
#define AQH 0
#define AQL (256*AT_STR)
#define AKV (2*256*AT_STR)
#define KVSTG (3*64*AT_STR)
#define ABF_END (AKV + 3*KVSTG)
#define ATTN_SMEM (ABF_END*2 + 2048*2)      // 160768 B (1 CTA/SM)

__global__ void __launch_bounds__(256, 1) attn_kernel(__half* __restrict__ escr,
                                                      const float* __restrict__ rpe,
                                                      int write_attn) {
    extern __shared__ char smc[];
    uint32_t sb = smem_u32(smc);
    __nv_bfloat16* rc = (__nv_bfloat16*)(smc + ABF_END * 2);

    int qt = blockIdx.x, h = blockIdx.y, b = blockIdx.z;
    int bh_i = b * H_ + h;
    int tid = threadIdx.x, lane = tid & 31, wm = tid >> 5;
    int q0 = qt << 8;                        // 256-row tiles

    for (int i = tid; i < S_; i += 256)
        rc[i] = __float2bfloat16(rpe[(size_t)i * H_ + h]);

    const __nv_bfloat16* qhg = g_Qh + ((size_t)bh_i * N_ + q0) * HD_;
    const __nv_bfloat16* qlg = g_Ql + ((size_t)bh_i * N_ + q0) * HD_;
    const __nv_bfloat16* khg = g_Kh + (size_t)bh_i * N_ * HD_;
    const __nv_bfloat16* klg = g_Kl + (size_t)bh_i * N_ * HD_;
    const __half*        vg  = g_Vt + (size_t)bh_i * HD_ * N_;

    // Q load: 256 rows x 64 cols, hi+lo
#pragma unroll
    for (int j = 0; j < 8; j++) {
        int u = tid + j * 256;               // 0..2047
        int r = u >> 3, ch = (u & 7) << 3;
        cp16(sb + (uint32_t)(AQH + r * AT_STR + ch) * 2, qhg + (size_t)r * HD_ + ch);
        cp16(sb + (uint32_t)(AQL + r * AT_STR + ch) * 2, qlg + (size_t)r * HD_ + ch);
    }
    CP_COMMIT;

    int r_ld = tid >> 3, c_ld = (tid & 7) << 3;
    auto issue_kv = [&](int t) {
        int k0g = t * 64;
        uint32_t stg = sb + (uint32_t)(AKV + (t % 3) * KVSTG) * 2;
#pragma unroll
        for (int j = 0; j < 2; j++) {
            int r = r_ld + j * 32, ch = c_ld;
            cp16(stg + (uint32_t)(0 * 4608 + r * AT_STR + ch) * 2,
                 khg + (size_t)(k0g + r) * HD_ + ch);
            cp16(stg + (uint32_t)(1 * 4608 + r * AT_STR + ch) * 2,
                 klg + (size_t)(k0g + r) * HD_ + ch);
            cp16(stg + (uint32_t)(2 * 4608 + r * AT_STR + ch) * 2,
                 vg + (size_t)r * N_ + k0g + ch);
        }
        CP_COMMIT;
    };
    issue_kv(0);
    issue_kv(1);

    float co[2][8][4];
#pragma unroll
    for (int mf = 0; mf < 2; mf++)
#pragma unroll
        for (int nh = 0; nh < 8; nh++)
#pragma unroll
            for (int q = 0; q < 4; q++) co[mf][nh][q] = 0.f;
    float rs[2][2] = {{0.f, 0.f}, {0.f, 0.f}};

    int row_q = q0 + wm * 32 + (lane >> 2);
    const float scale = 0.125f;

#pragma unroll 1
    for (int t = 0; t < N_ / 64; t++) {
        if (t < 31) { CP_WAIT1; } else { CP_WAIT0; }
        __syncthreads();

        int k0g = t * 64;
        uint32_t kb = sb + (uint32_t)(AKV + (t % 3) * KVSTG) * 2;

        // ---- S = Q.K^T (split bf16, 3 MMAs; K frags shared by 2 m-frags) ----
        float s[2][8][4];
#pragma unroll
        for (int mf = 0; mf < 2; mf++)
#pragma unroll
            for (int nt = 0; nt < 8; nt++)
#pragma unroll
                for (int q = 0; q < 4; q++) s[mf][nt][q] = 0.f;
#pragma unroll
        for (int ks = 0; ks < 4; ks++) {
            uint32_t ah[2][4], al[2][4];
#pragma unroll
            for (int mf = 0; mf < 2; mf++) {
                int arow = wm * 32 + mf * 16 + (lane & 15);
                int acol = ks * 16 + (lane >> 4) * 8;
                uint32_t aa = sb + (uint32_t)(AQH + arow * AT_STR + acol) * 2;
                ldsm4(ah[mf][0], ah[mf][1], ah[mf][2], ah[mf][3], aa);
                ldsm4(al[mf][0], al[mf][1], al[mf][2], al[mf][3], aa + AQL * 2);
            }
            uint32_t bh[8][2], bl[8][2];
#pragma unroll
            for (int ng = 0; ng < 4; ng++) {
                int brow = ng * 16 + (lane & 7) + ((lane & 16) >> 1);
                int bcol = ks * 16 + ((lane >> 3) & 1) * 8;
                uint32_t ba = kb + (uint32_t)(brow * AT_STR + bcol) * 2;
                ldsm4(bh[2 * ng][0], bh[2 * ng][1], bh[2 * ng + 1][0],
                      bh[2 * ng + 1][1], ba);
                ldsm4(bl[2 * ng][0], bl[2 * ng][1], bl[2 * ng + 1][0],
                      bl[2 * ng + 1][1], ba + 4608 * 2);
            }
#pragma unroll
            for (int mf = 0; mf < 2; mf++)
#pragma unroll
                for (int nt = 0; nt < 8; nt++) {
                    mma16816(s[mf][nt], ah[mf], bh[nt]);
                    mma16816(s[mf][nt], ah[mf], bl[nt]);
                    mma16816(s[mf][nt], al[mf], bh[nt]);
                }
        }

        // ---- bias + exp + rowsum + fp16 e store ----
#pragma unroll
        for (int mf = 0; mf < 2; mf++) {
            int rq = row_q + mf * 16;
#pragma unroll
            for (int nt = 0; nt < 8; nt++) {
                int col = k0g + nt * 8 + ((lane & 3) << 1);
                int d0 = rq - col;     if (d0 < 0) d0 = -d0;
                int d1 = rq - col - 1; if (d1 < 0) d1 = -d1;
                int d2 = rq + 8 - col;     if (d2 < 0) d2 = -d2;
                int d3 = rq + 8 - col - 1; if (d3 < 0) d3 = -d3;
                float e0 = __expf(fmaf(s[mf][nt][0], scale, __bfloat162float(rc[d0])));
                float e1 = __expf(fmaf(s[mf][nt][1], scale, __bfloat162float(rc[d1])));
                float e2 = __expf(fmaf(s[mf][nt][2], scale, __bfloat162float(rc[d2])));
                float e3 = __expf(fmaf(s[mf][nt][3], scale, __bfloat162float(rc[d3])));
                s[mf][nt][0] = e0; s[mf][nt][1] = e1;
                s[mf][nt][2] = e2; s[mf][nt][3] = e3;
                rs[mf][0] += e0 + e1;
                rs[mf][1] += e2 + e3;
                if (write_attn) {
                    __half* ep = escr + ((size_t)bh_i * N_ + rq) * N_ + col;
                    *(uint32_t*)ep = pkhf(e0, e1);
                    *(uint32_t*)(ep + 8 * N_) = pkhf(e2, e3);
                }
            }
        }

        // ---- O += e.V (single fp16 MMA; V frags shared by 2 m-frags) ----
        uint32_t vb0 = kb + 2 * 4608 * 2;
#pragma unroll
        for (int ks = 0; ks < 4; ks++) {
            uint32_t ea[2][4];
#pragma unroll
            for (int mf = 0; mf < 2; mf++) {
                ea[mf][0] = pkhf(s[mf][2 * ks][0], s[mf][2 * ks][1]);
                ea[mf][1] = pkhf(s[mf][2 * ks][2], s[mf][2 * ks][3]);
                ea[mf][2] = pkhf(s[mf][2 * ks + 1][0], s[mf][2 * ks + 1][1]);
                ea[mf][3] = pkhf(s[mf][2 * ks + 1][2], s[mf][2 * ks + 1][3]);
            }
            uint32_t vb[8][2];
#pragma unroll
            for (int ng = 0; ng < 4; ng++) {
                int brow = ng * 16 + (lane & 7) + ((lane & 16) >> 1);
                int bcol = ks * 16 + ((lane >> 3) & 1) * 8;
                uint32_t ba = vb0 + (uint32_t)(brow * AT_STR + bcol) * 2;
                ldsm4(vb[2 * ng][0], vb[2 * ng][1], vb[2 * ng + 1][0],
                      vb[2 * ng + 1][1], ba);
            }
#pragma unroll
            for (int mf = 0; mf < 2; mf++)
#pragma unroll
                for (int nh = 0; nh < 8; nh++)
                    mma16816h(co[mf][nh], ea[mf], vb[nh]);
        }

        if (t + 2 < N_ / 64) issue_kv(t + 2);
    }

    // ---- rowsum reduce + outputs per m-frag ----
#pragma unroll
    for (int mf = 0; mf < 2; mf++) {
        float r0 = rs[mf][0], r1 = rs[mf][1];
        r0 += __shfl_xor_sync(0xffffffffu, r0, 1);
        r0 += __shfl_xor_sync(0xffffffffu, r0, 2);
        r1 += __shfl_xor_sync(0xffffffffu, r1, 1);
        r1 += __shfl_xor_sync(0xffffffffu, r1, 2);
        int rq = row_q + mf * 16;
        if ((lane & 3) == 0) {
            g_rowsum[(size_t)bh_i * N_ + rq] = r0;
            g_rowsum[(size_t)bh_i * N_ + rq + 8] = r1;
        }
        float inv0 = 1.0f / r0, inv1 = 1.0f / r1;
#pragma unroll
        for (int nh = 0; nh < 8; nh++) {
            int hd = nh * 8 + ((lane & 3) << 1);
            size_t p = ((size_t)(b * N_ + rq)) * D_ + h * HD_ + hd;
            split_st2(g_aoh, g_aol, p,
                      make_float2(co[mf][nh][0] * inv0, co[mf][nh][1] * inv0));
            split_st2(g_aoh, g_aol, p + 8 * D_,
                      make_float2(co[mf][nh][2] * inv1, co[mf][nh][3] * inv1));
        }
    }
}

// =============================================================================
extern "C" void kernel_launch(void* const* d_in, const int* in_sizes, int n_in,
                              void* d_out, int out_size) {
    const float* query = (const float*)d_in[0];
    const float* w_in  = (const float*)d_in[4];
    const float* b_in  = (const float*)d_in[5];
    const float* w_out = (const float*)d_in[6];
    const float* b_out = (const float*)d_in[7];
    const float* rpe   = (const float*)d_in[8];

    float* out  = (float*)d_out;
    const long long out_elems  = (long long)B_ * N_ * D_;
    const long long attn_elems = (long long)BH_ * N_ * N_;
    int write_attn = ((long long)out_size >= out_elems + attn_elems) ? 1 : 0;
    float* attn = out + out_elems;

    cudaFuncSetAttribute(attn_kernel, cudaFuncAttributeMaxDynamicSharedMemorySize,
                         ATTN_SMEM);
    cudaFuncSetAttribute(qkv_gemm_k, cudaFuncAttributeMaxDynamicSharedMemorySize,
                         GEMM_SMEM);
    cudaFuncSetAttribute(v_gemm_k, cudaFuncAttributeMaxDynamicSharedMemorySize,
                         VGEMM_SMEM);
    cudaFuncSetAttribute(out_norm_kernel, cudaFuncAttributeMaxDynamicSharedMemorySize,
                         GEMM_SMEM);

    __nv_bfloat16 *xh, *xl, *wih, *wil, *aoh, *aol, *woh, *wol;
    __half *xf, *wvf, *escr;
    cudaGetSymbolAddress((void**)&xh,  g_xh);
    cudaGetSymbolAddress((void**)&xl,  g_xl);
    cudaGetSymbolAddress((void**)&xf,  g_xf);
    cudaGetSymbolAddress((void**)&wih, g_wih);
    cudaGetSymbolAddress((void**)&wil, g_wil);
    cudaGetSymbolAddress((void**)&wvf, g_wvf);
    cudaGetSymbolAddress((void**)&aoh, g_aoh);
    cudaGetSymbolAddress((void**)&aol, g_aol);
    cudaGetSymbolAddress((void**)&woh, g_woh);
    cudaGetSymbolAddress((void**)&wol, g_wol);
    cudaGetSymbolAddress((void**)&escr, g_escr);

    cvt3_kernel<<<8192, 256>>>(query, xh, xl, xf, w_in, wih, wil, wvf,
                               w_out, woh, wol);

    qkv_gemm_k<<<dim3(16, 32), 256, GEMM_SMEM>>>(xh, xl, wih, wil, b_in);
    v_gemm_k<<<dim3(8, 32), 256, VGEMM_SMEM>>>(xf, wvf, b_in);

    attn_kernel<<<dim3(8, 16, 2), 256, ATTN_SMEM>>>(escr, rpe, write_attn);

    out_norm_kernel<<<256 + NN_BLOCKS, 256, GEMM_SMEM>>>(
        aoh, aol, woh, wol, b_out, out, escr, attn, write_attn);
}

// round 16
// speedup vs baseline: 2.2794x; 1.1662x over previous
#include <cuda_runtime.h>
#include <cuda_bf16.h>
#include <cuda_fp16.h>
#include <cstdint>

#define B_  2
#define N_  2048
#define D_  1024
#define H_  16
#define HD_ 64
#define S_  2048
#define BH_ (B_*H_)

// ---------------- scratch ----------------------------------------------------
static __device__ float g_rowsum[(size_t)BH_*N_];

static __device__ __nv_bfloat16 g_xh[(size_t)4096*1024];
static __device__ __nv_bfloat16 g_xl[(size_t)4096*1024];
static __device__ __half        g_xf[(size_t)4096*1024];
static __device__ __nv_bfloat16 g_wih[(size_t)3072*1024];
static __device__ __nv_bfloat16 g_wil[(size_t)3072*1024];
static __device__ __half        g_wvf[(size_t)1024*1024];
static __device__ __nv_bfloat16 g_aoh[(size_t)4096*1024];
static __device__ __nv_bfloat16 g_aol[(size_t)4096*1024];
static __device__ __nv_bfloat16 g_woh[(size_t)1024*1024];
static __device__ __nv_bfloat16 g_wol[(size_t)1024*1024];

static __device__ __half g_Qf[(size_t)BH_*N_*HD_];          // fp16 [bh,n,hd]
static __device__ __half g_Kf[(size_t)BH_*N_*HD_];
static __device__ __half g_Vt[(size_t)BH_*HD_*N_];          // fp16 [bh,hd,n]
static __device__ __half g_escr[(size_t)BH_*N_*N_];         // fp16 unnormalized e

// ---------------- helpers ----------------------------------------------------
__device__ __forceinline__ uint32_t smem_u32(const void* p) {
    uint32_t a;
    asm("{ .reg .u64 t; cvta.to.shared.u64 t, %1; cvt.u32.u64 %0, t; }"
        : "=r"(a) : "l"(p));
    return a;
}
__device__ __forceinline__ void cp16(uint32_t dst, const void* src) {
    asm volatile("cp.async.cg.shared.global [%0], [%1], 16;" :: "r"(dst), "l"(src));
}
#define CP_COMMIT asm volatile("cp.async.commit_group;" ::: "memory")
#define CP_WAIT0  asm volatile("cp.async.wait_group 0;" ::: "memory")
#define CP_WAIT1  asm volatile("cp.async.wait_group 1;" ::: "memory")
#define CP_WAIT2  asm volatile("cp.async.wait_group 2;" ::: "memory")

__device__ __forceinline__ void ldsm4(uint32_t& r0, uint32_t& r1, uint32_t& r2,
                                      uint32_t& r3, uint32_t addr) {
    asm volatile("ldmatrix.sync.aligned.m8n8.x4.shared.b16 {%0,%1,%2,%3}, [%4];"
                 : "=r"(r0), "=r"(r1), "=r"(r2), "=r"(r3) : "r"(addr));
}
__device__ __forceinline__ void mma16816(float* c, const uint32_t* a,
                                         const uint32_t* b) {
    asm volatile(
        "mma.sync.aligned.m16n8k16.row.col.f32.bf16.bf16.f32 "
        "{%0,%1,%2,%3}, {%4,%5,%6,%7}, {%8,%9}, {%0,%1,%2,%3};"
        : "+f"(c[0]), "+f"(c[1]), "+f"(c[2]), "+f"(c[3])
        : "r"(a[0]), "r"(a[1]), "r"(a[2]), "r"(a[3]), "r"(b[0]), "r"(b[1]));
}
__device__ __forceinline__ void mma16816h(float* c, const uint32_t* a,
                                          const uint32_t* b) {
    asm volatile(
        "mma.sync.aligned.m16n8k16.row.col.f32.f16.f16.f32 "
        "{%0,%1,%2,%3}, {%4,%5,%6,%7}, {%8,%9}, {%0,%1,%2,%3};"
        : "+f"(c[0]), "+f"(c[1]), "+f"(c[2]), "+f"(c[3])
        : "r"(a[0]), "r"(a[1]), "r"(a[2]), "r"(a[3]), "r"(b[0]), "r"(b[1]));
}
__device__ __forceinline__ uint32_t pkhf(float lo, float hi) {
    uint32_t d;
    asm("cvt.rn.f16x2.f32 %0, %1, %2;" : "=r"(d) : "f"(hi), "f"(lo));
    return d;
}

// =============================================================================
// fp32 -> bf16 hi/lo split (+ fp16 copies of x and W_v), 3 tensors, one launch
// =============================================================================
__global__ void __launch_bounds__(256) cvt3_kernel(
        const float* __restrict__ x0, __nv_bfloat16* __restrict__ h0p,
        __nv_bfloat16* __restrict__ l0p, __half* __restrict__ xf,
        const float* __restrict__ x1, __nv_bfloat16* __restrict__ h1p,
        __nv_bfloat16* __restrict__ l1p, __half* __restrict__ wvf,
        const float* __restrict__ x2, __nv_bfloat16* __restrict__ h2p,
        __nv_bfloat16* __restrict__ l2p) {
    int blk = blockIdx.x;
    const float* x; __nv_bfloat16 *hi, *lo; int i; int which;
    if (blk < 4096)      { x = x0; hi = h0p; lo = l0p; i = blk * 256 + threadIdx.x; which = 0; }
    else if (blk < 7168) { x = x1; hi = h1p; lo = l1p; i = (blk - 4096) * 256 + threadIdx.x; which = 1; }
    else                 { x = x2; hi = h2p; lo = l2p; i = (blk - 7168) * 256 + threadIdx.x; which = 2; }
    float4 v = ((const float4*)x)[i];
    __nv_bfloat16 a0 = __float2bfloat16(v.x), a1 = __float2bfloat16(v.y);
    __nv_bfloat16 a2 = __float2bfloat16(v.z), a3 = __float2bfloat16(v.w);
    ((__nv_bfloat162*)hi)[2 * i] = __nv_bfloat162(a0, a1);
    ((__nv_bfloat162*)hi)[2 * i + 1] = __nv_bfloat162(a2, a3);
    ((__nv_bfloat162*)lo)[2 * i] = __nv_bfloat162(
        __float2bfloat16(v.x - __bfloat162float(a0)),
        __float2bfloat16(v.y - __bfloat162float(a1)));
    ((__nv_bfloat162*)lo)[2 * i + 1] = __nv_bfloat162(
        __float2bfloat16(v.z - __bfloat162float(a2)),
        __float2bfloat16(v.w - __bfloat162float(a3)));
    if (which == 0) {
        ((__half2*)xf)[2 * i] = __floats2half2_rn(v.x, v.y);
        ((__half2*)xf)[2 * i + 1] = __floats2half2_rn(v.z, v.w);
    } else if (which == 1 && i >= 524288) {     // W rows [2048,3072) = W_v
        int j = i - 524288;
        ((__half2*)wvf)[2 * j] = __floats2half2_rn(v.x, v.y);
        ((__half2*)wvf)[2 * j + 1] = __floats2half2_rn(v.z, v.w);
    }
}

// =============================================================================
// Split-bf16 GEMM core (Q/K projection + out projection)
// =============================================================================
#define SSTR  40
#define ARRB  (128*SSTR*2)
#define STAGE (4*ARRB)
#define GEMM_SMEM (2*STAGE)

__device__ __forceinline__ void split_st2(__nv_bfloat16* dh, __nv_bfloat16* dl,
                                          size_t idx, float2 v) {
    __nv_bfloat16 h0 = __float2bfloat16(v.x), h1 = __float2bfloat16(v.y);
    *(__nv_bfloat162*)(dh + idx) = __nv_bfloat162(h0, h1);
    *(__nv_bfloat162*)(dl + idx) = __nv_bfloat162(
        __float2bfloat16(v.x - __bfloat162float(h0)),
        __float2bfloat16(v.y - __bfloat162float(h1)));
}

template<bool QKV>
__device__ __forceinline__ void gemm_body(
        uint32_t sb, int m0, int n0,
        const __nv_bfloat16* __restrict__ Ah_g, const __nv_bfloat16* __restrict__ Al_g,
        const __nv_bfloat16* __restrict__ Bh_g, const __nv_bfloat16* __restrict__ Bl_g,
        const float* __restrict__ bias, float* __restrict__ outp) {
    int tid = threadIdx.x, lane = tid & 31, wid = tid >> 5;
    int wm = wid >> 1, wn = wid & 1;

    const __nv_bfloat16* base[4] = {
        Ah_g + (size_t)m0 * 1024, Al_g + (size_t)m0 * 1024,
        Bh_g + (size_t)n0 * 1024, Bl_g + (size_t)n0 * 1024 };

    float c[2][8][4];
#pragma unroll
    for (int mt = 0; mt < 2; mt++)
#pragma unroll
        for (int nt = 0; nt < 8; nt++)
#pragma unroll
            for (int q = 0; q < 4; q++) c[mt][nt][q] = 0.f;

    int r_ld = tid >> 2, c_ld = (tid & 3) << 3;

    {
#pragma unroll
        for (int arr = 0; arr < 4; arr++)
#pragma unroll
            for (int j = 0; j < 2; j++) {
                int r = r_ld + j * 64;
                cp16(sb + arr * ARRB + (uint32_t)(r * SSTR + c_ld) * 2,
                     base[arr] + (size_t)r * 1024 + c_ld);
            }
        CP_COMMIT;
    }

#pragma unroll 1
    for (int t = 0; t < 32; t++) {
        if (t + 1 < 32) {
            int s = (t + 1) & 1, k0 = (t + 1) << 5;
#pragma unroll
            for (int arr = 0; arr < 4; arr++)
#pragma unroll
                for (int j = 0; j < 2; j++) {
                    int r = r_ld + j * 64;
                    cp16(sb + (uint32_t)s * STAGE + arr * ARRB +
                             (uint32_t)(r * SSTR + c_ld) * 2,
                         base[arr] + (size_t)r * 1024 + k0 + c_ld);
                }
            CP_COMMIT;
            CP_WAIT1;
        } else {
            CP_WAIT0;
        }
        __syncthreads();

        uint32_t st = sb + (uint32_t)(t & 1) * STAGE;
#pragma unroll
        for (int kk = 0; kk < 2; kk++) {
            uint32_t bh[8][2], bl[8][2];
#pragma unroll
            for (int ng = 0; ng < 4; ng++) {
                int brow = wn * 64 + ng * 16 + (lane & 7) + ((lane & 16) >> 1);
                int bcol = kk * 16 + ((lane >> 3) & 1) * 8;
                uint32_t ba = st + 2 * ARRB + (uint32_t)(brow * SSTR + bcol) * 2;
                ldsm4(bh[2 * ng][0], bh[2 * ng][1], bh[2 * ng + 1][0],
                      bh[2 * ng + 1][1], ba);
                ldsm4(bl[2 * ng][0], bl[2 * ng][1], bl[2 * ng + 1][0],
                      bl[2 * ng + 1][1], ba + ARRB);
            }
#pragma unroll
            for (int mt = 0; mt < 2; mt++) {
                int arow = wm * 32 + mt * 16 + (lane & 15);
                int acol = kk * 16 + (lane >> 4) * 8;
                uint32_t aa = st + (uint32_t)(arow * SSTR + acol) * 2;
                uint32_t ah[4], al[4];
                ldsm4(ah[0], ah[1], ah[2], ah[3], aa);
                ldsm4(al[0], al[1], al[2], al[3], aa + ARRB);
#pragma unroll
                for (int nt = 0; nt < 8; nt++) {
                    mma16816(c[mt][nt], ah, bh[nt]);
                    mma16816(c[mt][nt], ah, bl[nt]);
                    mma16816(c[mt][nt], al, bh[nt]);
                }
            }
        }
        __syncthreads();
    }

#pragma unroll
    for (int mt = 0; mt < 2; mt++) {
        int m = m0 + wm * 32 + mt * 16 + (lane >> 2);
#pragma unroll
        for (int nt = 0; nt < 8; nt++) {
            int n = n0 + wn * 64 + nt * 8 + ((lane & 3) << 1);
            float b0 = bias[n], b1 = bias[n + 1];
            float2 v0 = make_float2(c[mt][nt][0] + b0, c[mt][nt][1] + b1);
            float2 v1 = make_float2(c[mt][nt][2] + b0, c[mt][nt][3] + b1);
            if (QKV) {                       // Q and K sections (n < 2048), fp16 store
                int sect = n >> 10;
                int h = (n & 1023) >> 6, hd = n & 63;
                int bb = m >> 11, row = m & 2047;
                int bh_i = bb * H_ + h;
                __half* d = sect == 0 ? g_Qf : g_Kf;
                size_t p = ((size_t)bh_i * N_ + row) * HD_ + hd;
                *(__half2*)(d + p) = __floats2half2_rn(v0.x, v0.y);
                *(__half2*)(d + p + 8 * HD_) = __floats2half2_rn(v1.x, v1.y);
            } else {
                float* p = outp + (size_t)m * 1024 + n;
                *(float2*)p = v0;
                *(float2*)(p + 8 * 1024) = v1;
            }
        }
    }
}

// =============================================================================
// V projection body: single-fp16 GEMM, scatter transposed into g_Vt.
// =============================================================================
__device__ __forceinline__ void v_body(uint32_t sb, int m0, int n0,
        const __half* __restrict__ A_g, const __half* __restrict__ B_g,
        const float* __restrict__ bias) {
    int tid = threadIdx.x, lane = tid & 31, wid = tid >> 5;
    int wm = wid >> 1, wn = wid & 1;
    const int VSTAGE = 2 * ARRB;

    const __half* base[2] = { A_g + (size_t)m0 * 1024, B_g + (size_t)n0 * 1024 };

    float c[2][8][4];
#pragma unroll
    for (int mt = 0; mt < 2; mt++)
#pragma unroll
        for (int nt = 0; nt < 8; nt++)
#pragma unroll
            for (int q = 0; q < 4; q++) c[mt][nt][q] = 0.f;

    int r_ld = tid >> 2, c_ld = (tid & 3) << 3;
    {
#pragma unroll
        for (int arr = 0; arr < 2; arr++)
#pragma unroll
            for (int j = 0; j < 2; j++) {
                int r = r_ld + j * 64;
                cp16(sb + arr * ARRB + (uint32_t)(r * SSTR + c_ld) * 2,
                     base[arr] + (size_t)r * 1024 + c_ld);
            }
        CP_COMMIT;
    }

#pragma unroll 1
    for (int t = 0; t < 32; t++) {
        if (t + 1 < 32) {
            int s = (t + 1) & 1, k0 = (t + 1) << 5;
#pragma unroll
            for (int arr = 0; arr < 2; arr++)
#pragma unroll
                for (int j = 0; j < 2; j++) {
                    int r = r_ld + j * 64;
                    cp16(sb + (uint32_t)s * VSTAGE + arr * ARRB +
                             (uint32_t)(r * SSTR + c_ld) * 2,
                         base[arr] + (size_t)r * 1024 + k0 + c_ld);
                }
            CP_COMMIT;
            CP_WAIT1;
        } else {
            CP_WAIT0;
        }
        __syncthreads();

        uint32_t st = sb + (uint32_t)(t & 1) * VSTAGE;
#pragma unroll
        for (int kk = 0; kk < 2; kk++) {
            uint32_t bb[8][2];
#pragma unroll
            for (int ng = 0; ng < 4; ng++) {
                int brow = wn * 64 + ng * 16 + (lane & 7) + ((lane & 16) >> 1);
                int bcol = kk * 16 + ((lane >> 3) & 1) * 8;
                uint32_t ba = st + ARRB + (uint32_t)(brow * SSTR + bcol) * 2;
                ldsm4(bb[2 * ng][0], bb[2 * ng][1], bb[2 * ng + 1][0],
                      bb[2 * ng + 1][1], ba);
            }
#pragma unroll
            for (int mt = 0; mt < 2; mt++) {
                int arow = wm * 32 + mt * 16 + (lane & 15);
                int acol = kk * 16 + (lane >> 4) * 8;
                uint32_t aa = st + (uint32_t)(arow * SSTR + acol) * 2;
                uint32_t ah[4];
                ldsm4(ah[0], ah[1], ah[2], ah[3], aa);
#pragma unroll
                for (int nt = 0; nt < 8; nt++)
                    mma16816h(c[mt][nt], ah, bb[nt]);
            }
        }
        __syncthreads();
    }

#pragma unroll
    for (int mt = 0; mt < 2; mt++) {
        int m = m0 + wm * 32 + mt * 16 + (lane >> 2);
#pragma unroll
        for (int nt = 0; nt < 8; nt++) {
            int n = n0 + wn * 64 + nt * 8 + ((lane & 3) << 1);
            float b0 = bias[2048 + n], b1 = bias[2048 + n + 1];
            int h = n >> 6, hd = n & 63;
            int bb = m >> 11, row = m & 2047;
            int bh_i = bb * H_ + h;
            size_t pb = ((size_t)bh_i * HD_ + hd) * N_ + row;
            g_Vt[pb]          = __float2half(c[mt][nt][0] + b0);
            g_Vt[pb + N_]     = __float2half(c[mt][nt][1] + b1);
            g_Vt[pb + 8]      = __float2half(c[mt][nt][2] + b0);
            g_Vt[pb + N_ + 8] = __float2half(c[mt][nt][3] + b1);
        }
    }
}

// Fused Q/K projection (split bf16) + V projection (fp16) in one launch.
__global__ void __launch_bounds__(256) qkv_all_kernel(
        const __nv_bfloat16* __restrict__ xh, const __nv_bfloat16* __restrict__ xl,
        const __nv_bfloat16* __restrict__ wih, const __nv_bfloat16* __restrict__ wil,
        const __half* __restrict__ xf, const __half* __restrict__ wvf,
        const float* __restrict__ bias) {
    extern __shared__ char smem[];
    int blk = blockIdx.x;
    if (blk < 512) {
        gemm_body<true>(smem_u32(smem), (blk >> 4) << 7, (blk & 15) << 7,
                        xh, xl, wih, wil, bias, nullptr);
    } else {
        int vb = blk - 512;
        v_body(smem_u32(smem), (vb >> 3) << 7, (vb & 7) << 7, xf, wvf, bias);
    }
}

// =============================================================================
// Fused out-projection GEMM + attn normalize (reads fp16 escr, writes fp32)
// =============================================================================
#define NN_BLOCKS 2048

__global__ void __launch_bounds__(256, 2) out_norm_kernel(
        const __nv_bfloat16* __restrict__ Ah_g, const __nv_bfloat16* __restrict__ Al_g,
        const __nv_bfloat16* __restrict__ Bh_g, const __nv_bfloat16* __restrict__ Bl_g,
        const float* __restrict__ bias, float* __restrict__ outp,
        const __half* __restrict__ escr, float* __restrict__ attn, int write_attn) {
    int blk = blockIdx.x;
    if (blk < 256) {
        extern __shared__ char smem[];
        int n0 = (blk & 7) << 7, m0 = (blk >> 3) << 7;
        gemm_body<false>(smem_u32(smem), m0, n0, Ah_g, Al_g, Bh_g, Bl_g, bias, outp);
        return;
    }
    if (!write_attn) return;
    const size_t total4 = (size_t)BH_ * N_ * N_ / 4;
    const size_t per_blk = total4 / NN_BLOCKS;
    size_t i0 = (size_t)(blk - 256) * per_blk;
    int tid = threadIdx.x;
#pragma unroll 1
    for (int it = 0; it < 8; it++) {
        size_t idx[8];
        uint2 ev[8];
#pragma unroll
        for (int u = 0; u < 8; u++) {
            idx[u] = i0 + (size_t)(it * 8 + u) * 256 + tid;
            ev[u] = __ldcs((const uint2*)escr + idx[u]);
        }
#pragma unroll
        for (int u = 0; u < 8; u++) {
            int row = (int)(idx[u] >> 9);
            float inv = 1.0f / g_rowsum[row];
            __half2 p0 = *(__half2*)&ev[u].x;
            __half2 p1 = *(__half2*)&ev[u].y;
            float4 v = make_float4(__low2float(p0) * inv, __high2float(p0) * inv,
                                   __low2float(p1) * inv, __high2float(p1) * inv);
            __stcs((float4*)attn + idx[u], v);
        }
    }
}

// =============================================================================
// Fused attention, all-fp16 operands: S = Qf.Kf^T (1 MMA), O += e.V (1 MMA).
// Q fragments hoisted to registers; 256-row Q tile; 3-stage K+V ring.
// =============================================================================
#define AT_STR 72
#define AQ  0
#define AKV (256*AT_STR)
#define KVSTG (2*64*AT_STR)
#define ABF_END (AKV + 3*KVSTG)
#define ATTN_SMEM (ABF_END*2 + 2048*2)      // 96256 B

__global__ void __launch_bounds__(256, 1) attn_kernel(__half* __restrict__ escr,
                                                      const float* __restrict__ rpe,
                                                      int write_attn) {
    extern __shared__ char smc[];
    uint32_t sb = smem_u32(smc);
    __nv_bfloat16* rc = (__nv_bfloat16*)(smc + ABF_END * 2);

    int qt = blockIdx.x, h = blockIdx.y, b = blockIdx.z;
    int bh_i = b * H_ + h;
    int tid = threadIdx.x, lane = tid & 31, wm = tid >> 5;
    int q0 = qt << 8;

    for (int i = tid; i < S_; i += 256)
        rc[i] = __float2bfloat16(rpe[(size_t)i * H_ + h]);

    const __half* qg = g_Qf + ((size_t)bh_i * N_ + q0) * HD_;
    const __half* kg = g_Kf + (size_t)bh_i * N_ * HD_;
    const __half* vg = g_Vt + (size_t)bh_i * HD_ * N_;

    // Q load: 256 rows x 64 cols fp16
#pragma unroll
    for (int j = 0; j < 8; j++) {
        int u = tid + j * 256;
        int r = u >> 3, ch = (u & 7) << 3;
        cp16(sb + (uint32_t)(AQ + r * AT_STR + ch) * 2, qg + (size_t)r * HD_ + ch);
    }
    CP_COMMIT;

    int r_ld = tid >> 3, c_ld = (tid & 7) << 3;
    auto issue_kv = [&](int t) {
        int k0g = t * 64;
        uint32_t stg = sb + (uint32_t)(AKV + (t % 3) * KVSTG) * 2;
#pragma unroll
        for (int j = 0; j < 2; j++) {
            int r = r_ld + j * 32, ch = c_ld;
            cp16(stg + (uint32_t)(r * AT_STR + ch) * 2,
                 kg + (size_t)(k0g + r) * HD_ + ch);
            cp16(stg + (uint32_t)(4608 + r * AT_STR + ch) * 2,
                 vg + (size_t)r * N_ + k0g + ch);
        }
        CP_COMMIT;
    };
    issue_kv(0);
    issue_kv(1);

    // hoist Q fragments to registers (Q smem never changes)
    CP_WAIT2;            // Q group done (kv0, kv1 may be pending)
    __syncthreads();
    uint32_t qa[2][4][4];
#pragma unroll
    for (int mf = 0; mf < 2; mf++)
#pragma unroll
        for (int ks = 0; ks < 4; ks++) {
            int arow = wm * 32 + mf * 16 + (lane & 15);
            int acol = ks * 16 + (lane >> 4) * 8;
            uint32_t aa = sb + (uint32_t)(AQ + arow * AT_STR + acol) * 2;
            ldsm4(qa[mf][ks][0], qa[mf][ks][1], qa[mf][ks][2], qa[mf][ks][3], aa);
        }

    float co[2][8][4];
#pragma unroll
    for (int mf = 0; mf < 2; mf++)
#pragma unroll
        for (int nh = 0; nh < 8; nh++)
#pragma unroll
            for (int q = 0; q < 4; q++) co[mf][nh][q] = 0.f;
    float rs[2][2] = {{0.f, 0.f}, {0.f, 0.f}};

    int row_q = q0 + wm * 32 + (lane >> 2);
    const float scale = 0.125f;

#pragma unroll 1
    for (int t = 0; t < N_ / 64; t++) {
        if (t < 31) { CP_WAIT1; } else { CP_WAIT0; }
        __syncthreads();

        int k0g = t * 64;
        uint32_t kb = sb + (uint32_t)(AKV + (t % 3) * KVSTG) * 2;

        // ---- S = Qf.Kf^T (single fp16 MMA) ----
        float s[2][8][4];
#pragma unroll
        for (int mf = 0; mf < 2; mf++)
#pragma unroll
            for (int nt = 0; nt < 8; nt++)
#pragma unroll
                for (int q = 0; q < 4; q++) s[mf][nt][q] = 0.f;
#pragma unroll
        for (int ks = 0; ks < 4; ks++) {
            uint32_t bh[8][2];
#pragma unroll
            for (int ng = 0; ng < 4; ng++) {
                int brow = ng * 16 + (lane & 7) + ((lane & 16) >> 1);
                int bcol = ks * 16 + ((lane >> 3) & 1) * 8;
                uint32_t ba = kb + (uint32_t)(brow * AT_STR + bcol) * 2;
                ldsm4(bh[2 * ng][0], bh[2 * ng][1], bh[2 * ng + 1][0],
                      bh[2 * ng + 1][1], ba);
            }
#pragma unroll
            for (int mf = 0; mf < 2; mf++)
#pragma unroll
                for (int nt = 0; nt < 8; nt++)
                    mma16816h(s[mf][nt], qa[mf][ks], bh[nt]);
        }

        // ---- bias + exp + rowsum + fp16 e store ----
#pragma unroll
        for (int mf = 0; mf < 2; mf++) {
            int rq = row_q + mf * 16;
#pragma unroll
            for (int nt = 0; nt < 8; nt++) {
                int col = k0g + nt * 8 + ((lane & 3) << 1);
                int d0 = rq - col;     if (d0 < 0) d0 = -d0;
                int d1 = rq - col - 1; if (d1 < 0) d1 = -d1;
                int d2 = rq + 8 - col;     if (d2 < 0) d2 = -d2;
                int d3 = rq + 8 - col - 1; if (d3 < 0) d3 = -d3;
                float e0 = __expf(fmaf(s[mf][nt][0], scale, __bfloat162float(rc[d0])));
                float e1 = __expf(fmaf(s[mf][nt][1], scale, __bfloat162float(rc[d1])));
                float e2 = __expf(fmaf(s[mf][nt][2], scale, __bfloat162float(rc[d2])));
                float e3 = __expf(fmaf(s[mf][nt][3], scale, __bfloat162float(rc[d3])));
                s[mf][nt][0] = e0; s[mf][nt][1] = e1;
                s[mf][nt][2] = e2; s[mf][nt][3] = e3;
                rs[mf][0] += e0 + e1;
                rs[mf][1] += e2 + e3;
                if (write_attn) {
                    __half* ep = escr + ((size_t)bh_i * N_ + rq) * N_ + col;
                    *(uint32_t*)ep = pkhf(e0, e1);
                    *(uint32_t*)(ep + 8 * N_) = pkhf(e2, e3);
                }
            }
        }

        // ---- O += e.V (single fp16 MMA) ----
        uint32_t vb0 = kb + 4608 * 2;
#pragma unroll
        for (int ks = 0; ks < 4; ks++) {
            uint32_t ea[2][4];
#pragma unroll
            for (int mf = 0; mf < 2; mf++) {
                ea[mf][0] = pkhf(s[mf][2 * ks][0], s[mf][2 * ks][1]);
                ea[mf][1] = pkhf(s[mf][2 * ks][2], s[mf][2 * ks][3]);
                ea[mf][2] = pkhf(s[mf][2 * ks + 1][0], s[mf][2 * ks + 1][1]);
                ea[mf][3] = pkhf(s[mf][2 * ks + 1][2], s[mf][2 * ks + 1][3]);
            }
            uint32_t vb[8][2];
#pragma unroll
            for (int ng = 0; ng < 4; ng++) {
                int brow = ng * 16 + (lane & 7) + ((lane & 16) >> 1);
                int bcol = ks * 16 + ((lane >> 3) & 1) * 8;
                uint32_t ba = vb0 + (uint32_t)(brow * AT_STR + bcol) * 2;
                ldsm4(vb[2 * ng][0], vb[2 * ng][1], vb[2 * ng + 1][0],
                      vb[2 * ng + 1][1], ba);
            }
#pragma unroll
            for (int mf = 0; mf < 2; mf++)
#pragma unroll
                for (int nh = 0; nh < 8; nh++)
                    mma16816h(co[mf][nh], ea[mf], vb[nh]);
        }

        if (t + 2 < N_ / 64) issue_kv(t + 2);
    }

    // ---- rowsum reduce + outputs per m-frag ----
#pragma unroll
    for (int mf = 0; mf < 2; mf++) {
        float r0 = rs[mf][0], r1 = rs[mf][1];
        r0 += __shfl_xor_sync(0xffffffffu, r0, 1);
        r0 += __shfl_xor_sync(0xffffffffu, r0, 2);
        r1 += __shfl_xor_sync(0xffffffffu, r1, 1);
        r1 += __shfl_xor_sync(0xffffffffu, r1, 2);
        int rq = row_q + mf * 16;
        if ((lane & 3) == 0) {
            g_rowsum[(size_t)bh_i * N_ + rq] = r0;
            g_rowsum[(size_t)bh_i * N_ + rq + 8] = r1;
        }
        float inv0 = 1.0f / r0, inv1 = 1.0f / r1;
#pragma unroll
        for (int nh = 0; nh < 8; nh++) {
            int hd = nh * 8 + ((lane & 3) << 1);
            size_t p = ((size_t)(b * N_ + rq)) * D_ + h * HD_ + hd;
            split_st2(g_aoh, g_aol, p,
                      make_float2(co[mf][nh][0] * inv0, co[mf][nh][1] * inv0));
            split_st2(g_aoh, g_aol, p + 8 * D_,
                      make_float2(co[mf][nh][2] * inv1, co[mf][nh][3] * inv1));
        }
    }
}

// =============================================================================
extern "C" void kernel_launch(void* const* d_in, const int* in_sizes, int n_in,
                              void* d_out, int out_size) {
    const float* query = (const float*)d_in[0];
    const float* w_in  = (const float*)d_in[4];
    const float* b_in  = (const float*)d_in[5];
    const float* w_out = (const float*)d_in[6];
    const float* b_out = (const float*)d_in[7];
    const float* rpe   = (const float*)d_in[8];

    float* out  = (float*)d_out;
    const long long out_elems  = (long long)B_ * N_ * D_;
    const long long attn_elems = (long long)BH_ * N_ * N_;
    int write_attn = ((long long)out_size >= out_elems + attn_elems) ? 1 : 0;
    float* attn = out + out_elems;

    cudaFuncSetAttribute(attn_kernel, cudaFuncAttributeMaxDynamicSharedMemorySize,
                         ATTN_SMEM);
    cudaFuncSetAttribute(qkv_all_kernel, cudaFuncAttributeMaxDynamicSharedMemorySize,
                         GEMM_SMEM);
    cudaFuncSetAttribute(out_norm_kernel, cudaFuncAttributeMaxDynamicSharedMemorySize,
                         GEMM_SMEM);

    __nv_bfloat16 *xh, *xl, *wih, *wil, *aoh, *aol, *woh, *wol;
    __half *xf, *wvf, *escr;
    cudaGetSymbolAddress((void**)&xh,  g_xh);
    cudaGetSymbolAddress((void**)&xl,  g_xl);
    cudaGetSymbolAddress((void**)&xf,  g_xf);
    cudaGetSymbolAddress((void**)&wih, g_wih);
    cudaGetSymbolAddress((void**)&wil, g_wil);
    cudaGetSymbolAddress((void**)&wvf, g_wvf);
    cudaGetSymbolAddress((void**)&aoh, g_aoh);
    cudaGetSymbolAddress((void**)&aol, g_aol);
    cudaGetSymbolAddress((void**)&woh, g_woh);
    cudaGetSymbolAddress((void**)&wol, g_wol);
    cudaGetSymbolAddress((void**)&escr, g_escr);

    cvt3_kernel<<<8192, 256>>>(query, xh, xl, xf, w_in, wih, wil, wvf,
                               w_out, woh, wol);

    qkv_all_kernel<<<768, 256, GEMM_SMEM>>>(xh, xl, wih, wil, xf, wvf, b_in);

    attn_kernel<<<dim3(8, 16, 2), 256, ATTN_SMEM>>>(escr, rpe, write_attn);

    out_norm_kernel<<<256 + NN_BLOCKS, 256, GEMM_SMEM>>>(
        aoh, aol, woh, wol, b_out, out, escr, attn, write_attn);
}

// round 17
// speedup vs baseline: 2.3069x; 1.0121x over previous
#include <cuda_runtime.h>
#include <cuda_bf16.h>
#include <cuda_fp16.h>
#include <cstdint>

#define B_  2
#define N_  2048
#define D_  1024
#define H_  16
#define HD_ 64
#define S_  2048
#define BH_ (B_*H_)

// ---------------- scratch ----------------------------------------------------
static __device__ float g_rowsum[(size_t)BH_*N_];

static __device__ __nv_bfloat16 g_xh[(size_t)4096*1024];
static __device__ __nv_bfloat16 g_xl[(size_t)4096*1024];
static __device__ __half        g_xf[(size_t)4096*1024];
static __device__ __nv_bfloat16 g_wih[(size_t)3072*1024];
static __device__ __nv_bfloat16 g_wil[(size_t)3072*1024];
static __device__ __half        g_wvf[(size_t)1024*1024];
static __device__ __nv_bfloat16 g_aoh[(size_t)4096*1024];
static __device__ __nv_bfloat16 g_aol[(size_t)4096*1024];
static __device__ __nv_bfloat16 g_woh[(size_t)1024*1024];
static __device__ __nv_bfloat16 g_wol[(size_t)1024*1024];

static __device__ __half g_Qf[(size_t)BH_*N_*HD_];          // fp16 [bh,n,hd]
static __device__ __half g_Kf[(size_t)BH_*N_*HD_];
static __device__ __half g_Vt[(size_t)BH_*HD_*N_];          // fp16 [bh,hd,n]
static __device__ __half g_escr[(size_t)BH_*N_*N_];         // fp16 unnormalized e

// ---------------- helpers ----------------------------------------------------
__device__ __forceinline__ uint32_t smem_u32(const void* p) {
    uint32_t a;
    asm("{ .reg .u64 t; cvta.to.shared.u64 t, %1; cvt.u32.u64 %0, t; }"
        : "=r"(a) : "l"(p));
    return a;
}
__device__ __forceinline__ void cp16(uint32_t dst, const void* src) {
    asm volatile("cp.async.cg.shared.global [%0], [%1], 16;" :: "r"(dst), "l"(src));
}
#define CP_COMMIT asm volatile("cp.async.commit_group;" ::: "memory")
#define CP_WAIT0  asm volatile("cp.async.wait_group 0;" ::: "memory")
#define CP_WAIT1  asm volatile("cp.async.wait_group 1;" ::: "memory")
#define CP_WAIT2  asm volatile("cp.async.wait_group 2;" ::: "memory")

__device__ __forceinline__ void ldsm4(uint32_t& r0, uint32_t& r1, uint32_t& r2,
                                      uint32_t& r3, uint32_t addr) {
    asm volatile("ldmatrix.sync.aligned.m8n8.x4.shared.b16 {%0,%1,%2,%3}, [%4];"
                 : "=r"(r0), "=r"(r1), "=r"(r2), "=r"(r3) : "r"(addr));
}
__device__ __forceinline__ void mma16816(float* c, const uint32_t* a,
                                         const uint32_t* b) {
    asm volatile(
        "mma.sync.aligned.m16n8k16.row.col.f32.bf16.bf16.f32 "
        "{%0,%1,%2,%3}, {%4,%5,%6,%7}, {%8,%9}, {%0,%1,%2,%3};"
        : "+f"(c[0]), "+f"(c[1]), "+f"(c[2]), "+f"(c[3])
        : "r"(a[0]), "r"(a[1]), "r"(a[2]), "r"(a[3]), "r"(b[0]), "r"(b[1]));
}
__device__ __forceinline__ void mma16816h(float* c, const uint32_t* a,
                                          const uint32_t* b) {
    asm volatile(
        "mma.sync.aligned.m16n8k16.row.col.f32.f16.f16.f32 "
        "{%0,%1,%2,%3}, {%4,%5,%6,%7}, {%8,%9}, {%0,%1,%2,%3};"
        : "+f"(c[0]), "+f"(c[1]), "+f"(c[2]), "+f"(c[3])
        : "r"(a[0]), "r"(a[1]), "r"(a[2]), "r"(a[3]), "r"(b[0]), "r"(b[1]));
}
__device__ __forceinline__ uint32_t pkhf(float lo, float hi) {
    uint32_t d;
    asm("cvt.rn.f16x2.f32 %0, %1, %2;" : "=r"(d) : "f"(hi), "f"(lo));
    return d;
}

// =============================================================================
// fp32 -> bf16 hi/lo split (+ fp16 copies of x and W_v), 3 tensors, one launch
// =============================================================================
__global__ void __launch_bounds__(256) cvt3_kernel(
        const float* __restrict__ x0, __nv_bfloat16* __restrict__ h0p,
        __nv_bfloat16* __restrict__ l0p, __half* __restrict__ xf,
        const float* __restrict__ x1, __nv_bfloat16* __restrict__ h1p,
        __nv_bfloat16* __restrict__ l1p, __half* __restrict__ wvf,
        const float* __restrict__ x2, __nv_bfloat16* __restrict__ h2p,
        __nv_bfloat16* __restrict__ l2p) {
    int blk = blockIdx.x;
    const float* x; __nv_bfloat16 *hi, *lo; int i; int which;
    if (blk < 4096)      { x = x0; hi = h0p; lo = l0p; i = blk * 256 + threadIdx.x; which = 0; }
    else if (blk < 7168) { x = x1; hi = h1p; lo = l1p; i = (blk - 4096) * 256 + threadIdx.x; which = 1; }
    else                 { x = x2; hi = h2p; lo = l2p; i = (blk - 7168) * 256 + threadIdx.x; which = 2; }
    float4 v = ((const float4*)x)[i];
    __nv_bfloat16 a0 = __float2bfloat16(v.x), a1 = __float2bfloat16(v.y);
    __nv_bfloat16 a2 = __float2bfloat16(v.z), a3 = __float2bfloat16(v.w);
    ((__nv_bfloat162*)hi)[2 * i] = __nv_bfloat162(a0, a1);
    ((__nv_bfloat162*)hi)[2 * i + 1] = __nv_bfloat162(a2, a3);
    ((__nv_bfloat162*)lo)[2 * i] = __nv_bfloat162(
        __float2bfloat16(v.x - __bfloat162float(a0)),
        __float2bfloat16(v.y - __bfloat162float(a1)));
    ((__nv_bfloat162*)lo)[2 * i + 1] = __nv_bfloat162(
        __float2bfloat16(v.z - __bfloat162float(a2)),
        __float2bfloat16(v.w - __bfloat162float(a3)));
    if (which == 0) {
        ((__half2*)xf)[2 * i] = __floats2half2_rn(v.x, v.y);
        ((__half2*)xf)[2 * i + 1] = __floats2half2_rn(v.z, v.w);
    } else if (which == 1 && i >= 524288) {     // W rows [2048,3072) = W_v
        int j = i - 524288;
        ((__half2*)wvf)[2 * j] = __floats2half2_rn(v.x, v.y);
        ((__half2*)wvf)[2 * j + 1] = __floats2half2_rn(v.z, v.w);
    }
}

// =============================================================================
// Split-bf16 GEMM core (Q/K projection + out projection)
// =============================================================================
#define SSTR  40
#define ARRB  (128*SSTR*2)
#define STAGE (4*ARRB)
#define GEMM_SMEM (2*STAGE)

__device__ __forceinline__ void split_st2(__nv_bfloat16* dh, __nv_bfloat16* dl,
                                          size_t idx, float2 v) {
    __nv_bfloat16 h0 = __float2bfloat16(v.x), h1 = __float2bfloat16(v.y);
    *(__nv_bfloat162*)(dh + idx) = __nv_bfloat162(h0, h1);
    *(__nv_bfloat162*)(dl + idx) = __nv_bfloat162(
        __float2bfloat16(v.x - __bfloat162float(h0)),
        __float2bfloat16(v.y - __bfloat162float(h1)));
}

template<bool QKV>
__device__ __forceinline__ void gemm_body(
        uint32_t sb, int m0, int n0,
        const __nv_bfloat16* __restrict__ Ah_g, const __nv_bfloat16* __restrict__ Al_g,
        const __nv_bfloat16* __restrict__ Bh_g, const __nv_bfloat16* __restrict__ Bl_g,
        const float* __restrict__ bias, float* __restrict__ outp) {
    int tid = threadIdx.x, lane = tid & 31, wid = tid >> 5;
    int wm = wid >> 1, wn = wid & 1;

    const __nv_bfloat16* base[4] = {
        Ah_g + (size_t)m0 * 1024, Al_g + (size_t)m0 * 1024,
        Bh_g + (size_t)n0 * 1024, Bl_g + (size_t)n0 * 1024 };

    float c[2][8][4];
#pragma unroll
    for (int mt = 0; mt < 2; mt++)
#pragma unroll
        for (int nt = 0; nt < 8; nt++)
#pragma unroll
            for (int q = 0; q < 4; q++) c[mt][nt][q] = 0.f;

    int r_ld = tid >> 2, c_ld = (tid & 3) << 3;

    {
#pragma unroll
        for (int arr = 0; arr < 4; arr++)
#pragma unroll
            for (int j = 0; j < 2; j++) {
                int r = r_ld + j * 64;
                cp16(sb + arr * ARRB + (uint32_t)(r * SSTR + c_ld) * 2,
                     base[arr] + (size_t)r * 1024 + c_ld);
            }
        CP_COMMIT;
    }

#pragma unroll 1
    for (int t = 0; t < 32; t++) {
        if (t + 1 < 32) {
            int s = (t + 1) & 1, k0 = (t + 1) << 5;
#pragma unroll
            for (int arr = 0; arr < 4; arr++)
#pragma unroll
                for (int j = 0; j < 2; j++) {
                    int r = r_ld + j * 64;
                    cp16(sb + (uint32_t)s * STAGE + arr * ARRB +
                             (uint32_t)(r * SSTR + c_ld) * 2,
                         base[arr] + (size_t)r * 1024 + k0 + c_ld);
                }
            CP_COMMIT;
            CP_WAIT1;
        } else {
            CP_WAIT0;
        }
        __syncthreads();

        uint32_t st = sb + (uint32_t)(t & 1) * STAGE;
#pragma unroll
        for (int kk = 0; kk < 2; kk++) {
            uint32_t bh[8][2], bl[8][2];
#pragma unroll
            for (int ng = 0; ng < 4; ng++) {
                int brow = wn * 64 + ng * 16 + (lane & 7) + ((lane & 16) >> 1);
                int bcol = kk * 16 + ((lane >> 3) & 1) * 8;
                uint32_t ba = st + 2 * ARRB + (uint32_t)(brow * SSTR + bcol) * 2;
                ldsm4(bh[2 * ng][0], bh[2 * ng][1], bh[2 * ng + 1][0],
                      bh[2 * ng + 1][1], ba);
                ldsm4(bl[2 * ng][0], bl[2 * ng][1], bl[2 * ng + 1][0],
                      bl[2 * ng + 1][1], ba + ARRB);
            }
#pragma unroll
            for (int mt = 0; mt < 2; mt++) {
                int arow = wm * 32 + mt * 16 + (lane & 15);
                int acol = kk * 16 + (lane >> 4) * 8;
                uint32_t aa = st + (uint32_t)(arow * SSTR + acol) * 2;
                uint32_t ah[4], al[4];
                ldsm4(ah[0], ah[1], ah[2], ah[3], aa);
                ldsm4(al[0], al[1], al[2], al[3], aa + ARRB);
#pragma unroll
                for (int nt = 0; nt < 8; nt++) {
                    mma16816(c[mt][nt], ah, bh[nt]);
                    mma16816(c[mt][nt], ah, bl[nt]);
                    mma16816(c[mt][nt], al, bh[nt]);
                }
            }
        }
        __syncthreads();
    }

#pragma unroll
    for (int mt = 0; mt < 2; mt++) {
        int m = m0 + wm * 32 + mt * 16 + (lane >> 2);
#pragma unroll
        for (int nt = 0; nt < 8; nt++) {
            int n = n0 + wn * 64 + nt * 8 + ((lane & 3) << 1);
            float b0 = bias[n], b1 = bias[n + 1];
            float2 v0 = make_float2(c[mt][nt][0] + b0, c[mt][nt][1] + b1);
            float2 v1 = make_float2(c[mt][nt][2] + b0, c[mt][nt][3] + b1);
            if (QKV) {                       // Q and K sections (n < 2048), fp16 store
                int sect = n >> 10;
                int h = (n & 1023) >> 6, hd = n & 63;
                int bb = m >> 11, row = m & 2047;
                int bh_i = bb * H_ + h;
                __half* d = sect == 0 ? g_Qf : g_Kf;
                size_t p = ((size_t)bh_i * N_ + row) * HD_ + hd;
                *(__half2*)(d + p) = __floats2half2_rn(v0.x, v0.y);
                *(__half2*)(d + p + 8 * HD_) = __floats2half2_rn(v1.x, v1.y);
            } else {
                float* p = outp + (size_t)m * 1024 + n;
                *(float2*)p = v0;
                *(float2*)(p + 8 * 1024) = v1;
            }
        }
    }
}

// =============================================================================
// V projection body: single-fp16 GEMM, scatter transposed into g_Vt.
// =============================================================================
__device__ __forceinline__ void v_body(uint32_t sb, int m0, int n0,
        const __half* __restrict__ A_g, const __half* __restrict__ B_g,
        const float* __restrict__ bias) {
    int tid = threadIdx.x, lane = tid & 31, wid = tid >> 5;
    int wm = wid >> 1, wn = wid & 1;
    const int VSTAGE = 2 * ARRB;

    const __half* base[2] = { A_g + (size_t)m0 * 1024, B_g + (size_t)n0 * 1024 };

    float c[2][8][4];
#pragma unroll
    for (int mt = 0; mt < 2; mt++)
#pragma unroll
        for (int nt = 0; nt < 8; nt++)
#pragma unroll
            for (int q = 0; q < 4; q++) c[mt][nt][q] = 0.f;

    int r_ld = tid >> 2, c_ld = (tid & 3) << 3;
    {
#pragma unroll
        for (int arr = 0; arr < 2; arr++)
#pragma unroll
            for (int j = 0; j < 2; j++) {
                int r = r_ld + j * 64;
                cp16(sb + arr * ARRB + (uint32_t)(r * SSTR + c_ld) * 2,
                     base[arr] + (size_t)r * 1024 + c_ld);
            }
        CP_COMMIT;
    }

#pragma unroll 1
    for (int t = 0; t < 32; t++) {
        if (t + 1 < 32) {
            int s = (t + 1) & 1, k0 = (t + 1) << 5;
#pragma unroll
            for (int arr = 0; arr < 2; arr++)
#pragma unroll
                for (int j = 0; j < 2; j++) {
                    int r = r_ld + j * 64;
                    cp16(sb + (uint32_t)s * VSTAGE + arr * ARRB +
                             (uint32_t)(r * SSTR + c_ld) * 2,
                         base[arr] + (size_t)r * 1024 + k0 + c_ld);
                }
            CP_COMMIT;
            CP_WAIT1;
        } else {
            CP_WAIT0;
        }
        __syncthreads();

        uint32_t st = sb + (uint32_t)(t & 1) * VSTAGE;
#pragma unroll
        for (int kk = 0; kk < 2; kk++) {
            uint32_t bb[8][2];
#pragma unroll
            for (int ng = 0; ng < 4; ng++) {
                int brow = wn * 64 + ng * 16 + (lane & 7) + ((lane & 16) >> 1);
                int bcol = kk * 16 + ((lane >> 3) & 1) * 8;
                uint32_t ba = st + ARRB + (uint32_t)(brow * SSTR + bcol) * 2;
                ldsm4(bb[2 * ng][0], bb[2 * ng][1], bb[2 * ng + 1][0],
                      bb[2 * ng + 1][1], ba);
            }
#pragma unroll
            for (int mt = 0; mt < 2; mt++) {
                int arow = wm * 32 + mt * 16 + (lane & 15);
                int acol = kk * 16 + (lane >> 4) * 8;
                uint32_t aa = st + (uint32_t)(arow * SSTR + acol) * 2;
                uint32_t ah[4];
                ldsm4(ah[0], ah[1], ah[2], ah[3], aa);
#pragma unroll
                for (int nt = 0; nt < 8; nt++)
                    mma16816h(c[mt][nt], ah, bb[nt]);
            }
        }
        __syncthreads();
    }

#pragma unroll
    for (int mt = 0; mt < 2; mt++) {
        int m = m0 + wm * 32 + mt * 16 + (lane >> 2);
#pragma unroll
        for (int nt = 0; nt < 8; nt++) {
            int n = n0 + wn * 64 + nt * 8 + ((lane & 3) << 1);
            float b0 = bias[2048 + n], b1 = bias[2048 + n + 1];
            int h = n >> 6, hd = n & 63;
            int bb = m >> 11, row = m & 2047;
            int bh_i = bb * H_ + h;
            size_t pb = ((size_t)bh_i * HD_ + hd) * N_ + row;
            g_Vt[pb]          = __float2half(c[mt][nt][0] + b0);
            g_Vt[pb + N_]     = __float2half(c[mt][nt][1] + b1);
            g_Vt[pb + 8]      = __float2half(c[mt][nt][2] + b0);
            g_Vt[pb + N_ + 8] = __float2half(c[mt][nt][3] + b1);
        }
    }
}

// Fused Q/K projection (split bf16) + V projection (fp16) in one launch.
__global__ void __launch_bounds__(256) qkv_all_kernel(
        const __nv_bfloat16* __restrict__ xh, const __nv_bfloat16* __restrict__ xl,
        const __nv_bfloat16* __restrict__ wih, const __nv_bfloat16* __restrict__ wil,
        const __half* __restrict__ xf, const __half* __restrict__ wvf,
        const float* __restrict__ bias) {
    extern __shared__ char smem[];
    int blk = blockIdx.x;
    if (blk < 512) {
        gemm_body<true>(smem_u32(smem), (blk >> 4) << 7, (blk & 15) << 7,
                        xh, xl, wih, wil, bias, nullptr);
    } else {
        int vb = blk - 512;
        v_body(smem_u32(smem), (vb >> 3) << 7, (vb & 7) << 7, xf, wvf, bias);
    }
}

// =============================================================================
// Fused out-projection GEMM + attn normalize. Norm path: per-block 32-row
// reciprocals precomputed in smem (kills the 33M MUFU RCPs), MLP-8 streaming.
// =============================================================================
#define NN_BLOCKS 2048

__global__ void __launch_bounds__(256, 2) out_norm_kernel(
        const __nv_bfloat16* __restrict__ Ah_g, const __nv_bfloat16* __restrict__ Al_g,
        const __nv_bfloat16* __restrict__ Bh_g, const __nv_bfloat16* __restrict__ Bl_g,
        const float* __restrict__ bias, float* __restrict__ outp,
        const __half* __restrict__ escr, float* __restrict__ attn, int write_attn) {
    int blk = blockIdx.x;
    extern __shared__ char smem[];
    if (blk < 256) {
        int n0 = (blk & 7) << 7, m0 = (blk >> 3) << 7;
        gemm_body<false>(smem_u32(smem), m0, n0, Ah_g, Al_g, Bh_g, Bl_g, bias, outp);
        return;
    }
    if (!write_attn) return;
    const size_t total4 = (size_t)BH_ * N_ * N_ / 4;
    const size_t per_blk = total4 / NN_BLOCKS;                    // 16384 f4 = 32 rows
    size_t i0 = (size_t)(blk - 256) * per_blk;
    int tid = threadIdx.x;
    int row0 = (int)(i0 >> 9);                                    // 512 f4 per row
    float* inv_s = (float*)smem;                                  // [32]
    if (tid < 32) inv_s[tid] = 1.0f / g_rowsum[row0 + tid];
    __syncthreads();
#pragma unroll 1
    for (int it = 0; it < 8; it++) {
        size_t idx[8];
        uint2 ev[8];
#pragma unroll
        for (int u = 0; u < 8; u++) {
            idx[u] = i0 + (size_t)(it * 8 + u) * 256 + tid;
            ev[u] = __ldcs((const uint2*)escr + idx[u]);
        }
#pragma unroll
        for (int u = 0; u < 8; u++) {
            float inv = inv_s[(int)(idx[u] >> 9) - row0];
            __half2 p0 = *(__half2*)&ev[u].x;
            __half2 p1 = *(__half2*)&ev[u].y;
            float4 v = make_float4(__low2float(p0) * inv, __high2float(p0) * inv,
                                   __low2float(p1) * inv, __high2float(p1) * inv);
            __stcs((float4*)attn + idx[u], v);
        }
    }
}

// =============================================================================
// Fused attention, all-fp16 operands (unchanged from R16 — proven)
// =============================================================================
#define AT_STR 72
#define AQ  0
#define AKV (256*AT_STR)
#define KVSTG (2*64*AT_STR)
#define ABF_END (AKV + 3*KVSTG)
#define ATTN_SMEM (ABF_END*2 + 2048*2)      // 96256 B

__global__ void __launch_bounds__(256, 1) attn_kernel(__half* __restrict__ escr,
                                                      const float* __restrict__ rpe,
                                                      int write_attn) {
    extern __shared__ char smc[];
    uint32_t sb = smem_u32(smc);
    __nv_bfloat16* rc = (__nv_bfloat16*)(smc + ABF_END * 2);

    int qt = blockIdx.x, h = blockIdx.y, b = blockIdx.z;
    int bh_i = b * H_ + h;
    int tid = threadIdx.x, lane = tid & 31, wm = tid >> 5;
    int q0 = qt << 8;

    for (int i = tid; i < S_; i += 256)
        rc[i] = __float2bfloat16(rpe[(size_t)i * H_ + h]);

    const __half* qg = g_Qf + ((size_t)bh_i * N_ + q0) * HD_;
    const __half* kg = g_Kf + (size_t)bh_i * N_ * HD_;
    const __half* vg = g_Vt + (size_t)bh_i * HD_ * N_;

#pragma unroll
    for (int j = 0; j < 8; j++) {
        int u = tid + j * 256;
        int r = u >> 3, ch = (u & 7) << 3;
        cp16(sb + (uint32_t)(AQ + r * AT_STR + ch) * 2, qg + (size_t)r * HD_ + ch);
    }
    CP_COMMIT;

    int r_ld = tid >> 3, c_ld = (tid & 7) << 3;
    auto issue_kv = [&](int t) {
        int k0g = t * 64;
        uint32_t stg = sb + (uint32_t)(AKV + (t % 3) * KVSTG) * 2;
#pragma unroll
        for (int j = 0; j < 2; j++) {
            int r = r_ld + j * 32, ch = c_ld;
            cp16(stg + (uint32_t)(r * AT_STR + ch) * 2,
                 kg + (size_t)(k0g + r) * HD_ + ch);
            cp16(stg + (uint32_t)(4608 + r * AT_STR + ch) * 2,
                 vg + (size_t)r * N_ + k0g + ch);
        }
        CP_COMMIT;
    };
    issue_kv(0);
    issue_kv(1);

    CP_WAIT2;
    __syncthreads();
    uint32_t qa[2][4][4];
#pragma unroll
    for (int mf = 0; mf < 2; mf++)
#pragma unroll
        for (int ks = 0; ks < 4; ks++) {
            int arow = wm * 32 + mf * 16 + (lane & 15);
            int acol = ks * 16 + (lane >> 4) * 8;
            uint32_t aa = sb + (uint32_t)(AQ + arow * AT_STR + acol) * 2;
            ldsm4(qa[mf][ks][0], qa[mf][ks][1], qa[mf][ks][2], qa[mf][ks][3], aa);
        }

    float co[2][8][4];
#pragma unroll
    for (int mf = 0; mf < 2; mf++)
#pragma unroll
        for (int nh = 0; nh < 8; nh++)
#pragma unroll
            for (int q = 0; q < 4; q++) co[mf][nh][q] = 0.f;
    float rs[2][2] = {{0.f, 0.f}, {0.f, 0.f}};

    int row_q = q0 + wm * 32 + (lane >> 2);
    const float scale = 0.125f;

#pragma unroll 1
    for (int t = 0; t < N_ / 64; t++) {
        if (t < 31) { CP_WAIT1; } else { CP_WAIT0; }
        __syncthreads();

        int k0g = t * 64;
        uint32_t kb = sb + (uint32_t)(AKV + (t % 3) * KVSTG) * 2;

        float s[2][8][4];
#pragma unroll
        for (int mf = 0; mf < 2; mf++)
#pragma unroll
            for (int nt = 0; nt < 8; nt++)
#pragma unroll
                for (int q = 0; q < 4; q++) s[mf][nt][q] = 0.f;
#pragma unroll
        for (int ks = 0; ks < 4; ks++) {
            uint32_t bh[8][2];
#pragma unroll
            for (int ng = 0; ng < 4; ng++) {
                int brow = ng * 16 + (lane & 7) + ((lane & 16) >> 1);
                int bcol = ks * 16 + ((lane >> 3) & 1) * 8;
                uint32_t ba = kb + (uint32_t)(brow * AT_STR + bcol) * 2;
                ldsm4(bh[2 * ng][0], bh[2 * ng][1], bh[2 * ng + 1][0],
                      bh[2 * ng + 1][1], ba);
            }
#pragma unroll
            for (int mf = 0; mf < 2; mf++)
#pragma unroll
                for (int nt = 0; nt < 8; nt++)
                    mma16816h(s[mf][nt], qa[mf][ks], bh[nt]);
        }

#pragma unroll
        for (int mf = 0; mf < 2; mf++) {
            int rq = row_q + mf * 16;
#pragma unroll
            for (int nt = 0; nt < 8; nt++) {
                int col = k0g + nt * 8 + ((lane & 3) << 1);
                int d0 = rq - col;     if (d0 < 0) d0 = -d0;
                int d1 = rq - col - 1; if (d1 < 0) d1 = -d1;
                int d2 = rq + 8 - col;     if (d2 < 0) d2 = -d2;
                int d3 = rq + 8 - col - 1; if (d3 < 0) d3 = -d3;
                float e0 = __expf(fmaf(s[mf][nt][0], scale, __bfloat162float(rc[d0])));
                float e1 = __expf(fmaf(s[mf][nt][1], scale, __bfloat162float(rc[d1])));
                float e2 = __expf(fmaf(s[mf][nt][2], scale, __bfloat162float(rc[d2])));
                float e3 = __expf(fmaf(s[mf][nt][3], scale, __bfloat162float(rc[d3])));
                s[mf][nt][0] = e0; s[mf][nt][1] = e1;
                s[mf][nt][2] = e2; s[mf][nt][3] = e3;
                rs[mf][0] += e0 + e1;
                rs[mf][1] += e2 + e3;
                if (write_attn) {
                    __half* ep = escr + ((size_t)bh_i * N_ + rq) * N_ + col;
                    *(uint32_t*)ep = pkhf(e0, e1);
                    *(uint32_t*)(ep + 8 * N_) = pkhf(e2, e3);
                }
            }
        }

        uint32_t vb0 = kb + 4608 * 2;
#pragma unroll
        for (int ks = 0; ks < 4; ks++) {
            uint32_t ea[2][4];
#pragma unroll
            for (int mf = 0; mf < 2; mf++) {
                ea[mf][0] = pkhf(s[mf][2 * ks][0], s[mf][2 * ks][1]);
                ea[mf][1] = pkhf(s[mf][2 * ks][2], s[mf][2 * ks][3]);
                ea[mf][2] = pkhf(s[mf][2 * ks + 1][0], s[mf][2 * ks + 1][1]);
                ea[mf][3] = pkhf(s[mf][2 * ks + 1][2], s[mf][2 * ks + 1][3]);
            }
            uint32_t vb[8][2];
#pragma unroll
            for (int ng = 0; ng < 4; ng++) {
                int brow = ng * 16 + (lane & 7) + ((lane & 16) >> 1);
                int bcol = ks * 16 + ((lane >> 3) & 1) * 8;
                uint32_t ba = vb0 + (uint32_t)(brow * AT_STR + bcol) * 2;
                ldsm4(vb[2 * ng][0], vb[2 * ng][1], vb[2 * ng + 1][0],
                      vb[2 * ng + 1][1], ba);
            }
#pragma unroll
            for (int mf = 0; mf < 2; mf++)
#pragma unroll
                for (int nh = 0; nh < 8; nh++)
                    mma16816h(co[mf][nh], ea[mf], vb[nh]);
        }

        if (t + 2 < N_ / 64) issue_kv(t + 2);
    }

#pragma unroll
    for (int mf = 0; mf < 2; mf++) {
        float r0 = rs[mf][0], r1 = rs[mf][1];
        r0 += __shfl_xor_sync(0xffffffffu, r0, 1);
        r0 += __shfl_xor_sync(0xffffffffu, r0, 2);
        r1 += __shfl_xor_sync(0xffffffffu, r1, 1);
        r1 += __shfl_xor_sync(0xffffffffu, r1, 2);
        int rq = row_q + mf * 16;
        if ((lane & 3) == 0) {
            g_rowsum[(size_t)bh_i * N_ + rq] = r0;
            g_rowsum[(size_t)bh_i * N_ + rq + 8] = r1;
        }
        float inv0 = 1.0f / r0, inv1 = 1.0f / r1;
#pragma unroll
        for (int nh = 0; nh < 8; nh++) {
            int hd = nh * 8 + ((lane & 3) << 1);
            size_t p = ((size_t)(b * N_ + rq)) * D_ + h * HD_ + hd;
            split_st2(g_aoh, g_aol, p,
                      make_float2(co[mf][nh][0] * inv0, co[mf][nh][1] * inv0));
            split_st2(g_aoh, g_aol, p + 8 * D_,
                      make_float2(co[mf][nh][2] * inv1, co[mf][nh][3] * inv1));
        }
    }
}

// =============================================================================
extern "C" void kernel_launch(void* const* d_in, const int* in_sizes, int n_in,
                              void* d_out, int out_size) {
    const float* query = (const float*)d_in[0];
    const float* w_in  = (const float*)d_in[4];
    const float* b_in  = (const float*)d_in[5];
    const float* w_out = (const float*)d_in[6];
    const float* b_out = (const float*)d_in[7];
    const float* rpe   = (const float*)d_in[8];

    float* out  = (float*)d_out;
    const long long out_elems  = (long long)B_ * N_ * D_;
    const long long attn_elems = (long long)BH_ * N_ * N_;
    int write_attn = ((long long)out_size >= out_elems + attn_elems) ? 1 : 0;
    float* attn = out + out_elems;

    cudaFuncSetAttribute(attn_kernel, cudaFuncAttributeMaxDynamicSharedMemorySize,
                         ATTN_SMEM);
    cudaFuncSetAttribute(qkv_all_kernel, cudaFuncAttributeMaxDynamicSharedMemorySize,
                         GEMM_SMEM);
    cudaFuncSetAttribute(out_norm_kernel, cudaFuncAttributeMaxDynamicSharedMemorySize,
                         GEMM_SMEM);

    __nv_bfloat16 *xh, *xl, *wih, *wil, *aoh, *aol, *woh, *wol;
    __half *xf, *wvf, *escr;
    cudaGetSymbolAddress((void**)&xh,  g_xh);
    cudaGetSymbolAddress((void**)&xl,  g_xl);
    cudaGetSymbolAddress((void**)&xf,  g_xf);
    cudaGetSymbolAddress((void**)&wih, g_wih);
    cudaGetSymbolAddress((void**)&wil, g_wil);
    cudaGetSymbolAddress((void**)&wvf, g_wvf);
    cudaGetSymbolAddress((void**)&aoh, g_aoh);
    cudaGetSymbolAddress((void**)&aol, g_aol);
    cudaGetSymbolAddress((void**)&woh, g_woh);
    cudaGetSymbolAddress((void**)&wol, g_wol);
    cudaGetSymbolAddress((void**)&escr, g_escr);

    cvt3_kernel<<<8192, 256>>>(query, xh, xl, xf, w_in, wih, wil, wvf,
                               w_out, woh, wol);

    qkv_all_kernel<<<768, 256, GEMM_SMEM>>>(xh, xl, wih, wil, xf, wvf, b_in);

    attn_kernel<<<dim3(8, 16, 2), 256, ATTN_SMEM>>>(escr, rpe, write_attn);

    out_norm_kernel<<<256 + NN_BLOCKS, 256, GEMM_SMEM>>>(
        aoh, aol, woh, wol, b_out, out, escr, attn, write_attn);
}